// round 6
// baseline (speedup 1.0000x reference)
#include <cuda_runtime.h>
#include <cuda_bf16.h>
#include <cuda_fp16.h>
#include <cstdint>

// Problem constants
#define NBATCH 2
#define LSEQ   2048
#define EMBD   1024
#define NHEAD  16
#define HDIM   64
#define MROWS  (NBATCH * LSEQ)   // 4096
#define QKV_ELEMS (NBATCH * NHEAD * LSEQ * HDIM)

// Scratch (device globals: no allocation allowed)
__device__ __half g_qh[QKV_ELEMS], g_ql[QKV_ELEMS];
__device__ __half g_kh[QKV_ELEMS], g_kl[QKV_ELEMS];
__device__ __half g_vh[QKV_ELEMS], g_vl[QKV_ELEMS];
__device__ float  g_attn[MROWS * EMBD];

__device__ __forceinline__ uint32_t smem_u32(const void* p) {
    uint32_t a;
    asm("{ .reg .u64 t; cvta.to.shared.u64 t, %1; cvt.u32.u64 %0, t; }"
        : "=r"(a) : "l"(p));
    return a;
}

// ---------------- GEMM (bf16 3x split mma, epilogue emits fp16 hi/lo for QKV) ----------------
#define BK 32
#define ASTR 36
#define ARR_BYTES (128 * ASTR * 2)
#define STAGE_BYTES_G (4 * ARR_BYTES)
#define GEMM_SMEM (2 * STAGE_BYTES_G)

__device__ __forceinline__ uint32_t pack2(__nv_bfloat16 a, __nv_bfloat16 b) {
    __nv_bfloat162 t = __halves2bfloat162(a, b);
    return *reinterpret_cast<uint32_t*>(&t);
}

__device__ __forceinline__ void mma16816(float* c, const uint32_t* a, const uint32_t* b) {
    asm volatile(
        "mma.sync.aligned.m16n8k16.row.col.f32.bf16.bf16.f32 "
        "{%0,%1,%2,%3}, {%4,%5,%6,%7}, {%8,%9}, {%0,%1,%2,%3};"
        : "+f"(c[0]), "+f"(c[1]), "+f"(c[2]), "+f"(c[3])
        : "r"(a[0]), "r"(a[1]), "r"(a[2]), "r"(a[3]), "r"(b[0]), "r"(b[1]));
}

// MODE 0: per-head LayerNorm epilogue, half hi/lo head-major output [N,H,L,D]
// MODE 1: half hi/lo head-major output, no LN
// MODE 2: fp32 row-major output + bias
template <int MODE>
__global__ void __launch_bounds__(256, 2) bf16_gemm(
    const float* __restrict__ A, const float* __restrict__ W,
    const float* __restrict__ gamma, const float* __restrict__ beta,
    const float* __restrict__ bias,
    __half* __restrict__ Ch, __half* __restrict__ Cl, float* __restrict__ C)
{
    extern __shared__ char sm[];
    const int tid  = threadIdx.x;
    const int lane = tid & 31;
    const int wid  = tid >> 5;
    const int g    = lane >> 2;
    const int q    = lane & 3;
    const int warp_m = wid >> 2;
    const int warp_n = wid & 3;
    const int rb = blockIdx.x * 128;
    const int cb = blockIdx.y * 128;

    auto arr = [&](int s, int a) -> __nv_bfloat16* {
        return (__nv_bfloat16*)(sm + s * STAGE_BYTES_G + a * ARR_BYTES);
    };

    const int lr = tid >> 1;
    const int lh = (tid & 1) * 16;
    const float* Ap = A + (size_t)(rb + lr) * EMBD + lh;
    const float* Wp = W + (size_t)(cb + lr) * EMBD + lh;

    float4 av[4], bv[4];
    auto ldg = [&](int kc) {
#pragma unroll
        for (int i = 0; i < 4; i++) {
            av[i] = *(const float4*)(Ap + kc * BK + 4 * i);
            bv[i] = *(const float4*)(Wp + kc * BK + 4 * i);
        }
    };
    auto sts = [&](int s) {
        __nv_bfloat16 *Ah = arr(s, 0), *Al = arr(s, 1), *Bh = arr(s, 2), *Bl = arr(s, 3);
#pragma unroll
        for (int i = 0; i < 4; i++) {
            const int off = lr * ASTR + lh + i * 4;
            {
                float4 a = av[i];
                __nv_bfloat16 h0 = __float2bfloat16(a.x), h1 = __float2bfloat16(a.y),
                              h2 = __float2bfloat16(a.z), h3 = __float2bfloat16(a.w);
                *(uint2*)(Ah + off) = make_uint2(pack2(h0, h1), pack2(h2, h3));
                *(uint2*)(Al + off) = make_uint2(
                    pack2(__float2bfloat16(a.x - __bfloat162float(h0)),
                          __float2bfloat16(a.y - __bfloat162float(h1))),
                    pack2(__float2bfloat16(a.z - __bfloat162float(h2)),
                          __float2bfloat16(a.w - __bfloat162float(h3))));
            }
            {
                float4 b = bv[i];
                __nv_bfloat16 h0 = __float2bfloat16(b.x), h1 = __float2bfloat16(b.y),
                              h2 = __float2bfloat16(b.z), h3 = __float2bfloat16(b.w);
                *(uint2*)(Bh + off) = make_uint2(pack2(h0, h1), pack2(h2, h3));
                *(uint2*)(Bl + off) = make_uint2(
                    pack2(__float2bfloat16(b.x - __bfloat162float(h0)),
                          __float2bfloat16(b.y - __bfloat162float(h1))),
                    pack2(__float2bfloat16(b.z - __bfloat162float(h2)),
                          __float2bfloat16(b.w - __bfloat162float(h3))));
            }
        }
    };

    float acc[4][4][4] = {};

    auto compute = [&](int s) {
        const __nv_bfloat16 *Ah = arr(s, 0), *Al = arr(s, 1),
                            *Bh = arr(s, 2), *Bl = arr(s, 3);
#pragma unroll
        for (int ks = 0; ks < 2; ks++) {
            const int kb = ks * 16 + q * 2;
            uint32_t ah[4][4], bh[4][2];
#pragma unroll
            for (int mf = 0; mf < 4; mf++) {
                const __nv_bfloat16* p = Ah + (warp_m * 64 + mf * 16 + g) * ASTR + kb;
                ah[mf][0] = *(const uint32_t*)p;
                ah[mf][1] = *(const uint32_t*)(p + 8 * ASTR);
                ah[mf][2] = *(const uint32_t*)(p + 8);
                ah[mf][3] = *(const uint32_t*)(p + 8 * ASTR + 8);
            }
#pragma unroll
            for (int nf = 0; nf < 4; nf++) {
                const __nv_bfloat16* p = Bh + (warp_n * 32 + nf * 8 + g) * ASTR + kb;
                bh[nf][0] = *(const uint32_t*)p;
                bh[nf][1] = *(const uint32_t*)(p + 8);
            }
#pragma unroll
            for (int mf = 0; mf < 4; mf++)
#pragma unroll
                for (int nf = 0; nf < 4; nf++)
                    mma16816(acc[mf][nf], ah[mf], bh[nf]);
#pragma unroll
            for (int nf = 0; nf < 4; nf++) {
                const __nv_bfloat16* p = Bl + (warp_n * 32 + nf * 8 + g) * ASTR + kb;
                uint32_t bl[2] = { *(const uint32_t*)p, *(const uint32_t*)(p + 8) };
#pragma unroll
                for (int mf = 0; mf < 4; mf++)
                    mma16816(acc[mf][nf], ah[mf], bl);
            }
#pragma unroll
            for (int mf = 0; mf < 4; mf++) {
                const __nv_bfloat16* p = Al + (warp_m * 64 + mf * 16 + g) * ASTR + kb;
                uint32_t al[4] = { *(const uint32_t*)p,
                                   *(const uint32_t*)(p + 8 * ASTR),
                                   *(const uint32_t*)(p + 8),
                                   *(const uint32_t*)(p + 8 * ASTR + 8) };
#pragma unroll
                for (int nf = 0; nf < 4; nf++)
                    mma16816(acc[mf][nf], al, bh[nf]);
            }
        }
    };

    ldg(0); sts(0);
    __syncthreads();
    for (int kc = 0; kc < EMBD / BK; kc++) {
        compute(kc & 1);
        if (kc + 1 < EMBD / BK) {
            ldg(kc + 1);
            sts((kc + 1) & 1);
        }
        __syncthreads();
    }

    float* Ct = (float*)sm;   // [128][132]
#pragma unroll
    for (int mf = 0; mf < 4; mf++)
#pragma unroll
        for (int nf = 0; nf < 4; nf++) {
            const int r = warp_m * 64 + mf * 16 + g;
            const int c = warp_n * 32 + nf * 8 + q * 2;
            *(float2*)&Ct[r * 132 + c]       = make_float2(acc[mf][nf][0], acc[mf][nf][1]);
            *(float2*)&Ct[(r + 8) * 132 + c] = make_float2(acc[mf][nf][2], acc[mf][nf][3]);
        }
    __syncthreads();

    {
        const int row = tid >> 1;
        const int seg = tid & 1;
        float f[64];
#pragma unroll
        for (int j = 0; j < 16; j++)
            *(float4*)&f[4 * j] = *(const float4*)&Ct[row * 132 + seg * 64 + 4 * j];

        if (MODE == 0) {
            float s = 0.f, s2 = 0.f;
#pragma unroll
            for (int j = 0; j < 64; j++) { s += f[j]; s2 += f[j] * f[j]; }
            const float mean = s * (1.0f / 64.0f);
            const float var  = s2 * (1.0f / 64.0f) - mean * mean;
            const float rstd = rsqrtf(var + 1e-5f);
#pragma unroll
            for (int j = 0; j < 64; j++)
                f[j] = (f[j] - mean) * rstd * __ldg(gamma + j) + __ldg(beta + j);
        }

        if (MODE == 0 || MODE == 1) {
            __half hi[64], lo[64];
#pragma unroll
            for (int j = 0; j < 64; j++) {
                __half hh = __float2half_rn(f[j]);
                hi[j] = hh;
                lo[j] = __float2half_rn(f[j] - __half2float(hh));
            }
            const int grow = rb + row;
            const int n = grow >> 11;
            const int l = grow & (LSEQ - 1);
            const int hd = (cb >> 6) + seg;
            const size_t off = ((size_t)((n * NHEAD + hd) * LSEQ + l)) * HDIM;
#pragma unroll
            for (int j = 0; j < 8; j++) {
                *(uint4*)(Ch + off + 8 * j) = *(uint4*)&hi[8 * j];
                *(uint4*)(Cl + off + 8 * j) = *(uint4*)&lo[8 * j];
            }
        } else {
            const int c0 = cb + seg * 64;
#pragma unroll
            for (int j = 0; j < 64; j++) f[j] += __ldg(bias + c0 + j);
            float* dst = C + (size_t)(rb + row) * EMBD + c0;
#pragma unroll
            for (int j = 0; j < 16; j++) *(float4*)(dst + 4 * j) = *(float4*)&f[4 * j];
        }
    }
}

// ---------------- Attention v3: pre-split fp16, cp.async double-buffered ----------------
#define APAD 72
#define KARR (64 * APAD)                  // halves per array
#define STAGE_H (4 * KARR)                // halves per stage (Kh|Kl|Vh|Vl)
#define ATTN_SMEM (2 * STAGE_H * 2)       // bytes = 73728

#define LDSM_X4(r0, r1, r2, r3, addr) \
    asm volatile("ldmatrix.sync.aligned.m8n8.x4.shared.b16 {%0,%1,%2,%3}, [%4];" \
        : "=r"(r0), "=r"(r1), "=r"(r2), "=r"(r3) : "r"(addr))
#define LDSM_X2(r0, r1, addr) \
    asm volatile("ldmatrix.sync.aligned.m8n8.x2.shared.b16 {%0,%1}, [%2];" \
        : "=r"(r0), "=r"(r1) : "r"(addr))
#define LDSM_X2T(r0, r1, addr) \
    asm volatile("ldmatrix.sync.aligned.m8n8.x2.trans.shared.b16 {%0,%1}, [%2];" \
        : "=r"(r0), "=r"(r1) : "r"(addr))

__device__ __forceinline__ void mma_f16(float* c, const uint32_t* a, const uint32_t* b) {
    asm volatile(
        "mma.sync.aligned.m16n8k16.row.col.f32.f16.f16.f32 "
        "{%0,%1,%2,%3}, {%4,%5,%6,%7}, {%8,%9}, {%0,%1,%2,%3};"
        : "+f"(c[0]), "+f"(c[1]), "+f"(c[2]), "+f"(c[3])
        : "r"(a[0]), "r"(a[1]), "r"(a[2]), "r"(a[3]), "r"(b[0]), "r"(b[1]));
}

__device__ __forceinline__ uint32_t packh2(float a, float b) {
    __half2 h = __floats2half2_rn(a, b);
    return *reinterpret_cast<uint32_t*>(&h);
}

__device__ __forceinline__ void cp_async16(uint32_t dst, const void* src) {
    asm volatile("cp.async.cg.shared.global [%0], [%1], 16;" :: "r"(dst), "l"(src));
}
#define CP_COMMIT() asm volatile("cp.async.commit_group;" ::: "memory")
#define CP_WAIT(N)  asm volatile("cp.async.wait_group %0;" :: "n"(N) : "memory")

__global__ void __launch_bounds__(128, 3) attn_mma(
    const __half* __restrict__ Qh, const __half* __restrict__ Ql,
    const __half* __restrict__ Kh, const __half* __restrict__ Kl,
    const __half* __restrict__ Vh, const __half* __restrict__ Vl,
    float* __restrict__ O)
{
    extern __shared__ __half smh[];
    const uint32_t sbase = smem_u32(smh);

    const int tid  = threadIdx.x;
    const int lane = tid & 31;
    const int wid  = tid >> 5;      // 0..3
    const int g    = lane >> 2;     // 0..7
    const int t    = lane & 3;      // 0..3
    const int nh   = blockIdx.y;
    const int qt   = gridDim.x - 1 - blockIdx.x;   // heavy tiles first
    const int qb   = qt * 64;
    const size_t base = (size_t)nh * LSEQ * HDIM;

    // cp.async loader coords: thread t -> row lr, 32-half column half
    const int lr = tid >> 1;
    const int lc = (tid & 1) * 32;
    const uint32_t sm_row_off = ((uint32_t)lr * APAD + (uint32_t)lc) * 2;

    // stage K/V tile kt into buffer b (4 arrays x 4 chunks of 16B per thread)
    auto stage_kv = [&](int b, int kt) {
        const size_t goff = base + (size_t)(kt * 64 + lr) * HDIM + lc;
        const uint32_t s0 = sbase + (uint32_t)b * (STAGE_H * 2) + sm_row_off;
#pragma unroll
        for (int i = 0; i < 4; i++) {
            cp_async16(s0 + 0 * (KARR * 2) + i * 16, Kh + goff + i * 8);
            cp_async16(s0 + 1 * (KARR * 2) + i * 16, Kl + goff + i * 8);
            cp_async16(s0 + 2 * (KARR * 2) + i * 16, Vh + goff + i * 8);
            cp_async16(s0 + 3 * (KARR * 2) + i * 16, Vl + goff + i * 8);
        }
    };

    // prologue: Q tile into buffer 1 (slots 0/1), K/V tile 0 into buffer 0
    {
        const size_t goff = base + (size_t)(qb + lr) * HDIM + lc;
        const uint32_t s1 = sbase + (uint32_t)(STAGE_H * 2) + sm_row_off;
#pragma unroll
        for (int i = 0; i < 4; i++) {
            cp_async16(s1 + 0 * (KARR * 2) + i * 16, Qh + goff + i * 8);
            cp_async16(s1 + 1 * (KARR * 2) + i * 16, Ql + goff + i * 8);
        }
        stage_kv(0, 0);
        CP_COMMIT();
        CP_WAIT(0);
    }
    __syncthreads();

    // Q fragments from buffer 1
    uint32_t qfh[4][4], qfl[4][4];
    {
        __half* q0 = smh + STAGE_H;
        __half* q1 = smh + STAGE_H + KARR;
        const int frow = wid * 16 + (lane & 15);
        const int fcol8 = (lane >> 4) << 3;
#pragma unroll
        for (int kc = 0; kc < 4; kc++) {
            LDSM_X4(qfh[kc][0], qfh[kc][1], qfh[kc][2], qfh[kc][3],
                    smem_u32(q0 + frow * APAD + kc * 16 + fcol8));
            LDSM_X4(qfl[kc][0], qfl[kc][1], qfl[kc][2], qfl[kc][3],
                    smem_u32(q1 + frow * APAD + kc * 16 + fcol8));
        }
    }
    __syncthreads();   // Q reads done before buffer 1 is re-staged

    float oc[8][4] = {};
    float m0 = -1e30f, m1 = -1e30f, l0 = 0.f, l1 = 0.f;

    const int kfr = lane & 7;
    const int kfc = ((lane & 15) >> 3) << 3;
    const int vfr = lane & 15;

    for (int kt = 0; kt <= qt; kt++) {
        if (kt < qt) { stage_kv((kt + 1) & 1, kt + 1); CP_COMMIT(); }
        if (kt < qt) { CP_WAIT(1); } else { CP_WAIT(0); }
        __syncthreads();

        __half* Khp = smh + (size_t)(kt & 1) * STAGE_H;
        __half* Klp = Khp + KARR;
        __half* Vhp = Khp + 2 * KARR;
        __half* Vlp = Khp + 3 * KARR;

        // ---- S = Q K^T (3-product split) ----
        float sc[8][4] = {};
#pragma unroll
        for (int kc = 0; kc < 4; kc++) {
#pragma unroll
            for (int nf = 0; nf < 8; nf++) {
                uint32_t bh[2], bl[2];
                LDSM_X2(bh[0], bh[1],
                        smem_u32(Khp + (nf * 8 + kfr) * APAD + kc * 16 + kfc));
                LDSM_X2(bl[0], bl[1],
                        smem_u32(Klp + (nf * 8 + kfr) * APAD + kc * 16 + kfc));
                mma_f16(sc[nf], qfh[kc], bh);
                mma_f16(sc[nf], qfh[kc], bl);
                mma_f16(sc[nf], qfl[kc], bh);
            }
        }

        // ---- causal mask on diagonal tile ----
        if (kt == qt) {
            const int r0 = wid * 16 + g;
            const int r1 = r0 + 8;
#pragma unroll
            for (int nf = 0; nf < 8; nf++) {
                const int c0 = nf * 8 + 2 * t;
                if (c0     > r0) sc[nf][0] = -1e30f;
                if (c0 + 1 > r0) sc[nf][1] = -1e30f;
                if (c0     > r1) sc[nf][2] = -1e30f;
                if (c0 + 1 > r1) sc[nf][3] = -1e30f;
            }
        }

        // ---- online softmax ----
        {
            float rm0 = -1e30f, rm1 = -1e30f;
#pragma unroll
            for (int nf = 0; nf < 8; nf++) {
                rm0 = fmaxf(rm0, fmaxf(sc[nf][0], sc[nf][1]));
                rm1 = fmaxf(rm1, fmaxf(sc[nf][2], sc[nf][3]));
            }
            rm0 = fmaxf(rm0, __shfl_xor_sync(0xffffffffu, rm0, 1));
            rm0 = fmaxf(rm0, __shfl_xor_sync(0xffffffffu, rm0, 2));
            rm1 = fmaxf(rm1, __shfl_xor_sync(0xffffffffu, rm1, 1));
            rm1 = fmaxf(rm1, __shfl_xor_sync(0xffffffffu, rm1, 2));

            const float mn0 = fmaxf(m0, rm0), mn1 = fmaxf(m1, rm1);
            const float cr0 = __expf(m0 - mn0), cr1 = __expf(m1 - mn1);
            float rs0 = 0.f, rs1 = 0.f;
#pragma unroll
            for (int nf = 0; nf < 8; nf++) {
                sc[nf][0] = __expf(sc[nf][0] - mn0);
                sc[nf][1] = __expf(sc[nf][1] - mn0);
                sc[nf][2] = __expf(sc[nf][2] - mn1);
                sc[nf][3] = __expf(sc[nf][3] - mn1);
                rs0 += sc[nf][0] + sc[nf][1];
                rs1 += sc[nf][2] + sc[nf][3];
            }
            rs0 += __shfl_xor_sync(0xffffffffu, rs0, 1);
            rs0 += __shfl_xor_sync(0xffffffffu, rs0, 2);
            rs1 += __shfl_xor_sync(0xffffffffu, rs1, 1);
            rs1 += __shfl_xor_sync(0xffffffffu, rs1, 2);

            l0 = l0 * cr0 + rs0; l1 = l1 * cr1 + rs1;
            m0 = mn0; m1 = mn1;
#pragma unroll
            for (int nf = 0; nf < 8; nf++) {
                oc[nf][0] *= cr0; oc[nf][1] *= cr0;
                oc[nf][2] *= cr1; oc[nf][3] *= cr1;
            }
        }

        // ---- O += P V (3-product split) ----
#pragma unroll
        for (int kc = 0; kc < 4; kc++) {
            uint32_t pah[4], pal[4];
            {
                const float* e0 = sc[2 * kc];
                const float* e1 = sc[2 * kc + 1];
                __half h00 = __float2half_rn(e0[0]), h01 = __float2half_rn(e0[1]);
                __half h02 = __float2half_rn(e0[2]), h03 = __float2half_rn(e0[3]);
                __half h10 = __float2half_rn(e1[0]), h11 = __float2half_rn(e1[1]);
                __half h12 = __float2half_rn(e1[2]), h13 = __float2half_rn(e1[3]);
                __half2 p;
                p = __halves2half2(h00, h01); pah[0] = *(uint32_t*)&p;
                p = __halves2half2(h02, h03); pah[1] = *(uint32_t*)&p;
                p = __halves2half2(h10, h11); pah[2] = *(uint32_t*)&p;
                p = __halves2half2(h12, h13); pah[3] = *(uint32_t*)&p;
                pal[0] = packh2(e0[0] - __half2float(h00), e0[1] - __half2float(h01));
                pal[1] = packh2(e0[2] - __half2float(h02), e0[3] - __half2float(h03));
                pal[2] = packh2(e1[0] - __half2float(h10), e1[1] - __half2float(h11));
                pal[3] = packh2(e1[2] - __half2float(h12), e1[3] - __half2float(h13));
            }
#pragma unroll
            for (int nf = 0; nf < 8; nf++) {
                uint32_t vh[2], vl[2];
                LDSM_X2T(vh[0], vh[1], smem_u32(Vhp + (kc * 16 + vfr) * APAD + nf * 8));
                LDSM_X2T(vl[0], vl[1], smem_u32(Vlp + (kc * 16 + vfr) * APAD + nf * 8));
                mma_f16(oc[nf], pah, vh);
                mma_f16(oc[nf], pal, vh);
                mma_f16(oc[nf], pah, vl);
            }
        }
        __syncthreads();   // compute done before this buffer is re-staged
    }

    // ---- epilogue: normalize, scatter to [N, L, H*D] ----
    const float inv0 = 1.0f / l0, inv1 = 1.0f / l1;
    const int n = nh >> 4;
    const int h = nh & 15;
    const int r0 = qb + wid * 16 + g;
    const int r1 = r0 + 8;
#pragma unroll
    for (int nf = 0; nf < 8; nf++) {
        const int col = h * HDIM + nf * 8 + 2 * t;
        *(float2*)&O[(size_t)(n * LSEQ + r0) * EMBD + col] =
            make_float2(oc[nf][0] * inv0, oc[nf][1] * inv0);
        *(float2*)&O[(size_t)(n * LSEQ + r1) * EMBD + col] =
            make_float2(oc[nf][2] * inv1, oc[nf][3] * inv1);
    }
}

// ------------------------- launch -------------------------
extern "C" void kernel_launch(void* const* d_in, const int* in_sizes, int n_in,
                              void* d_out, int out_size)
{
    (void)in_sizes; (void)n_in; (void)out_size;
    const float* x  = (const float*)d_in[0];
    const float* Wq = (const float*)d_in[2];
    const float* Wk = (const float*)d_in[3];
    const float* Wv = (const float*)d_in[4];
    const float* gq = (const float*)d_in[5];
    const float* bq = (const float*)d_in[6];
    const float* gk = (const float*)d_in[7];
    const float* bk = (const float*)d_in[8];
    const float* Wo = (const float*)d_in[9];
    const float* bo = (const float*)d_in[10];
    float* out = (float*)d_out;

    __half *qh, *ql, *kh, *kl, *vh, *vl;
    float *ap;
    cudaGetSymbolAddress((void**)&qh, g_qh);
    cudaGetSymbolAddress((void**)&ql, g_ql);
    cudaGetSymbolAddress((void**)&kh, g_kh);
    cudaGetSymbolAddress((void**)&kl, g_kl);
    cudaGetSymbolAddress((void**)&vh, g_vh);
    cudaGetSymbolAddress((void**)&vl, g_vl);
    cudaGetSymbolAddress((void**)&ap, g_attn);

    cudaFuncSetAttribute(bf16_gemm<0>, cudaFuncAttributeMaxDynamicSharedMemorySize, GEMM_SMEM);
    cudaFuncSetAttribute(bf16_gemm<1>, cudaFuncAttributeMaxDynamicSharedMemorySize, GEMM_SMEM);
    cudaFuncSetAttribute(bf16_gemm<2>, cudaFuncAttributeMaxDynamicSharedMemorySize, GEMM_SMEM);
    cudaFuncSetAttribute(attn_mma, cudaFuncAttributeMaxDynamicSharedMemorySize, ATTN_SMEM);

    dim3 gg(MROWS / 128, EMBD / 128);
    bf16_gemm<0><<<gg, 256, GEMM_SMEM>>>(x, Wq, gq, bq, nullptr, qh, ql, nullptr);
    bf16_gemm<0><<<gg, 256, GEMM_SMEM>>>(x, Wk, gk, bk, nullptr, kh, kl, nullptr);
    bf16_gemm<1><<<gg, 256, GEMM_SMEM>>>(x, Wv, nullptr, nullptr, nullptr, vh, vl, nullptr);

    attn_mma<<<dim3(LSEQ / 64, NBATCH * NHEAD), 128, ATTN_SMEM>>>(qh, ql, kh, kl, vh, vl, ap);

    bf16_gemm<2><<<gg, 256, GEMM_SMEM>>>(ap, Wo, nullptr, nullptr, bo, nullptr, nullptr, out);
}

// round 7
// speedup vs baseline: 1.7475x; 1.7475x over previous
#include <cuda_runtime.h>
#include <cuda_bf16.h>
#include <cuda_fp16.h>
#include <cstdint>

// Problem constants
#define NBATCH 2
#define LSEQ   2048
#define EMBD   1024
#define NHEAD  16
#define HDIM   64
#define MROWS  (NBATCH * LSEQ)   // 4096
#define QKV_ELEMS (NBATCH * NHEAD * LSEQ * HDIM)

// Scratch (device globals: no allocation allowed)
__device__ __half g_qh[QKV_ELEMS], g_ql[QKV_ELEMS];
__device__ __half g_kh[QKV_ELEMS], g_kl[QKV_ELEMS];
__device__ __half g_vh[QKV_ELEMS];
__device__ float  g_attn[MROWS * EMBD];

__device__ __forceinline__ uint32_t smem_u32(const void* p) {
    uint32_t a;
    asm("{ .reg .u64 t; cvta.to.shared.u64 t, %1; cvt.u32.u64 %0, t; }"
        : "=r"(a) : "l"(p));
    return a;
}

// ---------------- GEMM (bf16 3x split mma; R5-proven main loop) ----------------
#define BK 32
#define ASTR 36
#define ARR_BYTES (128 * ASTR * 2)
#define STAGE_BYTES_G (4 * ARR_BYTES)
#define GEMM_SMEM (2 * STAGE_BYTES_G)

__device__ __forceinline__ uint32_t pack2(__nv_bfloat16 a, __nv_bfloat16 b) {
    __nv_bfloat162 t = __halves2bfloat162(a, b);
    return *reinterpret_cast<uint32_t*>(&t);
}

__device__ __forceinline__ void mma16816(float* c, const uint32_t* a, const uint32_t* b) {
    asm volatile(
        "mma.sync.aligned.m16n8k16.row.col.f32.bf16.bf16.f32 "
        "{%0,%1,%2,%3}, {%4,%5,%6,%7}, {%8,%9}, {%0,%1,%2,%3};"
        : "+f"(c[0]), "+f"(c[1]), "+f"(c[2]), "+f"(c[3])
        : "r"(a[0]), "r"(a[1]), "r"(a[2]), "r"(a[3]), "r"(b[0]), "r"(b[1]));
}

// MODE 0: per-head LayerNorm, half hi+lo head-major output [N,H,L,D]
// MODE 1: half hi-only head-major output
// MODE 2: fp32 row-major output + bias
template <int MODE>
__global__ void __launch_bounds__(256, 2) bf16_gemm(
    const float* __restrict__ A, const float* __restrict__ W,
    const float* __restrict__ gamma, const float* __restrict__ beta,
    const float* __restrict__ bias,
    __half* __restrict__ Ch, __half* __restrict__ Cl, float* __restrict__ C)
{
    extern __shared__ char sm[];
    const int tid  = threadIdx.x;
    const int lane = tid & 31;
    const int wid  = tid >> 5;
    const int g    = lane >> 2;
    const int q    = lane & 3;
    const int warp_m = wid >> 2;
    const int warp_n = wid & 3;
    const int rb = blockIdx.x * 128;
    const int cb = blockIdx.y * 128;

    auto arr = [&](int s, int a) -> __nv_bfloat16* {
        return (__nv_bfloat16*)(sm + s * STAGE_BYTES_G + a * ARR_BYTES);
    };

    const int lr = tid >> 1;
    const int lh = (tid & 1) * 16;
    const float* Ap = A + (size_t)(rb + lr) * EMBD + lh;
    const float* Wp = W + (size_t)(cb + lr) * EMBD + lh;

    float4 av[4], bv[4];
    auto ldg = [&](int kc) {
#pragma unroll
        for (int i = 0; i < 4; i++) {
            av[i] = *(const float4*)(Ap + kc * BK + 4 * i);
            bv[i] = *(const float4*)(Wp + kc * BK + 4 * i);
        }
    };
    auto sts = [&](int s) {
        __nv_bfloat16 *Ah = arr(s, 0), *Al = arr(s, 1), *Bh = arr(s, 2), *Bl = arr(s, 3);
#pragma unroll
        for (int i = 0; i < 4; i++) {
            const int off = lr * ASTR + lh + i * 4;
            {
                float4 a = av[i];
                __nv_bfloat16 h0 = __float2bfloat16(a.x), h1 = __float2bfloat16(a.y),
                              h2 = __float2bfloat16(a.z), h3 = __float2bfloat16(a.w);
                *(uint2*)(Ah + off) = make_uint2(pack2(h0, h1), pack2(h2, h3));
                *(uint2*)(Al + off) = make_uint2(
                    pack2(__float2bfloat16(a.x - __bfloat162float(h0)),
                          __float2bfloat16(a.y - __bfloat162float(h1))),
                    pack2(__float2bfloat16(a.z - __bfloat162float(h2)),
                          __float2bfloat16(a.w - __bfloat162float(h3))));
            }
            {
                float4 b = bv[i];
                __nv_bfloat16 h0 = __float2bfloat16(b.x), h1 = __float2bfloat16(b.y),
                              h2 = __float2bfloat16(b.z), h3 = __float2bfloat16(b.w);
                *(uint2*)(Bh + off) = make_uint2(pack2(h0, h1), pack2(h2, h3));
                *(uint2*)(Bl + off) = make_uint2(
                    pack2(__float2bfloat16(b.x - __bfloat162float(h0)),
                          __float2bfloat16(b.y - __bfloat162float(h1))),
                    pack2(__float2bfloat16(b.z - __bfloat162float(h2)),
                          __float2bfloat16(b.w - __bfloat162float(h3))));
            }
        }
    };

    float acc[4][4][4] = {};

    auto compute = [&](int s) {
        const __nv_bfloat16 *Ah = arr(s, 0), *Al = arr(s, 1),
                            *Bh = arr(s, 2), *Bl = arr(s, 3);
#pragma unroll
        for (int ks = 0; ks < 2; ks++) {
            const int kb = ks * 16 + q * 2;
            uint32_t ah[4][4], bh[4][2];
#pragma unroll
            for (int mf = 0; mf < 4; mf++) {
                const __nv_bfloat16* p = Ah + (warp_m * 64 + mf * 16 + g) * ASTR + kb;
                ah[mf][0] = *(const uint32_t*)p;
                ah[mf][1] = *(const uint32_t*)(p + 8 * ASTR);
                ah[mf][2] = *(const uint32_t*)(p + 8);
                ah[mf][3] = *(const uint32_t*)(p + 8 * ASTR + 8);
            }
#pragma unroll
            for (int nf = 0; nf < 4; nf++) {
                const __nv_bfloat16* p = Bh + (warp_n * 32 + nf * 8 + g) * ASTR + kb;
                bh[nf][0] = *(const uint32_t*)p;
                bh[nf][1] = *(const uint32_t*)(p + 8);
            }
#pragma unroll
            for (int mf = 0; mf < 4; mf++)
#pragma unroll
                for (int nf = 0; nf < 4; nf++)
                    mma16816(acc[mf][nf], ah[mf], bh[nf]);
#pragma unroll
            for (int nf = 0; nf < 4; nf++) {
                const __nv_bfloat16* p = Bl + (warp_n * 32 + nf * 8 + g) * ASTR + kb;
                uint32_t bl[2] = { *(const uint32_t*)p, *(const uint32_t*)(p + 8) };
#pragma unroll
                for (int mf = 0; mf < 4; mf++)
                    mma16816(acc[mf][nf], ah[mf], bl);
            }
#pragma unroll
            for (int mf = 0; mf < 4; mf++) {
                const __nv_bfloat16* p = Al + (warp_m * 64 + mf * 16 + g) * ASTR + kb;
                uint32_t al[4] = { *(const uint32_t*)p,
                                   *(const uint32_t*)(p + 8 * ASTR),
                                   *(const uint32_t*)(p + 8),
                                   *(const uint32_t*)(p + 8 * ASTR + 8) };
#pragma unroll
                for (int nf = 0; nf < 4; nf++)
                    mma16816(acc[mf][nf], al, bh[nf]);
            }
        }
    };

    ldg(0); sts(0);
    __syncthreads();
    for (int kc = 0; kc < EMBD / BK; kc++) {
        compute(kc & 1);
        if (kc + 1 < EMBD / BK) {
            ldg(kc + 1);
            sts((kc + 1) & 1);
        }
        __syncthreads();
    }

    float* Ct = (float*)sm;   // [128][132]
#pragma unroll
    for (int mf = 0; mf < 4; mf++)
#pragma unroll
        for (int nf = 0; nf < 4; nf++) {
            const int r = warp_m * 64 + mf * 16 + g;
            const int c = warp_n * 32 + nf * 8 + q * 2;
            *(float2*)&Ct[r * 132 + c]       = make_float2(acc[mf][nf][0], acc[mf][nf][1]);
            *(float2*)&Ct[(r + 8) * 132 + c] = make_float2(acc[mf][nf][2], acc[mf][nf][3]);
        }
    __syncthreads();

    // Streamed epilogue: no large local arrays (avoid register spills)
    {
        const int row = tid >> 1;
        const int seg = tid & 1;
        const float* crow = &Ct[row * 132 + seg * 64];

        if (MODE == 2) {
            const int c0 = cb + seg * 64;
            float* dst = C + (size_t)(rb + row) * EMBD + c0;
#pragma unroll
            for (int j = 0; j < 16; j++) {
                float4 v = *(const float4*)&crow[4 * j];
                float4 b4 = *(const float4*)&bias[c0 + 4 * j];
                v.x += b4.x; v.y += b4.y; v.z += b4.z; v.w += b4.w;
                *(float4*)(dst + 4 * j) = v;
            }
        } else {
            float mean = 0.f, rstd = 0.f;
            if (MODE == 0) {
                float s = 0.f, s2 = 0.f;
#pragma unroll
                for (int j = 0; j < 16; j++) {
                    float4 v = *(const float4*)&crow[4 * j];
                    s  += v.x + v.y + v.z + v.w;
                    s2 += v.x * v.x + v.y * v.y + v.z * v.z + v.w * v.w;
                }
                mean = s * (1.0f / 64.0f);
                rstd = rsqrtf(s2 * (1.0f / 64.0f) - mean * mean + 1e-5f);
            }
            const int grow = rb + row;
            const int n = grow >> 11;
            const int l = grow & (LSEQ - 1);
            const int hd = (cb >> 6) + seg;
            const size_t off = ((size_t)((n * NHEAD + hd) * LSEQ + l)) * HDIM;
#pragma unroll
            for (int j = 0; j < 8; j++) {
                float v[8];
                *(float4*)&v[0] = *(const float4*)&crow[8 * j];
                *(float4*)&v[4] = *(const float4*)&crow[8 * j + 4];
                if (MODE == 0) {
#pragma unroll
                    for (int k2 = 0; k2 < 8; k2++)
                        v[k2] = (v[k2] - mean) * rstd * __ldg(gamma + 8 * j + k2)
                                + __ldg(beta + 8 * j + k2);
                }
                __half hh[8];
#pragma unroll
                for (int k2 = 0; k2 < 8; k2++) hh[k2] = __float2half_rn(v[k2]);
                *(uint4*)(Ch + off + 8 * j) = *(uint4*)hh;
                if (MODE == 0) {
                    __half ll[8];
#pragma unroll
                    for (int k2 = 0; k2 < 8; k2++)
                        ll[k2] = __float2half_rn(v[k2] - __half2float(hh[k2]));
                    *(uint4*)(Cl + off + 8 * j) = *(uint4*)ll;
                }
            }
        }
    }
}

// ---------------- Attention v4: 64q x 32k tiles, fp16-V, 4 CTAs/SM ----------------
#define APAD 72
#define KV_ARR_H (32 * APAD)             // halves per K/V array (32 rows)
#define STAGE_HALVES (3 * KV_ARR_H)      // Kh | Kl | Vh = 6912 halves (13824 B)
#define ATTN_SMEM (2 * STAGE_HALVES * 2) // 27648 bytes

#define LDSM_X4(r0, r1, r2, r3, addr) \
    asm volatile("ldmatrix.sync.aligned.m8n8.x4.shared.b16 {%0,%1,%2,%3}, [%4];" \
        : "=r"(r0), "=r"(r1), "=r"(r2), "=r"(r3) : "r"(addr))
#define LDSM_X2(r0, r1, addr) \
    asm volatile("ldmatrix.sync.aligned.m8n8.x2.shared.b16 {%0,%1}, [%2];" \
        : "=r"(r0), "=r"(r1) : "r"(addr))
#define LDSM_X2T(r0, r1, addr) \
    asm volatile("ldmatrix.sync.aligned.m8n8.x2.trans.shared.b16 {%0,%1}, [%2];" \
        : "=r"(r0), "=r"(r1) : "r"(addr))

__device__ __forceinline__ void mma_f16(float* c, const uint32_t* a, const uint32_t* b) {
    asm volatile(
        "mma.sync.aligned.m16n8k16.row.col.f32.f16.f16.f32 "
        "{%0,%1,%2,%3}, {%4,%5,%6,%7}, {%8,%9}, {%0,%1,%2,%3};"
        : "+f"(c[0]), "+f"(c[1]), "+f"(c[2]), "+f"(c[3])
        : "r"(a[0]), "r"(a[1]), "r"(a[2]), "r"(a[3]), "r"(b[0]), "r"(b[1]));
}

__device__ __forceinline__ uint32_t packh2(float a, float b) {
    __half2 h = __floats2half2_rn(a, b);
    return *reinterpret_cast<uint32_t*>(&h);
}

__device__ __forceinline__ void cp_async16(uint32_t dst, const void* src) {
    asm volatile("cp.async.cg.shared.global [%0], [%1], 16;" :: "r"(dst), "l"(src));
}
#define CP_COMMIT() asm volatile("cp.async.commit_group;" ::: "memory")
#define CP_WAIT(N)  asm volatile("cp.async.wait_group %0;" :: "n"(N) : "memory")

__global__ void __launch_bounds__(128, 4) attn_mma(
    const __half* __restrict__ Qh, const __half* __restrict__ Ql,
    const __half* __restrict__ Kh, const __half* __restrict__ Kl,
    const __half* __restrict__ Vh, float* __restrict__ O)
{
    extern __shared__ __half smh[];
    const uint32_t sbase = smem_u32(smh);

    const int tid  = threadIdx.x;
    const int lane = tid & 31;
    const int wid  = tid >> 5;      // 0..3
    const int g    = lane >> 2;     // 0..7
    const int t    = lane & 3;      // 0..3
    const int nh   = blockIdx.y;
    const int qt   = gridDim.x - 1 - blockIdx.x;   // heavy tiles first
    const int qb   = qt * 64;
    const size_t base = (size_t)nh * LSEQ * HDIM;

    // K/V staging coords: 32 rows x 64 halves; thread -> row t>>2, 16-half col group
    const int krow = tid >> 2;
    const int kcol = (tid & 3) * 16;
    const uint32_t kv_sm_off = ((uint32_t)krow * APAD + (uint32_t)kcol) * 2;

    auto stage_kv = [&](int b, int kt) {
        const size_t goff = base + (size_t)(kt * 32 + krow) * HDIM + kcol;
        const uint32_t s0 = sbase + (uint32_t)b * (STAGE_HALVES * 2) + kv_sm_off;
        cp_async16(s0,                        Kh + goff);
        cp_async16(s0 + 16,                   Kh + goff + 8);
        cp_async16(s0 + KV_ARR_H * 2,         Kl + goff);
        cp_async16(s0 + KV_ARR_H * 2 + 16,    Kl + goff + 8);
        cp_async16(s0 + KV_ARR_H * 4,         Vh + goff);
        cp_async16(s0 + KV_ARR_H * 4 + 16,    Vh + goff + 8);
    };

    // --- prologue: Q tile (64x64 hi+lo) staged across the stage region ---
    {
        const int qr = tid >> 1;
        const int qc = (tid & 1) * 32;
        const size_t goff = base + (size_t)(qb + qr) * HDIM + qc;
        const uint32_t s0 = sbase + ((uint32_t)qr * APAD + (uint32_t)qc) * 2;
#pragma unroll
        for (int i = 0; i < 4; i++) {
            cp_async16(s0 + i * 16,                    Qh + goff + i * 8);
            cp_async16(s0 + 64 * APAD * 2 + i * 16,    Ql + goff + i * 8);
        }
        CP_COMMIT();
        CP_WAIT(0);
    }
    __syncthreads();

    uint32_t qfh[4][4], qfl[4][4];
    {
        __half* q0 = smh;
        __half* q1 = smh + 64 * APAD;
        const int frow = wid * 16 + (lane & 15);
        const int fcol8 = (lane >> 4) << 3;
#pragma unroll
        for (int kc = 0; kc < 4; kc++) {
            LDSM_X4(qfh[kc][0], qfh[kc][1], qfh[kc][2], qfh[kc][3],
                    smem_u32(q0 + frow * APAD + kc * 16 + fcol8));
            LDSM_X4(qfl[kc][0], qfl[kc][1], qfl[kc][2], qfl[kc][3],
                    smem_u32(q1 + frow * APAD + kc * 16 + fcol8));
        }
    }
    __syncthreads();   // Q reads complete before staging overwrites the region

    stage_kv(0, 0);
    CP_COMMIT();

    float oc[8][4] = {};
    float m0 = -1e30f, m1 = -1e30f, l0 = 0.f, l1 = 0.f;

    const int kfr = lane & 7;
    const int kfc = ((lane & 15) >> 3) << 3;
    const int vfr = lane & 15;
    const int nkt = 2 * (qt + 1);

    for (int kt = 0; kt < nkt; kt++) {
        if (kt + 1 < nkt) { stage_kv((kt + 1) & 1, kt + 1); CP_COMMIT(); CP_WAIT(1); }
        else              { CP_WAIT(0); }
        __syncthreads();

        __half* Khp = smh + (kt & 1) * STAGE_HALVES;
        __half* Klp = Khp + KV_ARR_H;
        __half* Vhp = Khp + 2 * KV_ARR_H;

        // ---- S = Q K^T (3-product split), 64x32 ----
        float sc[4][4] = {};
#pragma unroll
        for (int kc = 0; kc < 4; kc++) {
#pragma unroll
            for (int nf = 0; nf < 4; nf++) {
                uint32_t bh[2], bl[2];
                LDSM_X2(bh[0], bh[1],
                        smem_u32(Khp + (nf * 8 + kfr) * APAD + kc * 16 + kfc));
                LDSM_X2(bl[0], bl[1],
                        smem_u32(Klp + (nf * 8 + kfr) * APAD + kc * 16 + kfc));
                mma_f16(sc[nf], qfh[kc], bh);
                mma_f16(sc[nf], qfh[kc], bl);
                mma_f16(sc[nf], qfl[kc], bh);
            }
        }

        // ---- causal mask (last two tiles only) ----
        if (kt >= 2 * qt) {
            const int diag = (kt - 2 * qt) * 32;   // 0 or 32
            const int r0 = wid * 16 + g - diag;
            const int r1 = r0 + 8;
#pragma unroll
            for (int nf = 0; nf < 4; nf++) {
                const int c0 = nf * 8 + 2 * t;
                if (c0     > r0) sc[nf][0] = -1e30f;
                if (c0 + 1 > r0) sc[nf][1] = -1e30f;
                if (c0     > r1) sc[nf][2] = -1e30f;
                if (c0 + 1 > r1) sc[nf][3] = -1e30f;
            }
        }

        // ---- online softmax ----
        {
            float rm0 = -1e30f, rm1 = -1e30f;
#pragma unroll
            for (int nf = 0; nf < 4; nf++) {
                rm0 = fmaxf(rm0, fmaxf(sc[nf][0], sc[nf][1]));
                rm1 = fmaxf(rm1, fmaxf(sc[nf][2], sc[nf][3]));
            }
            rm0 = fmaxf(rm0, __shfl_xor_sync(0xffffffffu, rm0, 1));
            rm0 = fmaxf(rm0, __shfl_xor_sync(0xffffffffu, rm0, 2));
            rm1 = fmaxf(rm1, __shfl_xor_sync(0xffffffffu, rm1, 1));
            rm1 = fmaxf(rm1, __shfl_xor_sync(0xffffffffu, rm1, 2));

            const float mn0 = fmaxf(m0, rm0), mn1 = fmaxf(m1, rm1);
            const float cr0 = __expf(m0 - mn0), cr1 = __expf(m1 - mn1);
            float rs0 = 0.f, rs1 = 0.f;
#pragma unroll
            for (int nf = 0; nf < 4; nf++) {
                sc[nf][0] = __expf(sc[nf][0] - mn0);
                sc[nf][1] = __expf(sc[nf][1] - mn0);
                sc[nf][2] = __expf(sc[nf][2] - mn1);
                sc[nf][3] = __expf(sc[nf][3] - mn1);
                rs0 += sc[nf][0] + sc[nf][1];
                rs1 += sc[nf][2] + sc[nf][3];
            }
            rs0 += __shfl_xor_sync(0xffffffffu, rs0, 1);
            rs0 += __shfl_xor_sync(0xffffffffu, rs0, 2);
            rs1 += __shfl_xor_sync(0xffffffffu, rs1, 1);
            rs1 += __shfl_xor_sync(0xffffffffu, rs1, 2);

            l0 = l0 * cr0 + rs0; l1 = l1 * cr1 + rs1;
            m0 = mn0; m1 = mn1;
#pragma unroll
            for (int nf = 0; nf < 8; nf++) {
                oc[nf][0] *= cr0; oc[nf][1] *= cr0;
                oc[nf][2] *= cr1; oc[nf][3] *= cr1;
            }
        }

        // ---- O += (Ph + Pl) Vh  (P split, V pre-quantized fp16) ----
#pragma unroll
        for (int kc = 0; kc < 2; kc++) {
            uint32_t pah[4], pal[4];
            {
                const float* e0 = sc[2 * kc];
                const float* e1 = sc[2 * kc + 1];
                __half h00 = __float2half_rn(e0[0]), h01 = __float2half_rn(e0[1]);
                __half h02 = __float2half_rn(e0[2]), h03 = __float2half_rn(e0[3]);
                __half h10 = __float2half_rn(e1[0]), h11 = __float2half_rn(e1[1]);
                __half h12 = __float2half_rn(e1[2]), h13 = __float2half_rn(e1[3]);
                __half2 p;
                p = __halves2half2(h00, h01); pah[0] = *(uint32_t*)&p;
                p = __halves2half2(h02, h03); pah[1] = *(uint32_t*)&p;
                p = __halves2half2(h10, h11); pah[2] = *(uint32_t*)&p;
                p = __halves2half2(h12, h13); pah[3] = *(uint32_t*)&p;
                pal[0] = packh2(e0[0] - __half2float(h00), e0[1] - __half2float(h01));
                pal[1] = packh2(e0[2] - __half2float(h02), e0[3] - __half2float(h03));
                pal[2] = packh2(e1[0] - __half2float(h10), e1[1] - __half2float(h11));
                pal[3] = packh2(e1[2] - __half2float(h12), e1[3] - __half2float(h13));
            }
#pragma unroll
            for (int nf = 0; nf < 8; nf++) {
                uint32_t vh[2];
                LDSM_X2T(vh[0], vh[1], smem_u32(Vhp + (kc * 16 + vfr) * APAD + nf * 8));
                mma_f16(oc[nf], pah, vh);
                mma_f16(oc[nf], pal, vh);
            }
        }
        __syncthreads();   // compute done before this buffer is re-staged
    }

    // ---- epilogue: normalize, scatter to [N, L, H*D] ----
    const float inv0 = 1.0f / l0, inv1 = 1.0f / l1;
    const int n = nh >> 4;
    const int h = nh & 15;
    const int r0 = qb + wid * 16 + g;
    const int r1 = r0 + 8;
#pragma unroll
    for (int nf = 0; nf < 8; nf++) {
        const int col = h * HDIM + nf * 8 + 2 * t;
        *(float2*)&O[(size_t)(n * LSEQ + r0) * EMBD + col] =
            make_float2(oc[nf][0] * inv0, oc[nf][1] * inv0);
        *(float2*)&O[(size_t)(n * LSEQ + r1) * EMBD + col] =
            make_float2(oc[nf][2] * inv1, oc[nf][3] * inv1);
    }
}

// ------------------------- launch -------------------------
extern "C" void kernel_launch(void* const* d_in, const int* in_sizes, int n_in,
                              void* d_out, int out_size)
{
    (void)in_sizes; (void)n_in; (void)out_size;
    const float* x  = (const float*)d_in[0];
    const float* Wq = (const float*)d_in[2];
    const float* Wk = (const float*)d_in[3];
    const float* Wv = (const float*)d_in[4];
    const float* gq = (const float*)d_in[5];
    const float* bq = (const float*)d_in[6];
    const float* gk = (const float*)d_in[7];
    const float* bk = (const float*)d_in[8];
    const float* Wo = (const float*)d_in[9];
    const float* bo = (const float*)d_in[10];
    float* out = (float*)d_out;

    __half *qh, *ql, *kh, *kl, *vh;
    float *ap;
    cudaGetSymbolAddress((void**)&qh, g_qh);
    cudaGetSymbolAddress((void**)&ql, g_ql);
    cudaGetSymbolAddress((void**)&kh, g_kh);
    cudaGetSymbolAddress((void**)&kl, g_kl);
    cudaGetSymbolAddress((void**)&vh, g_vh);
    cudaGetSymbolAddress((void**)&ap, g_attn);

    cudaFuncSetAttribute(bf16_gemm<0>, cudaFuncAttributeMaxDynamicSharedMemorySize, GEMM_SMEM);
    cudaFuncSetAttribute(bf16_gemm<1>, cudaFuncAttributeMaxDynamicSharedMemorySize, GEMM_SMEM);
    cudaFuncSetAttribute(bf16_gemm<2>, cudaFuncAttributeMaxDynamicSharedMemorySize, GEMM_SMEM);
    cudaFuncSetAttribute(attn_mma, cudaFuncAttributeMaxDynamicSharedMemorySize, ATTN_SMEM);

    dim3 gg(MROWS / 128, EMBD / 128);
    bf16_gemm<0><<<gg, 256, GEMM_SMEM>>>(x, Wq, gq, bq, nullptr, qh, ql, nullptr);
    bf16_gemm<0><<<gg, 256, GEMM_SMEM>>>(x, Wk, gk, bk, nullptr, kh, kl, nullptr);
    bf16_gemm<1><<<gg, 256, GEMM_SMEM>>>(x, Wv, nullptr, nullptr, nullptr, vh, nullptr, nullptr);

    attn_mma<<<dim3(LSEQ / 64, NBATCH * NHEAD), 128, ATTN_SMEM>>>(qh, ql, kh, kl, vh, ap);

    bf16_gemm<2><<<gg, 256, GEMM_SMEM>>>(ap, Wo, nullptr, nullptr, bo, nullptr, nullptr, out);
}

// round 8
// speedup vs baseline: 2.0059x; 1.1479x over previous
#include <cuda_runtime.h>
#include <cuda_fp16.h>
#include <cstdint>

// Problem constants
#define NBATCH 2
#define LSEQ   2048
#define EMBD   1024
#define NHEAD  16
#define HDIM   64
#define MROWS  (NBATCH * LSEQ)   // 4096
#define QKV_ELEMS (NBATCH * NHEAD * LSEQ * HDIM)
#define W_ELEMS (EMBD * EMBD)
#define X_ELEMS (MROWS * EMBD)

// Scratch (device globals: no allocation allowed)
__device__ __half g_xh[X_ELEMS], g_xl[X_ELEMS];
__device__ __half g_wqh[W_ELEMS], g_wql[W_ELEMS];
__device__ __half g_wkh[W_ELEMS], g_wkl[W_ELEMS];
__device__ __half g_wvh[W_ELEMS], g_wvl[W_ELEMS];
__device__ __half g_woh[W_ELEMS], g_wol[W_ELEMS];
__device__ __half g_qh[QKV_ELEMS], g_ql[QKV_ELEMS];
__device__ __half g_kh[QKV_ELEMS], g_kl[QKV_ELEMS];
__device__ __half g_vh[QKV_ELEMS];
__device__ __half g_oh[X_ELEMS], g_ol[X_ELEMS];

__device__ __forceinline__ uint32_t smem_u32(const void* p) {
    uint32_t a;
    asm("{ .reg .u64 t; cvta.to.shared.u64 t, %1; cvt.u32.u64 %0, t; }"
        : "=r"(a) : "l"(p));
    return a;
}
__device__ __forceinline__ uint32_t packh2(float a, float b) {
    __half2 h = __floats2half2_rn(a, b);
    return *reinterpret_cast<uint32_t*>(&h);
}
__device__ __forceinline__ void cp_async16(uint32_t dst, const void* src) {
    asm volatile("cp.async.cg.shared.global [%0], [%1], 16;" :: "r"(dst), "l"(src));
}
#define CP_COMMIT() asm volatile("cp.async.commit_group;" ::: "memory")
#define CP_WAIT(N)  asm volatile("cp.async.wait_group %0;" :: "n"(N) : "memory")

#define LDSM_X4(r0, r1, r2, r3, addr) \
    asm volatile("ldmatrix.sync.aligned.m8n8.x4.shared.b16 {%0,%1,%2,%3}, [%4];" \
        : "=r"(r0), "=r"(r1), "=r"(r2), "=r"(r3) : "r"(addr))
#define LDSM_X2(r0, r1, addr) \
    asm volatile("ldmatrix.sync.aligned.m8n8.x2.shared.b16 {%0,%1}, [%2];" \
        : "=r"(r0), "=r"(r1) : "r"(addr))
#define LDSM_X2T(r0, r1, addr) \
    asm volatile("ldmatrix.sync.aligned.m8n8.x2.trans.shared.b16 {%0,%1}, [%2];" \
        : "=r"(r0), "=r"(r1) : "r"(addr))

__device__ __forceinline__ void mma_f16(float* c, const uint32_t* a, const uint32_t* b) {
    asm volatile(
        "mma.sync.aligned.m16n8k16.row.col.f32.f16.f16.f32 "
        "{%0,%1,%2,%3}, {%4,%5,%6,%7}, {%8,%9}, {%0,%1,%2,%3};"
        : "+f"(c[0]), "+f"(c[1]), "+f"(c[2]), "+f"(c[3])
        : "r"(a[0]), "r"(a[1]), "r"(a[2]), "r"(a[3]), "r"(b[0]), "r"(b[1]));
}

// ---------------- split pass: fp32 -> fp16 hi/lo ----------------
__global__ void __launch_bounds__(256) split_f32(
    const float4* __restrict__ src, uint2* __restrict__ hi,
    uint2* __restrict__ lo, int n4)
{
    const int i = blockIdx.x * blockDim.x + threadIdx.x;
    if (i >= n4) return;
    float4 v = src[i];
    __half h0 = __float2half_rn(v.x), h1 = __float2half_rn(v.y),
           h2 = __float2half_rn(v.z), h3 = __float2half_rn(v.w);
    __half2 p01 = __halves2half2(h0, h1), p23 = __halves2half2(h2, h3);
    hi[i] = make_uint2(*(uint32_t*)&p01, *(uint32_t*)&p23);
    lo[i] = make_uint2(packh2(v.x - __half2float(h0), v.y - __half2float(h1)),
                       packh2(v.z - __half2float(h2), v.w - __half2float(h3)));
}

// ---------------- GEMM v2: pre-split fp16, cp.async + ldmatrix ----------------
#define GSTR 40                          // halves per smem row (ldmatrix conflict-free)
#define GARR_B (128 * GSTR * 2)          // 10240 B
#define GSTG_B (4 * GARR_B)              // 40960 B  (Ah|Al|Bh|Bl)
#define GEMM_SMEM (2 * GSTG_B)           // 81920 B (also covers 128x132 f32 C tile)

// C = A @ B^T, 3-product fp16 split. A:[4096,1024], B:[1024,1024] (rows = out cols).
// MODE 0: per-head LayerNorm, half hi+lo head-major output [N,H,L,D]
// MODE 1: half hi-only head-major output
// MODE 2: fp32 row-major output + bias
template <int MODE>
__global__ void __launch_bounds__(256, 2) h16_gemm(
    const __half* __restrict__ Ah_g, const __half* __restrict__ Al_g,
    const __half* __restrict__ Bh_g, const __half* __restrict__ Bl_g,
    const float* __restrict__ gamma, const float* __restrict__ beta,
    const float* __restrict__ bias,
    __half* __restrict__ Ch, __half* __restrict__ Cl, float* __restrict__ C)
{
    extern __shared__ char sm[];
    const uint32_t sbase = smem_u32(sm);
    const int tid  = threadIdx.x;
    const int lane = tid & 31;
    const int wid  = tid >> 5;
    const int warp_m = wid >> 2;   // 0..1
    const int warp_n = wid & 3;    // 0..3
    const int rb = blockIdx.x * 128;
    const int cb = blockIdx.y * 128;

    // staging coords: thread -> row tid>>1, k-offset (tid&1)*16 halves
    const int srow = tid >> 1;
    const int skoff = (tid & 1) * 16;
    const __half* Ap = Ah_g + (size_t)(rb + srow) * EMBD + skoff;
    const __half* Alp = Al_g + (size_t)(rb + srow) * EMBD + skoff;
    const __half* Bp = Bh_g + (size_t)(cb + srow) * EMBD + skoff;
    const __half* Blp = Bl_g + (size_t)(cb + srow) * EMBD + skoff;
    const uint32_t sdst = ((uint32_t)srow * GSTR + (uint32_t)skoff) * 2;

    auto stage = [&](int s, int kc) {
        const uint32_t d = sbase + (uint32_t)s * GSTG_B + sdst;
        const int go = kc * 32;
        cp_async16(d,                 Ap + go);
        cp_async16(d + 16,            Ap + go + 8);
        cp_async16(d + GARR_B,        Alp + go);
        cp_async16(d + GARR_B + 16,   Alp + go + 8);
        cp_async16(d + 2 * GARR_B,      Bp + go);
        cp_async16(d + 2 * GARR_B + 16, Bp + go + 8);
        cp_async16(d + 3 * GARR_B,      Blp + go);
        cp_async16(d + 3 * GARR_B + 16, Blp + go + 8);
    };

    float acc[4][4][4] = {};

    // fragment lane addressing
    const int afr = lane & 15;
    const int afc = (lane >> 4) << 3;
    const int bfr = lane & 7;
    const int bfc = ((lane & 15) >> 3) << 3;

    auto compute = [&](int s) {
        const __half* Ah = (const __half*)(sm + (size_t)s * GSTG_B);
        const __half* Al = (const __half*)(sm + (size_t)s * GSTG_B + GARR_B);
        const __half* Bh = (const __half*)(sm + (size_t)s * GSTG_B + 2 * GARR_B);
        const __half* Bl = (const __half*)(sm + (size_t)s * GSTG_B + 3 * GARR_B);
#pragma unroll
        for (int ks = 0; ks < 2; ks++) {
            uint32_t ah[4][4], al[4][4];
#pragma unroll
            for (int mf = 0; mf < 4; mf++) {
                const int r = warp_m * 64 + mf * 16 + afr;
                LDSM_X4(ah[mf][0], ah[mf][1], ah[mf][2], ah[mf][3],
                        smem_u32(Ah + r * GSTR + ks * 16 + afc));
                LDSM_X4(al[mf][0], al[mf][1], al[mf][2], al[mf][3],
                        smem_u32(Al + r * GSTR + ks * 16 + afc));
            }
#pragma unroll
            for (int nf = 0; nf < 4; nf++) {
                const int r = warp_n * 32 + nf * 8 + bfr;
                uint32_t bh[2], bl[2];
                LDSM_X2(bh[0], bh[1], smem_u32(Bh + r * GSTR + ks * 16 + bfc));
                LDSM_X2(bl[0], bl[1], smem_u32(Bl + r * GSTR + ks * 16 + bfc));
#pragma unroll
                for (int mf = 0; mf < 4; mf++) {
                    mma_f16(acc[mf][nf], ah[mf], bh);
                    mma_f16(acc[mf][nf], ah[mf], bl);
                    mma_f16(acc[mf][nf], al[mf], bh);
                }
            }
        }
    };

    stage(0, 0);
    CP_COMMIT();
    const int NC = EMBD / 32;
    for (int kc = 0; kc < NC; kc++) {
        if (kc + 1 < NC) { stage((kc + 1) & 1, kc + 1); CP_COMMIT(); CP_WAIT(1); }
        else             { CP_WAIT(0); }
        __syncthreads();
        compute(kc & 1);
        __syncthreads();
    }

    // C staging + streamed epilogue (R7-proven)
    const int g = lane >> 2;
    const int q = lane & 3;
    float* Ct = (float*)sm;   // [128][132]
#pragma unroll
    for (int mf = 0; mf < 4; mf++)
#pragma unroll
        for (int nf = 0; nf < 4; nf++) {
            const int r = warp_m * 64 + mf * 16 + g;
            const int c = warp_n * 32 + nf * 8 + q * 2;
            *(float2*)&Ct[r * 132 + c]       = make_float2(acc[mf][nf][0], acc[mf][nf][1]);
            *(float2*)&Ct[(r + 8) * 132 + c] = make_float2(acc[mf][nf][2], acc[mf][nf][3]);
        }
    __syncthreads();

    {
        const int row = tid >> 1;
        const int seg = tid & 1;
        const float* crow = &Ct[row * 132 + seg * 64];

        if (MODE == 2) {
            const int c0 = cb + seg * 64;
            float* dst = C + (size_t)(rb + row) * EMBD + c0;
#pragma unroll
            for (int j = 0; j < 16; j++) {
                float4 v = *(const float4*)&crow[4 * j];
                float4 b4 = *(const float4*)&bias[c0 + 4 * j];
                v.x += b4.x; v.y += b4.y; v.z += b4.z; v.w += b4.w;
                *(float4*)(dst + 4 * j) = v;
            }
        } else {
            float mean = 0.f, rstd = 0.f;
            if (MODE == 0) {
                float s = 0.f, s2 = 0.f;
#pragma unroll
                for (int j = 0; j < 16; j++) {
                    float4 v = *(const float4*)&crow[4 * j];
                    s  += v.x + v.y + v.z + v.w;
                    s2 += v.x * v.x + v.y * v.y + v.z * v.z + v.w * v.w;
                }
                mean = s * (1.0f / 64.0f);
                rstd = rsqrtf(s2 * (1.0f / 64.0f) - mean * mean + 1e-5f);
            }
            const int grow = rb + row;
            const int n = grow >> 11;
            const int l = grow & (LSEQ - 1);
            const int hd = (cb >> 6) + seg;
            const size_t off = ((size_t)((n * NHEAD + hd) * LSEQ + l)) * HDIM;
#pragma unroll
            for (int j = 0; j < 8; j++) {
                float v[8];
                *(float4*)&v[0] = *(const float4*)&crow[8 * j];
                *(float4*)&v[4] = *(const float4*)&crow[8 * j + 4];
                if (MODE == 0) {
#pragma unroll
                    for (int k2 = 0; k2 < 8; k2++)
                        v[k2] = (v[k2] - mean) * rstd * __ldg(gamma + 8 * j + k2)
                                + __ldg(beta + 8 * j + k2);
                }
                __half hh[8];
#pragma unroll
                for (int k2 = 0; k2 < 8; k2++) hh[k2] = __float2half_rn(v[k2]);
                *(uint4*)(Ch + off + 8 * j) = *(uint4*)hh;
                if (MODE == 0) {
                    __half ll[8];
#pragma unroll
                    for (int k2 = 0; k2 < 8; k2++)
                        ll[k2] = __float2half_rn(v[k2] - __half2float(hh[k2]));
                    *(uint4*)(Cl + off + 8 * j) = *(uint4*)ll;
                }
            }
        }
    }
}

// ---------------- Attention (R7-proven; epilogue now emits fp16 hi/lo) ----------------
#define APAD 72
#define KV_ARR_H (32 * APAD)
#define STAGE_HALVES (3 * KV_ARR_H)
#define ATTN_SMEM (2 * STAGE_HALVES * 2)

__global__ void __launch_bounds__(128, 4) attn_mma(
    const __half* __restrict__ Qh, const __half* __restrict__ Ql,
    const __half* __restrict__ Kh, const __half* __restrict__ Kl,
    const __half* __restrict__ Vh,
    __half* __restrict__ Oh, __half* __restrict__ Ol)
{
    extern __shared__ __half smh[];
    const uint32_t sbase = smem_u32(smh);

    const int tid  = threadIdx.x;
    const int lane = tid & 31;
    const int wid  = tid >> 5;
    const int g    = lane >> 2;
    const int t    = lane & 3;
    const int nh   = blockIdx.y;
    const int qt   = gridDim.x - 1 - blockIdx.x;
    const int qb   = qt * 64;
    const size_t base = (size_t)nh * LSEQ * HDIM;

    const int krow = tid >> 2;
    const int kcol = (tid & 3) * 16;
    const uint32_t kv_sm_off = ((uint32_t)krow * APAD + (uint32_t)kcol) * 2;

    auto stage_kv = [&](int b, int kt) {
        const size_t goff = base + (size_t)(kt * 32 + krow) * HDIM + kcol;
        const uint32_t s0 = sbase + (uint32_t)b * (STAGE_HALVES * 2) + kv_sm_off;
        cp_async16(s0,                        Kh + goff);
        cp_async16(s0 + 16,                   Kh + goff + 8);
        cp_async16(s0 + KV_ARR_H * 2,         Kl + goff);
        cp_async16(s0 + KV_ARR_H * 2 + 16,    Kl + goff + 8);
        cp_async16(s0 + KV_ARR_H * 4,         Vh + goff);
        cp_async16(s0 + KV_ARR_H * 4 + 16,    Vh + goff + 8);
    };

    {
        const int qr = tid >> 1;
        const int qc = (tid & 1) * 32;
        const size_t goff = base + (size_t)(qb + qr) * HDIM + qc;
        const uint32_t s0 = sbase + ((uint32_t)qr * APAD + (uint32_t)qc) * 2;
#pragma unroll
        for (int i = 0; i < 4; i++) {
            cp_async16(s0 + i * 16,                 Qh + goff + i * 8);
            cp_async16(s0 + 64 * APAD * 2 + i * 16, Ql + goff + i * 8);
        }
        CP_COMMIT();
        CP_WAIT(0);
    }
    __syncthreads();

    uint32_t qfh[4][4], qfl[4][4];
    {
        __half* q0 = smh;
        __half* q1 = smh + 64 * APAD;
        const int frow = wid * 16 + (lane & 15);
        const int fcol8 = (lane >> 4) << 3;
#pragma unroll
        for (int kc = 0; kc < 4; kc++) {
            LDSM_X4(qfh[kc][0], qfh[kc][1], qfh[kc][2], qfh[kc][3],
                    smem_u32(q0 + frow * APAD + kc * 16 + fcol8));
            LDSM_X4(qfl[kc][0], qfl[kc][1], qfl[kc][2], qfl[kc][3],
                    smem_u32(q1 + frow * APAD + kc * 16 + fcol8));
        }
    }
    __syncthreads();

    stage_kv(0, 0);
    CP_COMMIT();

    float oc[8][4] = {};
    float m0 = -1e30f, m1 = -1e30f, l0 = 0.f, l1 = 0.f;

    const int kfr = lane & 7;
    const int kfc = ((lane & 15) >> 3) << 3;
    const int vfr = lane & 15;
    const int nkt = 2 * (qt + 1);

    for (int kt = 0; kt < nkt; kt++) {
        if (kt + 1 < nkt) { stage_kv((kt + 1) & 1, kt + 1); CP_COMMIT(); CP_WAIT(1); }
        else              { CP_WAIT(0); }
        __syncthreads();

        __half* Khp = smh + (kt & 1) * STAGE_HALVES;
        __half* Klp = Khp + KV_ARR_H;
        __half* Vhp = Khp + 2 * KV_ARR_H;

        float sc[4][4] = {};
#pragma unroll
        for (int kc = 0; kc < 4; kc++) {
#pragma unroll
            for (int nf = 0; nf < 4; nf++) {
                uint32_t bh[2], bl[2];
                LDSM_X2(bh[0], bh[1],
                        smem_u32(Khp + (nf * 8 + kfr) * APAD + kc * 16 + kfc));
                LDSM_X2(bl[0], bl[1],
                        smem_u32(Klp + (nf * 8 + kfr) * APAD + kc * 16 + kfc));
                mma_f16(sc[nf], qfh[kc], bh);
                mma_f16(sc[nf], qfh[kc], bl);
                mma_f16(sc[nf], qfl[kc], bh);
            }
        }

        if (kt >= 2 * qt) {
            const int diag = (kt - 2 * qt) * 32;
            const int r0 = wid * 16 + g - diag;
            const int r1 = r0 + 8;
#pragma unroll
            for (int nf = 0; nf < 4; nf++) {
                const int c0 = nf * 8 + 2 * t;
                if (c0     > r0) sc[nf][0] = -1e30f;
                if (c0 + 1 > r0) sc[nf][1] = -1e30f;
                if (c0     > r1) sc[nf][2] = -1e30f;
                if (c0 + 1 > r1) sc[nf][3] = -1e30f;
            }
        }

        {
            float rm0 = -1e30f, rm1 = -1e30f;
#pragma unroll
            for (int nf = 0; nf < 4; nf++) {
                rm0 = fmaxf(rm0, fmaxf(sc[nf][0], sc[nf][1]));
                rm1 = fmaxf(rm1, fmaxf(sc[nf][2], sc[nf][3]));
            }
            rm0 = fmaxf(rm0, __shfl_xor_sync(0xffffffffu, rm0, 1));
            rm0 = fmaxf(rm0, __shfl_xor_sync(0xffffffffu, rm0, 2));
            rm1 = fmaxf(rm1, __shfl_xor_sync(0xffffffffu, rm1, 1));
            rm1 = fmaxf(rm1, __shfl_xor_sync(0xffffffffu, rm1, 2));

            const float mn0 = fmaxf(m0, rm0), mn1 = fmaxf(m1, rm1);
            const float cr0 = __expf(m0 - mn0), cr1 = __expf(m1 - mn1);
            float rs0 = 0.f, rs1 = 0.f;
#pragma unroll
            for (int nf = 0; nf < 4; nf++) {
                sc[nf][0] = __expf(sc[nf][0] - mn0);
                sc[nf][1] = __expf(sc[nf][1] - mn0);
                sc[nf][2] = __expf(sc[nf][2] - mn1);
                sc[nf][3] = __expf(sc[nf][3] - mn1);
                rs0 += sc[nf][0] + sc[nf][1];
                rs1 += sc[nf][2] + sc[nf][3];
            }
            rs0 += __shfl_xor_sync(0xffffffffu, rs0, 1);
            rs0 += __shfl_xor_sync(0xffffffffu, rs0, 2);
            rs1 += __shfl_xor_sync(0xffffffffu, rs1, 1);
            rs1 += __shfl_xor_sync(0xffffffffu, rs1, 2);

            l0 = l0 * cr0 + rs0; l1 = l1 * cr1 + rs1;
            m0 = mn0; m1 = mn1;
#pragma unroll
            for (int nf = 0; nf < 8; nf++) {
                oc[nf][0] *= cr0; oc[nf][1] *= cr0;
                oc[nf][2] *= cr1; oc[nf][3] *= cr1;
            }
        }

#pragma unroll
        for (int kc = 0; kc < 2; kc++) {
            uint32_t pah[4], pal[4];
            {
                const float* e0 = sc[2 * kc];
                const float* e1 = sc[2 * kc + 1];
                __half h00 = __float2half_rn(e0[0]), h01 = __float2half_rn(e0[1]);
                __half h02 = __float2half_rn(e0[2]), h03 = __float2half_rn(e0[3]);
                __half h10 = __float2half_rn(e1[0]), h11 = __float2half_rn(e1[1]);
                __half h12 = __float2half_rn(e1[2]), h13 = __float2half_rn(e1[3]);
                __half2 p;
                p = __halves2half2(h00, h01); pah[0] = *(uint32_t*)&p;
                p = __halves2half2(h02, h03); pah[1] = *(uint32_t*)&p;
                p = __halves2half2(h10, h11); pah[2] = *(uint32_t*)&p;
                p = __halves2half2(h12, h13); pah[3] = *(uint32_t*)&p;
                pal[0] = packh2(e0[0] - __half2float(h00), e0[1] - __half2float(h01));
                pal[1] = packh2(e0[2] - __half2float(h02), e0[3] - __half2float(h03));
                pal[2] = packh2(e1[0] - __half2float(h10), e1[1] - __half2float(h11));
                pal[3] = packh2(e1[2] - __half2float(h12), e1[3] - __half2float(h13));
            }
#pragma unroll
            for (int nf = 0; nf < 8; nf++) {
                uint32_t vh[2];
                LDSM_X2T(vh[0], vh[1], smem_u32(Vhp + (kc * 16 + vfr) * APAD + nf * 8));
                mma_f16(oc[nf], pah, vh);
                mma_f16(oc[nf], pal, vh);
            }
        }
        __syncthreads();
    }

    // epilogue: normalize, split to fp16 hi/lo, scatter to [N, L, H*D]
    const float inv0 = 1.0f / l0, inv1 = 1.0f / l1;
    const int n = nh >> 4;
    const int h = nh & 15;
    const int r0 = qb + wid * 16 + g;
    const int r1 = r0 + 8;
#pragma unroll
    for (int nf = 0; nf < 8; nf++) {
        const int col = h * HDIM + nf * 8 + 2 * t;
        const size_t i0 = (size_t)(n * LSEQ + r0) * EMBD + col;
        const size_t i1 = (size_t)(n * LSEQ + r1) * EMBD + col;
        float v00 = oc[nf][0] * inv0, v01 = oc[nf][1] * inv0;
        float v10 = oc[nf][2] * inv1, v11 = oc[nf][3] * inv1;
        __half a0 = __float2half_rn(v00), a1 = __float2half_rn(v01);
        __half b0 = __float2half_rn(v10), b1 = __float2half_rn(v11);
        __half2 hp;
        hp = __halves2half2(a0, a1); *(__half2*)(Oh + i0) = hp;
        hp = __halves2half2(b0, b1); *(__half2*)(Oh + i1) = hp;
        *(uint32_t*)(Ol + i0) = packh2(v00 - __half2float(a0), v01 - __half2float(a1));
        *(uint32_t*)(Ol + i1) = packh2(v10 - __half2float(b0), v11 - __half2float(b1));
    }
}

// ------------------------- launch -------------------------
extern "C" void kernel_launch(void* const* d_in, const int* in_sizes, int n_in,
                              void* d_out, int out_size)
{
    (void)in_sizes; (void)n_in; (void)out_size;
    const float* x  = (const float*)d_in[0];
    const float* Wq = (const float*)d_in[2];
    const float* Wk = (const float*)d_in[3];
    const float* Wv = (const float*)d_in[4];
    const float* gq = (const float*)d_in[5];
    const float* bq = (const float*)d_in[6];
    const float* gk = (const float*)d_in[7];
    const float* bk = (const float*)d_in[8];
    const float* Wo = (const float*)d_in[9];
    const float* bo = (const float*)d_in[10];
    float* out = (float*)d_out;

    __half *xh, *xl, *wqh, *wql, *wkh, *wkl, *wvh, *wvl, *woh, *wol;
    __half *qh, *ql, *kh, *kl, *vh, *oh, *ol;
    cudaGetSymbolAddress((void**)&xh, g_xh);   cudaGetSymbolAddress((void**)&xl, g_xl);
    cudaGetSymbolAddress((void**)&wqh, g_wqh); cudaGetSymbolAddress((void**)&wql, g_wql);
    cudaGetSymbolAddress((void**)&wkh, g_wkh); cudaGetSymbolAddress((void**)&wkl, g_wkl);
    cudaGetSymbolAddress((void**)&wvh, g_wvh); cudaGetSymbolAddress((void**)&wvl, g_wvl);
    cudaGetSymbolAddress((void**)&woh, g_woh); cudaGetSymbolAddress((void**)&wol, g_wol);
    cudaGetSymbolAddress((void**)&qh, g_qh);   cudaGetSymbolAddress((void**)&ql, g_ql);
    cudaGetSymbolAddress((void**)&kh, g_kh);   cudaGetSymbolAddress((void**)&kl, g_kl);
    cudaGetSymbolAddress((void**)&vh, g_vh);
    cudaGetSymbolAddress((void**)&oh, g_oh);   cudaGetSymbolAddress((void**)&ol, g_ol);

    cudaFuncSetAttribute(h16_gemm<0>, cudaFuncAttributeMaxDynamicSharedMemorySize, GEMM_SMEM);
    cudaFuncSetAttribute(h16_gemm<1>, cudaFuncAttributeMaxDynamicSharedMemorySize, GEMM_SMEM);
    cudaFuncSetAttribute(h16_gemm<2>, cudaFuncAttributeMaxDynamicSharedMemorySize, GEMM_SMEM);
    cudaFuncSetAttribute(attn_mma, cudaFuncAttributeMaxDynamicSharedMemorySize, ATTN_SMEM);

    // split passes
    const int xn4 = X_ELEMS / 4, wn4 = W_ELEMS / 4;
    split_f32<<<(xn4 + 255) / 256, 256>>>((const float4*)x,  (uint2*)xh,  (uint2*)xl,  xn4);
    split_f32<<<(wn4 + 255) / 256, 256>>>((const float4*)Wq, (uint2*)wqh, (uint2*)wql, wn4);
    split_f32<<<(wn4 + 255) / 256, 256>>>((const float4*)Wk, (uint2*)wkh, (uint2*)wkl, wn4);
    split_f32<<<(wn4 + 255) / 256, 256>>>((const float4*)Wv, (uint2*)wvh, (uint2*)wvl, wn4);
    split_f32<<<(wn4 + 255) / 256, 256>>>((const float4*)Wo, (uint2*)woh, (uint2*)wol, wn4);

    dim3 gg(MROWS / 128, EMBD / 128);
    h16_gemm<0><<<gg, 256, GEMM_SMEM>>>(xh, xl, wqh, wql, gq, bq, nullptr, qh, ql, nullptr);
    h16_gemm<0><<<gg, 256, GEMM_SMEM>>>(xh, xl, wkh, wkl, gk, bk, nullptr, kh, kl, nullptr);
    h16_gemm<1><<<gg, 256, GEMM_SMEM>>>(xh, xl, wvh, wvl, nullptr, nullptr, nullptr, vh, nullptr, nullptr);

    attn_mma<<<dim3(LSEQ / 64, NBATCH * NHEAD), 128, ATTN_SMEM>>>(qh, ql, kh, kl, vh, oh, ol);

    h16_gemm<2><<<gg, 256, GEMM_SMEM>>>(oh, ol, woh, wol, nullptr, nullptr, bo, nullptr, nullptr, out);
}

// round 9
// speedup vs baseline: 2.0364x; 1.0152x over previous
#include <cuda_runtime.h>
#include <cuda_fp16.h>
#include <cstdint>

// Problem constants
#define NBATCH 2
#define LSEQ   2048
#define EMBD   1024
#define NHEAD  16
#define HDIM   64
#define MROWS  (NBATCH * LSEQ)   // 4096
#define QKV_ELEMS (NBATCH * NHEAD * LSEQ * HDIM)
#define W_ELEMS (EMBD * EMBD)
#define X_ELEMS (MROWS * EMBD)

// Scratch (device globals: no allocation allowed)
__device__ __half g_xh[X_ELEMS], g_xl[X_ELEMS];
__device__ __half g_wqh[W_ELEMS], g_wql[W_ELEMS];
__device__ __half g_wkh[W_ELEMS], g_wkl[W_ELEMS];
__device__ __half g_wvh[W_ELEMS], g_wvl[W_ELEMS];
__device__ __half g_woh[W_ELEMS], g_wol[W_ELEMS];
__device__ __half g_qh[QKV_ELEMS], g_ql[QKV_ELEMS];
__device__ __half g_kh[QKV_ELEMS], g_kl[QKV_ELEMS];
__device__ __half g_vh[QKV_ELEMS];
__device__ __half g_oh[X_ELEMS], g_ol[X_ELEMS];

__device__ __forceinline__ uint32_t smem_u32(const void* p) {
    uint32_t a;
    asm("{ .reg .u64 t; cvta.to.shared.u64 t, %1; cvt.u32.u64 %0, t; }"
        : "=r"(a) : "l"(p));
    return a;
}
__device__ __forceinline__ uint32_t packh2(float a, float b) {
    __half2 h = __floats2half2_rn(a, b);
    return *reinterpret_cast<uint32_t*>(&h);
}
__device__ __forceinline__ void cp_async16(uint32_t dst, const void* src) {
    asm volatile("cp.async.cg.shared.global [%0], [%1], 16;" :: "r"(dst), "l"(src));
}
#define CP_COMMIT() asm volatile("cp.async.commit_group;" ::: "memory")
#define CP_WAIT(N)  asm volatile("cp.async.wait_group %0;" :: "n"(N) : "memory")

#define LDSM_X4(r0, r1, r2, r3, addr) \
    asm volatile("ldmatrix.sync.aligned.m8n8.x4.shared.b16 {%0,%1,%2,%3}, [%4];" \
        : "=r"(r0), "=r"(r1), "=r"(r2), "=r"(r3) : "r"(addr))
#define LDSM_X2(r0, r1, addr) \
    asm volatile("ldmatrix.sync.aligned.m8n8.x2.shared.b16 {%0,%1}, [%2];" \
        : "=r"(r0), "=r"(r1) : "r"(addr))
#define LDSM_X2T(r0, r1, addr) \
    asm volatile("ldmatrix.sync.aligned.m8n8.x2.trans.shared.b16 {%0,%1}, [%2];" \
        : "=r"(r0), "=r"(r1) : "r"(addr))

__device__ __forceinline__ void mma_f16(float* c, const uint32_t* a, const uint32_t* b) {
    asm volatile(
        "mma.sync.aligned.m16n8k16.row.col.f32.f16.f16.f32 "
        "{%0,%1,%2,%3}, {%4,%5,%6,%7}, {%8,%9}, {%0,%1,%2,%3};"
        : "+f"(c[0]), "+f"(c[1]), "+f"(c[2]), "+f"(c[3])
        : "r"(a[0]), "r"(a[1]), "r"(a[2]), "r"(a[3]), "r"(b[0]), "r"(b[1]));
}

// ---------------- split pass: fp32 -> fp16 hi/lo ----------------
__global__ void __launch_bounds__(256) split_f32(
    const float4* __restrict__ src, uint2* __restrict__ hi,
    uint2* __restrict__ lo, int n4)
{
    const int i = blockIdx.x * blockDim.x + threadIdx.x;
    if (i >= n4) return;
    float4 v = src[i];
    __half h0 = __float2half_rn(v.x), h1 = __float2half_rn(v.y),
           h2 = __float2half_rn(v.z), h3 = __float2half_rn(v.w);
    __half2 p01 = __halves2half2(h0, h1), p23 = __halves2half2(h2, h3);
    hi[i] = make_uint2(*(uint32_t*)&p01, *(uint32_t*)&p23);
    lo[i] = make_uint2(packh2(v.x - __half2float(h0), v.y - __half2float(h1)),
                       packh2(v.z - __half2float(h2), v.w - __half2float(h3)));
}

// ---------------- GEMM v3: pre-split fp16, burst-MMA, uint32 addressing ----------------
#define GSTR 40                          // halves per smem row (ldmatrix conflict-free)
#define GARR_B (128 * GSTR * 2)          // 10240 B
#define GSTG_B (4 * GARR_B)              // 40960 B  (Ah|Al|Bh|Bl)
#define GEMM_SMEM (2 * GSTG_B)           // 81920 B (also covers 128x132 f32 C tile)

// C = A @ B^T, 3-product fp16 split.
// MODE 0: per-head LayerNorm, half hi+lo head-major output [N,H,L,D]
// MODE 1: half hi-only head-major output
// MODE 2: fp32 row-major output + bias
template <int MODE>
__global__ void __launch_bounds__(256, 2) h16_gemm(
    const __half* __restrict__ Ah_g, const __half* __restrict__ Al_g,
    const __half* __restrict__ Bh_g, const __half* __restrict__ Bl_g,
    const float* __restrict__ gamma, const float* __restrict__ beta,
    const float* __restrict__ bias,
    __half* __restrict__ Ch, __half* __restrict__ Cl, float* __restrict__ C)
{
    extern __shared__ char sm[];
    const uint32_t sbase = smem_u32(sm);
    const int tid  = threadIdx.x;
    const int lane = tid & 31;
    const int wid  = tid >> 5;
    const int warp_m = wid >> 2;   // 0..1
    const int warp_n = wid & 3;    // 0..3
    const int rb = blockIdx.x * 128;
    const int cb = blockIdx.y * 128;

    // staging coords
    const int srow = tid >> 1;
    const int skoff = (tid & 1) * 16;
    const __half* Ap  = Ah_g + (size_t)(rb + srow) * EMBD + skoff;
    const __half* Alp = Al_g + (size_t)(rb + srow) * EMBD + skoff;
    const __half* Bp  = Bh_g + (size_t)(cb + srow) * EMBD + skoff;
    const __half* Blp = Bl_g + (size_t)(cb + srow) * EMBD + skoff;
    const uint32_t sdst = ((uint32_t)srow * GSTR + (uint32_t)skoff) * 2;

    auto stage = [&](int s, int kc) {
        const uint32_t d = sbase + (uint32_t)s * GSTG_B + sdst;
        const int go = kc * 32;
        cp_async16(d,                   Ap + go);
        cp_async16(d + 16,              Ap + go + 8);
        cp_async16(d + GARR_B,          Alp + go);
        cp_async16(d + GARR_B + 16,     Alp + go + 8);
        cp_async16(d + 2 * GARR_B,      Bp + go);
        cp_async16(d + 2 * GARR_B + 16, Bp + go + 8);
        cp_async16(d + 3 * GARR_B,      Blp + go);
        cp_async16(d + 3 * GARR_B + 16, Blp + go + 8);
    };

    float acc[4][4][4] = {};

    // fragment lane addressing (uint32, computed once)
    const int afr = lane & 15;
    const int afc = (lane >> 4) << 3;
    const int bfr = lane & 7;
    const int bfc = ((lane & 15) >> 3) << 3;
    const uint32_t aM = sbase + ((uint32_t)(warp_m * 64 + afr) * GSTR + (uint32_t)afc) * 2;
    const uint32_t bN = sbase + 2 * GARR_B
                      + ((uint32_t)(warp_n * 32 + bfr) * GSTR + (uint32_t)bfc) * 2;

    auto compute = [&](int s) {
        const uint32_t so = (uint32_t)s * GSTG_B;
#pragma unroll
        for (int ks = 0; ks < 2; ks++) {
            // preload all B fragments (hi+lo) for this k-slice
            uint32_t bh[4][2], bl[4][2];
#pragma unroll
            for (int nf = 0; nf < 4; nf++) {
                const uint32_t ba = bN + so + (uint32_t)(nf * (8 * GSTR * 2) + ks * 32);
                LDSM_X2(bh[nf][0], bh[nf][1], ba);
                LDSM_X2(bl[nf][0], bl[nf][1], ba + GARR_B);
            }
            // per-mf: one hi + one lo A load, then 12-MMA burst
#pragma unroll
            for (int mf = 0; mf < 4; mf++) {
                uint32_t ah[4], al[4];
                const uint32_t aa = aM + so + (uint32_t)(mf * (16 * GSTR * 2) + ks * 32);
                LDSM_X4(ah[0], ah[1], ah[2], ah[3], aa);
                LDSM_X4(al[0], al[1], al[2], al[3], aa + GARR_B);
#pragma unroll
                for (int nf = 0; nf < 4; nf++) {
                    mma_f16(acc[mf][nf], ah, bh[nf]);
                    mma_f16(acc[mf][nf], ah, bl[nf]);
                    mma_f16(acc[mf][nf], al, bh[nf]);
                }
            }
        }
    };

    stage(0, 0);
    CP_COMMIT();
    const int NC = EMBD / 32;
    for (int kc = 0; kc < NC; kc++) {
        if (kc + 1 < NC) { stage((kc + 1) & 1, kc + 1); CP_COMMIT(); CP_WAIT(1); }
        else             { CP_WAIT(0); }
        __syncthreads();
        compute(kc & 1);
        __syncthreads();
    }

    // C staging + streamed epilogue (R7-proven)
    const int g = lane >> 2;
    const int q = lane & 3;
    float* Ct = (float*)sm;   // [128][132]
#pragma unroll
    for (int mf = 0; mf < 4; mf++)
#pragma unroll
        for (int nf = 0; nf < 4; nf++) {
            const int r = warp_m * 64 + mf * 16 + g;
            const int c = warp_n * 32 + nf * 8 + q * 2;
            *(float2*)&Ct[r * 132 + c]       = make_float2(acc[mf][nf][0], acc[mf][nf][1]);
            *(float2*)&Ct[(r + 8) * 132 + c] = make_float2(acc[mf][nf][2], acc[mf][nf][3]);
        }
    __syncthreads();

    {
        const int row = tid >> 1;
        const int seg = tid & 1;
        const float* crow = &Ct[row * 132 + seg * 64];

        if (MODE == 2) {
            const int c0 = cb + seg * 64;
            float* dst = C + (size_t)(rb + row) * EMBD + c0;
#pragma unroll
            for (int j = 0; j < 16; j++) {
                float4 v = *(const float4*)&crow[4 * j];
                float4 b4 = *(const float4*)&bias[c0 + 4 * j];
                v.x += b4.x; v.y += b4.y; v.z += b4.z; v.w += b4.w;
                *(float4*)(dst + 4 * j) = v;
            }
        } else {
            float mean = 0.f, rstd = 0.f;
            if (MODE == 0) {
                float s = 0.f, s2 = 0.f;
#pragma unroll
                for (int j = 0; j < 16; j++) {
                    float4 v = *(const float4*)&crow[4 * j];
                    s  += v.x + v.y + v.z + v.w;
                    s2 += v.x * v.x + v.y * v.y + v.z * v.z + v.w * v.w;
                }
                mean = s * (1.0f / 64.0f);
                rstd = rsqrtf(s2 * (1.0f / 64.0f) - mean * mean + 1e-5f);
            }
            const int grow = rb + row;
            const int n = grow >> 11;
            const int l = grow & (LSEQ - 1);
            const int hd = (cb >> 6) + seg;
            const size_t off = ((size_t)((n * NHEAD + hd) * LSEQ + l)) * HDIM;
#pragma unroll
            for (int j = 0; j < 8; j++) {
                float v[8];
                *(float4*)&v[0] = *(const float4*)&crow[8 * j];
                *(float4*)&v[4] = *(const float4*)&crow[8 * j + 4];
                if (MODE == 0) {
#pragma unroll
                    for (int k2 = 0; k2 < 8; k2++)
                        v[k2] = (v[k2] - mean) * rstd * __ldg(gamma + 8 * j + k2)
                                + __ldg(beta + 8 * j + k2);
                }
                __half hh[8];
#pragma unroll
                for (int k2 = 0; k2 < 8; k2++) hh[k2] = __float2half_rn(v[k2]);
                *(uint4*)(Ch + off + 8 * j) = *(uint4*)hh;
                if (MODE == 0) {
                    __half ll[8];
#pragma unroll
                    for (int k2 = 0; k2 < 8; k2++)
                        ll[k2] = __float2half_rn(v[k2] - __half2float(hh[k2]));
                    *(uint4*)(Cl + off + 8 * j) = *(uint4*)ll;
                }
            }
        }
    }
}

// ---------------- Attention (R8 structure, uint32 addressing) ----------------
#define APAD 72
#define KV_ARR_H (32 * APAD)
#define STAGE_HALVES (3 * KV_ARR_H)
#define ATTN_SMEM (2 * STAGE_HALVES * 2)

__global__ void __launch_bounds__(128, 4) attn_mma(
    const __half* __restrict__ Qh, const __half* __restrict__ Ql,
    const __half* __restrict__ Kh, const __half* __restrict__ Kl,
    const __half* __restrict__ Vh,
    __half* __restrict__ Oh, __half* __restrict__ Ol)
{
    extern __shared__ __half smh[];
    const uint32_t sbase = smem_u32(smh);

    const int tid  = threadIdx.x;
    const int lane = tid & 31;
    const int wid  = tid >> 5;
    const int g    = lane >> 2;
    const int t    = lane & 3;
    const int nh   = blockIdx.y;
    const int qt   = gridDim.x - 1 - blockIdx.x;
    const int qb   = qt * 64;
    const size_t base = (size_t)nh * LSEQ * HDIM;

    const int krow = tid >> 2;
    const int kcol = (tid & 3) * 16;
    const uint32_t kv_sm_off = ((uint32_t)krow * APAD + (uint32_t)kcol) * 2;

    auto stage_kv = [&](int b, int kt) {
        const size_t goff = base + (size_t)(kt * 32 + krow) * HDIM + kcol;
        const uint32_t s0 = sbase + (uint32_t)b * (STAGE_HALVES * 2) + kv_sm_off;
        cp_async16(s0,                        Kh + goff);
        cp_async16(s0 + 16,                   Kh + goff + 8);
        cp_async16(s0 + KV_ARR_H * 2,         Kl + goff);
        cp_async16(s0 + KV_ARR_H * 2 + 16,    Kl + goff + 8);
        cp_async16(s0 + KV_ARR_H * 4,         Vh + goff);
        cp_async16(s0 + KV_ARR_H * 4 + 16,    Vh + goff + 8);
    };

    {
        const int qr = tid >> 1;
        const int qc = (tid & 1) * 32;
        const size_t goff = base + (size_t)(qb + qr) * HDIM + qc;
        const uint32_t s0 = sbase + ((uint32_t)qr * APAD + (uint32_t)qc) * 2;
#pragma unroll
        for (int i = 0; i < 4; i++) {
            cp_async16(s0 + i * 16,                 Qh + goff + i * 8);
            cp_async16(s0 + 64 * APAD * 2 + i * 16, Ql + goff + i * 8);
        }
        CP_COMMIT();
        CP_WAIT(0);
    }
    __syncthreads();

    uint32_t qfh[4][4], qfl[4][4];
    {
        const uint32_t qa = sbase
            + ((uint32_t)(wid * 16 + (lane & 15)) * APAD + (uint32_t)((lane >> 4) << 3)) * 2;
#pragma unroll
        for (int kc = 0; kc < 4; kc++) {
            LDSM_X4(qfh[kc][0], qfh[kc][1], qfh[kc][2], qfh[kc][3], qa + kc * 32);
            LDSM_X4(qfl[kc][0], qfl[kc][1], qfl[kc][2], qfl[kc][3],
                    qa + kc * 32 + 64 * APAD * 2);
        }
    }
    __syncthreads();

    stage_kv(0, 0);
    CP_COMMIT();

    float oc[8][4] = {};
    float m0 = -1e30f, m1 = -1e30f, l0 = 0.f, l1 = 0.f;

    // precomputed uint32 fragment bases (buffer 0; add stg per tile)
    const uint32_t kO = sbase
        + ((uint32_t)(lane & 7) * APAD + (uint32_t)(((lane & 15) >> 3) << 3)) * 2;
    const uint32_t vO = sbase + 4 * KV_ARR_H + (uint32_t)(lane & 15) * (APAD * 2);
    const int nkt = 2 * (qt + 1);

    for (int kt = 0; kt < nkt; kt++) {
        if (kt + 1 < nkt) { stage_kv((kt + 1) & 1, kt + 1); CP_COMMIT(); CP_WAIT(1); }
        else              { CP_WAIT(0); }
        __syncthreads();

        const uint32_t stg = (uint32_t)(kt & 1) * (STAGE_HALVES * 2);

        float sc[4][4] = {};
#pragma unroll
        for (int kc = 0; kc < 4; kc++) {
#pragma unroll
            for (int nf = 0; nf < 4; nf++) {
                const uint32_t ka = kO + stg + (uint32_t)(nf * (8 * APAD * 2) + kc * 32);
                uint32_t bh[2], bl[2];
                LDSM_X2(bh[0], bh[1], ka);
                LDSM_X2(bl[0], bl[1], ka + KV_ARR_H * 2);
                mma_f16(sc[nf], qfh[kc], bh);
                mma_f16(sc[nf], qfh[kc], bl);
                mma_f16(sc[nf], qfl[kc], bh);
            }
        }

        if (kt >= 2 * qt) {
            const int diag = (kt - 2 * qt) * 32;
            const int r0 = wid * 16 + g - diag;
            const int r1 = r0 + 8;
#pragma unroll
            for (int nf = 0; nf < 4; nf++) {
                const int c0 = nf * 8 + 2 * t;
                if (c0     > r0) sc[nf][0] = -1e30f;
                if (c0 + 1 > r0) sc[nf][1] = -1e30f;
                if (c0     > r1) sc[nf][2] = -1e30f;
                if (c0 + 1 > r1) sc[nf][3] = -1e30f;
            }
        }

        {
            float rm0 = -1e30f, rm1 = -1e30f;
#pragma unroll
            for (int nf = 0; nf < 4; nf++) {
                rm0 = fmaxf(rm0, fmaxf(sc[nf][0], sc[nf][1]));
                rm1 = fmaxf(rm1, fmaxf(sc[nf][2], sc[nf][3]));
            }
            rm0 = fmaxf(rm0, __shfl_xor_sync(0xffffffffu, rm0, 1));
            rm0 = fmaxf(rm0, __shfl_xor_sync(0xffffffffu, rm0, 2));
            rm1 = fmaxf(rm1, __shfl_xor_sync(0xffffffffu, rm1, 1));
            rm1 = fmaxf(rm1, __shfl_xor_sync(0xffffffffu, rm1, 2));

            const float mn0 = fmaxf(m0, rm0), mn1 = fmaxf(m1, rm1);
            const float cr0 = __expf(m0 - mn0), cr1 = __expf(m1 - mn1);
            float rs0 = 0.f, rs1 = 0.f;
#pragma unroll
            for (int nf = 0; nf < 4; nf++) {
                sc[nf][0] = __expf(sc[nf][0] - mn0);
                sc[nf][1] = __expf(sc[nf][1] - mn0);
                sc[nf][2] = __expf(sc[nf][2] - mn1);
                sc[nf][3] = __expf(sc[nf][3] - mn1);
                rs0 += sc[nf][0] + sc[nf][1];
                rs1 += sc[nf][2] + sc[nf][3];
            }
            rs0 += __shfl_xor_sync(0xffffffffu, rs0, 1);
            rs0 += __shfl_xor_sync(0xffffffffu, rs0, 2);
            rs1 += __shfl_xor_sync(0xffffffffu, rs1, 1);
            rs1 += __shfl_xor_sync(0xffffffffu, rs1, 2);

            l0 = l0 * cr0 + rs0; l1 = l1 * cr1 + rs1;
            m0 = mn0; m1 = mn1;
#pragma unroll
            for (int nf = 0; nf < 8; nf++) {
                oc[nf][0] *= cr0; oc[nf][1] *= cr0;
                oc[nf][2] *= cr1; oc[nf][3] *= cr1;
            }
        }

#pragma unroll
        for (int kc = 0; kc < 2; kc++) {
            uint32_t pah[4], pal[4];
            {
                const float* e0 = sc[2 * kc];
                const float* e1 = sc[2 * kc + 1];
                __half h00 = __float2half_rn(e0[0]), h01 = __float2half_rn(e0[1]);
                __half h02 = __float2half_rn(e0[2]), h03 = __float2half_rn(e0[3]);
                __half h10 = __float2half_rn(e1[0]), h11 = __float2half_rn(e1[1]);
                __half h12 = __float2half_rn(e1[2]), h13 = __float2half_rn(e1[3]);
                __half2 p;
                p = __halves2half2(h00, h01); pah[0] = *(uint32_t*)&p;
                p = __halves2half2(h02, h03); pah[1] = *(uint32_t*)&p;
                p = __halves2half2(h10, h11); pah[2] = *(uint32_t*)&p;
                p = __halves2half2(h12, h13); pah[3] = *(uint32_t*)&p;
                pal[0] = packh2(e0[0] - __half2float(h00), e0[1] - __half2float(h01));
                pal[1] = packh2(e0[2] - __half2float(h02), e0[3] - __half2float(h03));
                pal[2] = packh2(e1[0] - __half2float(h10), e1[1] - __half2float(h11));
                pal[3] = packh2(e1[2] - __half2float(h12), e1[3] - __half2float(h13));
            }
#pragma unroll
            for (int nf = 0; nf < 8; nf++) {
                uint32_t vh[2];
                LDSM_X2T(vh[0], vh[1],
                         vO + stg + (uint32_t)(kc * (16 * APAD * 2) + nf * 16));
                mma_f16(oc[nf], pah, vh);
                mma_f16(oc[nf], pal, vh);
            }
        }
        __syncthreads();
    }

    // epilogue: normalize, split to fp16 hi/lo, scatter to [N, L, H*D]
    const float inv0 = 1.0f / l0, inv1 = 1.0f / l1;
    const int n = nh >> 4;
    const int h = nh & 15;
    const int r0 = qb + wid * 16 + g;
    const int r1 = r0 + 8;
#pragma unroll
    for (int nf = 0; nf < 8; nf++) {
        const int col = h * HDIM + nf * 8 + 2 * t;
        const size_t i0 = (size_t)(n * LSEQ + r0) * EMBD + col;
        const size_t i1 = (size_t)(n * LSEQ + r1) * EMBD + col;
        float v00 = oc[nf][0] * inv0, v01 = oc[nf][1] * inv0;
        float v10 = oc[nf][2] * inv1, v11 = oc[nf][3] * inv1;
        __half a0 = __float2half_rn(v00), a1 = __float2half_rn(v01);
        __half b0 = __float2half_rn(v10), b1 = __float2half_rn(v11);
        __half2 hp;
        hp = __halves2half2(a0, a1); *(__half2*)(Oh + i0) = hp;
        hp = __halves2half2(b0, b1); *(__half2*)(Oh + i1) = hp;
        *(uint32_t*)(Ol + i0) = packh2(v00 - __half2float(a0), v01 - __half2float(a1));
        *(uint32_t*)(Ol + i1) = packh2(v10 - __half2float(b0), v11 - __half2float(b1));
    }
}

// ------------------------- launch -------------------------
extern "C" void kernel_launch(void* const* d_in, const int* in_sizes, int n_in,
                              void* d_out, int out_size)
{
    (void)in_sizes; (void)n_in; (void)out_size;
    const float* x  = (const float*)d_in[0];
    const float* Wq = (const float*)d_in[2];
    const float* Wk = (const float*)d_in[3];
    const float* Wv = (const float*)d_in[4];
    const float* gq = (const float*)d_in[5];
    const float* bq = (const float*)d_in[6];
    const float* gk = (const float*)d_in[7];
    const float* bk = (const float*)d_in[8];
    const float* Wo = (const float*)d_in[9];
    const float* bo = (const float*)d_in[10];
    float* out = (float*)d_out;

    __half *xh, *xl, *wqh, *wql, *wkh, *wkl, *wvh, *wvl, *woh, *wol;
    __half *qh, *ql, *kh, *kl, *vh, *oh, *ol;
    cudaGetSymbolAddress((void**)&xh, g_xh);   cudaGetSymbolAddress((void**)&xl, g_xl);
    cudaGetSymbolAddress((void**)&wqh, g_wqh); cudaGetSymbolAddress((void**)&wql, g_wql);
    cudaGetSymbolAddress((void**)&wkh, g_wkh); cudaGetSymbolAddress((void**)&wkl, g_wkl);
    cudaGetSymbolAddress((void**)&wvh, g_wvh); cudaGetSymbolAddress((void**)&wvl, g_wvl);
    cudaGetSymbolAddress((void**)&woh, g_woh); cudaGetSymbolAddress((void**)&wol, g_wol);
    cudaGetSymbolAddress((void**)&qh, g_qh);   cudaGetSymbolAddress((void**)&ql, g_ql);
    cudaGetSymbolAddress((void**)&kh, g_kh);   cudaGetSymbolAddress((void**)&kl, g_kl);
    cudaGetSymbolAddress((void**)&vh, g_vh);
    cudaGetSymbolAddress((void**)&oh, g_oh);   cudaGetSymbolAddress((void**)&ol, g_ol);

    cudaFuncSetAttribute(h16_gemm<0>, cudaFuncAttributeMaxDynamicSharedMemorySize, GEMM_SMEM);
    cudaFuncSetAttribute(h16_gemm<1>, cudaFuncAttributeMaxDynamicSharedMemorySize, GEMM_SMEM);
    cudaFuncSetAttribute(h16_gemm<2>, cudaFuncAttributeMaxDynamicSharedMemorySize, GEMM_SMEM);
    cudaFuncSetAttribute(attn_mma, cudaFuncAttributeMaxDynamicSharedMemorySize, ATTN_SMEM);

    // split passes (5 launches; keeps ncu -s 5 landing on h16_gemm<0>)
    const int xn4 = X_ELEMS / 4, wn4 = W_ELEMS / 4;
    split_f32<<<(xn4 + 255) / 256, 256>>>((const float4*)x,  (uint2*)xh,  (uint2*)xl,  xn4);
    split_f32<<<(wn4 + 255) / 256, 256>>>((const float4*)Wq, (uint2*)wqh, (uint2*)wql, wn4);
    split_f32<<<(wn4 + 255) / 256, 256>>>((const float4*)Wk, (uint2*)wkh, (uint2*)wkl, wn4);
    split_f32<<<(wn4 + 255) / 256, 256>>>((const float4*)Wv, (uint2*)wvh, (uint2*)wvl, wn4);
    split_f32<<<(wn4 + 255) / 256, 256>>>((const float4*)Wo, (uint2*)woh, (uint2*)wol, wn4);

    dim3 gg(MROWS / 128, EMBD / 128);
    h16_gemm<0><<<gg, 256, GEMM_SMEM>>>(xh, xl, wqh, wql, gq, bq, nullptr, qh, ql, nullptr);
    h16_gemm<0><<<gg, 256, GEMM_SMEM>>>(xh, xl, wkh, wkl, gk, bk, nullptr, kh, kl, nullptr);
    h16_gemm<1><<<gg, 256, GEMM_SMEM>>>(xh, xl, wvh, wvl, nullptr, nullptr, nullptr, vh, nullptr, nullptr);

    attn_mma<<<dim3(LSEQ / 64, NBATCH * NHEAD), 128, ATTN_SMEM>>>(qh, ql, kh, kl, vh, oh, ol);

    h16_gemm<2><<<gg, 256, GEMM_SMEM>>>(oh, ol, woh, wol, nullptr, nullptr, bo, nullptr, nullptr, out);
}

// round 10
// speedup vs baseline: 2.3501x; 1.1540x over previous
#include <cuda_runtime.h>
#include <cuda_fp16.h>
#include <cstdint>

// Problem constants
#define NBATCH 2
#define LSEQ   2048
#define EMBD   1024
#define NHEAD  16
#define HDIM   64
#define MROWS  (NBATCH * LSEQ)   // 4096
#define QKV_ELEMS (NBATCH * NHEAD * LSEQ * HDIM)
#define W_ELEMS (EMBD * EMBD)
#define X_ELEMS (MROWS * EMBD)

// Scratch (device globals: no allocation allowed)
__device__ __half g_xh[X_ELEMS], g_xl[X_ELEMS];
__device__ __half g_wqh[W_ELEMS], g_wql[W_ELEMS];
__device__ __half g_wkh[W_ELEMS], g_wkl[W_ELEMS];
__device__ __half g_wvh[W_ELEMS], g_wvl[W_ELEMS];
__device__ __half g_woh[W_ELEMS], g_wol[W_ELEMS];
__device__ __half g_qh[QKV_ELEMS], g_ql[QKV_ELEMS];
__device__ __half g_kh[QKV_ELEMS], g_kl[QKV_ELEMS];
__device__ __half g_vh[QKV_ELEMS];
__device__ __half g_oh[X_ELEMS];

__device__ __forceinline__ uint32_t smem_u32(const void* p) {
    uint32_t a;
    asm("{ .reg .u64 t; cvta.to.shared.u64 t, %1; cvt.u32.u64 %0, t; }"
        : "=r"(a) : "l"(p));
    return a;
}
__device__ __forceinline__ uint32_t packh2(float a, float b) {
    __half2 h = __floats2half2_rn(a, b);
    return *reinterpret_cast<uint32_t*>(&h);
}
__device__ __forceinline__ void cp_async16(uint32_t dst, const void* src) {
    asm volatile("cp.async.cg.shared.global [%0], [%1], 16;" :: "r"(dst), "l"(src));
}
#define CP_COMMIT() asm volatile("cp.async.commit_group;" ::: "memory")
#define CP_WAIT(N)  asm volatile("cp.async.wait_group %0;" :: "n"(N) : "memory")

#define LDSM_X4(r0, r1, r2, r3, addr) \
    asm volatile("ldmatrix.sync.aligned.m8n8.x4.shared.b16 {%0,%1,%2,%3}, [%4];" \
        : "=r"(r0), "=r"(r1), "=r"(r2), "=r"(r3) : "r"(addr))
#define LDSM_X2(r0, r1, addr) \
    asm volatile("ldmatrix.sync.aligned.m8n8.x2.shared.b16 {%0,%1}, [%2];" \
        : "=r"(r0), "=r"(r1) : "r"(addr))
#define LDSM_X2T(r0, r1, addr) \
    asm volatile("ldmatrix.sync.aligned.m8n8.x2.trans.shared.b16 {%0,%1}, [%2];" \
        : "=r"(r0), "=r"(r1) : "r"(addr))

__device__ __forceinline__ void mma_f16(float* c, const uint32_t* a, const uint32_t* b) {
    asm volatile(
        "mma.sync.aligned.m16n8k16.row.col.f32.f16.f16.f32 "
        "{%0,%1,%2,%3}, {%4,%5,%6,%7}, {%8,%9}, {%0,%1,%2,%3};"
        : "+f"(c[0]), "+f"(c[1]), "+f"(c[2]), "+f"(c[3])
        : "r"(a[0]), "r"(a[1]), "r"(a[2]), "r"(a[3]), "r"(b[0]), "r"(b[1]));
}

// ---------------- split pass: fp32 -> fp16 hi/lo ----------------
__global__ void __launch_bounds__(256) split_f32(
    const float4* __restrict__ src, uint2* __restrict__ hi,
    uint2* __restrict__ lo, int n4)
{
    const int i = blockIdx.x * blockDim.x + threadIdx.x;
    if (i >= n4) return;
    float4 v = src[i];
    __half h0 = __float2half_rn(v.x), h1 = __float2half_rn(v.y),
           h2 = __float2half_rn(v.z), h3 = __float2half_rn(v.w);
    __half2 p01 = __halves2half2(h0, h1), p23 = __halves2half2(h2, h3);
    hi[i] = make_uint2(*(uint32_t*)&p01, *(uint32_t*)&p23);
    lo[i] = make_uint2(packh2(v.x - __half2float(h0), v.y - __half2float(h1)),
                       packh2(v.z - __half2float(h2), v.w - __half2float(h3)));
}

// ---------------- GEMM: pre-split fp16, 2- or 3-product ----------------
#define GSTR 40                          // halves per smem row (ldmatrix conflict-free)
#define GARR_B (128 * GSTR * 2)          // 10240 B
#define GEMM_SMEM 81920                  // covers 2 stages (max 4 arrays) + C tile

// C = A @ B^T.
// NPROD 3: Ah*Bh + Ah*Bl + Al*Bh (arrays Ah|Al|Bh|Bl)
// NPROD 2: Ah*Bh + Ah*Bl         (arrays Ah|Bh|Bl; Al_g unused)
// MODE 0: per-head LayerNorm, half hi+lo head-major output [N,H,L,D]
// MODE 1: half hi-only head-major output
// MODE 2: fp32 row-major output + bias
template <int MODE, int NPROD>
__global__ void __launch_bounds__(256, 2) h16_gemm(
    const __half* __restrict__ Ah_g, const __half* __restrict__ Al_g,
    const __half* __restrict__ Bh_g, const __half* __restrict__ Bl_g,
    const float* __restrict__ gamma, const float* __restrict__ beta,
    const float* __restrict__ bias,
    __half* __restrict__ Ch, __half* __restrict__ Cl, float* __restrict__ C)
{
    constexpr uint32_t BOFF  = (NPROD == 3 ? 2u : 1u) * GARR_B;  // Bh array offset
    constexpr uint32_t GSTG  = (NPROD == 3 ? 4u : 3u) * GARR_B;  // bytes per stage

    extern __shared__ char sm[];
    const uint32_t sbase = smem_u32(sm);
    const int tid  = threadIdx.x;
    const int lane = tid & 31;
    const int wid  = tid >> 5;
    const int warp_m = wid >> 2;   // 0..1
    const int warp_n = wid & 3;    // 0..3
    const int rb = blockIdx.x * 128;
    const int cb = blockIdx.y * 128;

    // staging coords
    const int srow = tid >> 1;
    const int skoff = (tid & 1) * 16;
    const __half* Ap  = Ah_g + (size_t)(rb + srow) * EMBD + skoff;
    const __half* Alp = (NPROD == 3) ? Al_g + (size_t)(rb + srow) * EMBD + skoff : nullptr;
    const __half* Bp  = Bh_g + (size_t)(cb + srow) * EMBD + skoff;
    const __half* Blp = Bl_g + (size_t)(cb + srow) * EMBD + skoff;
    const uint32_t sdst = ((uint32_t)srow * GSTR + (uint32_t)skoff) * 2;

    auto stage = [&](int s, int kc) {
        const uint32_t d = sbase + (uint32_t)s * GSTG + sdst;
        const int go = kc * 32;
        cp_async16(d,                 Ap + go);
        cp_async16(d + 16,            Ap + go + 8);
        if (NPROD == 3) {
            cp_async16(d + GARR_B,      Alp + go);
            cp_async16(d + GARR_B + 16, Alp + go + 8);
        }
        cp_async16(d + BOFF,               Bp + go);
        cp_async16(d + BOFF + 16,          Bp + go + 8);
        cp_async16(d + BOFF + GARR_B,      Blp + go);
        cp_async16(d + BOFF + GARR_B + 16, Blp + go + 8);
    };

    float acc[4][4][4] = {};

    // fragment lane addressing (uint32, computed once)
    const int afr = lane & 15;
    const int afc = (lane >> 4) << 3;
    const int bfr = lane & 7;
    const int bfc = ((lane & 15) >> 3) << 3;
    const uint32_t aM = sbase + ((uint32_t)(warp_m * 64 + afr) * GSTR + (uint32_t)afc) * 2;
    const uint32_t bN = sbase + BOFF
                      + ((uint32_t)(warp_n * 32 + bfr) * GSTR + (uint32_t)bfc) * 2;

    auto compute = [&](int s) {
        const uint32_t so = (uint32_t)s * GSTG;
#pragma unroll
        for (int ks = 0; ks < 2; ks++) {
            uint32_t bh[4][2], bl[4][2];
#pragma unroll
            for (int nf = 0; nf < 4; nf++) {
                const uint32_t ba = bN + so + (uint32_t)(nf * (8 * GSTR * 2) + ks * 32);
                LDSM_X2(bh[nf][0], bh[nf][1], ba);
                LDSM_X2(bl[nf][0], bl[nf][1], ba + GARR_B);
            }
#pragma unroll
            for (int mf = 0; mf < 4; mf++) {
                uint32_t ah[4], al[4];
                const uint32_t aa = aM + so + (uint32_t)(mf * (16 * GSTR * 2) + ks * 32);
                LDSM_X4(ah[0], ah[1], ah[2], ah[3], aa);
                if (NPROD == 3) { LDSM_X4(al[0], al[1], al[2], al[3], aa + GARR_B); }
#pragma unroll
                for (int nf = 0; nf < 4; nf++) {
                    mma_f16(acc[mf][nf], ah, bh[nf]);
                    mma_f16(acc[mf][nf], ah, bl[nf]);
                    if (NPROD == 3) mma_f16(acc[mf][nf], al, bh[nf]);
                }
            }
        }
    };

    stage(0, 0);
    CP_COMMIT();
    const int NC = EMBD / 32;
    for (int kc = 0; kc < NC; kc++) {
        if (kc + 1 < NC) { stage((kc + 1) & 1, kc + 1); CP_COMMIT(); CP_WAIT(1); }
        else             { CP_WAIT(0); }
        __syncthreads();
        compute(kc & 1);
        __syncthreads();
    }

    // C staging + streamed epilogue
    const int g = lane >> 2;
    const int q = lane & 3;
    float* Ct = (float*)sm;   // [128][132]
#pragma unroll
    for (int mf = 0; mf < 4; mf++)
#pragma unroll
        for (int nf = 0; nf < 4; nf++) {
            const int r = warp_m * 64 + mf * 16 + g;
            const int c = warp_n * 32 + nf * 8 + q * 2;
            *(float2*)&Ct[r * 132 + c]       = make_float2(acc[mf][nf][0], acc[mf][nf][1]);
            *(float2*)&Ct[(r + 8) * 132 + c] = make_float2(acc[mf][nf][2], acc[mf][nf][3]);
        }
    __syncthreads();

    {
        const int row = tid >> 1;
        const int seg = tid & 1;
        const float* crow = &Ct[row * 132 + seg * 64];

        if (MODE == 2) {
            const int c0 = cb + seg * 64;
            float* dst = C + (size_t)(rb + row) * EMBD + c0;
#pragma unroll
            for (int j = 0; j < 16; j++) {
                float4 v = *(const float4*)&crow[4 * j];
                float4 b4 = *(const float4*)&bias[c0 + 4 * j];
                v.x += b4.x; v.y += b4.y; v.z += b4.z; v.w += b4.w;
                *(float4*)(dst + 4 * j) = v;
            }
        } else {
            float mean = 0.f, rstd = 0.f;
            if (MODE == 0) {
                float s = 0.f, s2 = 0.f;
#pragma unroll
                for (int j = 0; j < 16; j++) {
                    float4 v = *(const float4*)&crow[4 * j];
                    s  += v.x + v.y + v.z + v.w;
                    s2 += v.x * v.x + v.y * v.y + v.z * v.z + v.w * v.w;
                }
                mean = s * (1.0f / 64.0f);
                rstd = rsqrtf(s2 * (1.0f / 64.0f) - mean * mean + 1e-5f);
            }
            const int grow = rb + row;
            const int n = grow >> 11;
            const int l = grow & (LSEQ - 1);
            const int hd = (cb >> 6) + seg;
            const size_t off = ((size_t)((n * NHEAD + hd) * LSEQ + l)) * HDIM;
#pragma unroll
            for (int j = 0; j < 8; j++) {
                float v[8];
                *(float4*)&v[0] = *(const float4*)&crow[8 * j];
                *(float4*)&v[4] = *(const float4*)&crow[8 * j + 4];
                if (MODE == 0) {
#pragma unroll
                    for (int k2 = 0; k2 < 8; k2++)
                        v[k2] = (v[k2] - mean) * rstd * __ldg(gamma + 8 * j + k2)
                                + __ldg(beta + 8 * j + k2);
                }
                __half hh[8];
#pragma unroll
                for (int k2 = 0; k2 < 8; k2++) hh[k2] = __float2half_rn(v[k2]);
                *(uint4*)(Ch + off + 8 * j) = *(uint4*)hh;
                if (MODE == 0) {
                    __half ll[8];
#pragma unroll
                    for (int k2 = 0; k2 < 8; k2++)
                        ll[k2] = __float2half_rn(v[k2] - __half2float(hh[k2]));
                    *(uint4*)(Cl + off + 8 * j) = *(uint4*)ll;
                }
            }
        }
    }
}

// ---------------- Attention: 1-product PV, hi-only O output ----------------
#define APAD 72
#define KV_ARR_H (32 * APAD)
#define STAGE_HALVES (3 * KV_ARR_H)
#define ATTN_SMEM (2 * STAGE_HALVES * 2)

__global__ void __launch_bounds__(128, 4) attn_mma(
    const __half* __restrict__ Qh, const __half* __restrict__ Ql,
    const __half* __restrict__ Kh, const __half* __restrict__ Kl,
    const __half* __restrict__ Vh, __half* __restrict__ Oh)
{
    extern __shared__ __half smh[];
    const uint32_t sbase = smem_u32(smh);

    const int tid  = threadIdx.x;
    const int lane = tid & 31;
    const int wid  = tid >> 5;
    const int g    = lane >> 2;
    const int t    = lane & 3;
    const int nh   = blockIdx.y;
    const int qt   = gridDim.x - 1 - blockIdx.x;
    const int qb   = qt * 64;
    const size_t base = (size_t)nh * LSEQ * HDIM;

    const int krow = tid >> 2;
    const int kcol = (tid & 3) * 16;
    const uint32_t kv_sm_off = ((uint32_t)krow * APAD + (uint32_t)kcol) * 2;

    auto stage_kv = [&](int b, int kt) {
        const size_t goff = base + (size_t)(kt * 32 + krow) * HDIM + kcol;
        const uint32_t s0 = sbase + (uint32_t)b * (STAGE_HALVES * 2) + kv_sm_off;
        cp_async16(s0,                        Kh + goff);
        cp_async16(s0 + 16,                   Kh + goff + 8);
        cp_async16(s0 + KV_ARR_H * 2,         Kl + goff);
        cp_async16(s0 + KV_ARR_H * 2 + 16,    Kl + goff + 8);
        cp_async16(s0 + KV_ARR_H * 4,         Vh + goff);
        cp_async16(s0 + KV_ARR_H * 4 + 16,    Vh + goff + 8);
    };

    {
        const int qr = tid >> 1;
        const int qc = (tid & 1) * 32;
        const size_t goff = base + (size_t)(qb + qr) * HDIM + qc;
        const uint32_t s0 = sbase + ((uint32_t)qr * APAD + (uint32_t)qc) * 2;
#pragma unroll
        for (int i = 0; i < 4; i++) {
            cp_async16(s0 + i * 16,                 Qh + goff + i * 8);
            cp_async16(s0 + 64 * APAD * 2 + i * 16, Ql + goff + i * 8);
        }
        CP_COMMIT();
        CP_WAIT(0);
    }
    __syncthreads();

    uint32_t qfh[4][4], qfl[4][4];
    {
        const uint32_t qa = sbase
            + ((uint32_t)(wid * 16 + (lane & 15)) * APAD + (uint32_t)((lane >> 4) << 3)) * 2;
#pragma unroll
        for (int kc = 0; kc < 4; kc++) {
            LDSM_X4(qfh[kc][0], qfh[kc][1], qfh[kc][2], qfh[kc][3], qa + kc * 32);
            LDSM_X4(qfl[kc][0], qfl[kc][1], qfl[kc][2], qfl[kc][3],
                    qa + kc * 32 + 64 * APAD * 2);
        }
    }
    __syncthreads();

    stage_kv(0, 0);
    CP_COMMIT();

    float oc[8][4] = {};
    float m0 = -1e30f, m1 = -1e30f, l0 = 0.f, l1 = 0.f;

    const uint32_t kO = sbase
        + ((uint32_t)(lane & 7) * APAD + (uint32_t)(((lane & 15) >> 3) << 3)) * 2;
    const uint32_t vO = sbase + 4 * KV_ARR_H + (uint32_t)(lane & 15) * (APAD * 2);
    const int nkt = 2 * (qt + 1);

    for (int kt = 0; kt < nkt; kt++) {
        if (kt + 1 < nkt) { stage_kv((kt + 1) & 1, kt + 1); CP_COMMIT(); CP_WAIT(1); }
        else              { CP_WAIT(0); }
        __syncthreads();

        const uint32_t stg = (uint32_t)(kt & 1) * (STAGE_HALVES * 2);

        float sc[4][4] = {};
#pragma unroll
        for (int kc = 0; kc < 4; kc++) {
#pragma unroll
            for (int nf = 0; nf < 4; nf++) {
                const uint32_t ka = kO + stg + (uint32_t)(nf * (8 * APAD * 2) + kc * 32);
                uint32_t bh[2], bl[2];
                LDSM_X2(bh[0], bh[1], ka);
                LDSM_X2(bl[0], bl[1], ka + KV_ARR_H * 2);
                mma_f16(sc[nf], qfh[kc], bh);
                mma_f16(sc[nf], qfh[kc], bl);
                mma_f16(sc[nf], qfl[kc], bh);
            }
        }

        if (kt >= 2 * qt) {
            const int diag = (kt - 2 * qt) * 32;
            const int r0 = wid * 16 + g - diag;
            const int r1 = r0 + 8;
#pragma unroll
            for (int nf = 0; nf < 4; nf++) {
                const int c0 = nf * 8 + 2 * t;
                if (c0     > r0) sc[nf][0] = -1e30f;
                if (c0 + 1 > r0) sc[nf][1] = -1e30f;
                if (c0     > r1) sc[nf][2] = -1e30f;
                if (c0 + 1 > r1) sc[nf][3] = -1e30f;
            }
        }

        {
            float rm0 = -1e30f, rm1 = -1e30f;
#pragma unroll
            for (int nf = 0; nf < 4; nf++) {
                rm0 = fmaxf(rm0, fmaxf(sc[nf][0], sc[nf][1]));
                rm1 = fmaxf(rm1, fmaxf(sc[nf][2], sc[nf][3]));
            }
            rm0 = fmaxf(rm0, __shfl_xor_sync(0xffffffffu, rm0, 1));
            rm0 = fmaxf(rm0, __shfl_xor_sync(0xffffffffu, rm0, 2));
            rm1 = fmaxf(rm1, __shfl_xor_sync(0xffffffffu, rm1, 1));
            rm1 = fmaxf(rm1, __shfl_xor_sync(0xffffffffu, rm1, 2));

            const float mn0 = fmaxf(m0, rm0), mn1 = fmaxf(m1, rm1);
            const float cr0 = __expf(m0 - mn0), cr1 = __expf(m1 - mn1);
            float rs0 = 0.f, rs1 = 0.f;
#pragma unroll
            for (int nf = 0; nf < 4; nf++) {
                sc[nf][0] = __expf(sc[nf][0] - mn0);
                sc[nf][1] = __expf(sc[nf][1] - mn0);
                sc[nf][2] = __expf(sc[nf][2] - mn1);
                sc[nf][3] = __expf(sc[nf][3] - mn1);
                rs0 += sc[nf][0] + sc[nf][1];
                rs1 += sc[nf][2] + sc[nf][3];
            }
            rs0 += __shfl_xor_sync(0xffffffffu, rs0, 1);
            rs0 += __shfl_xor_sync(0xffffffffu, rs0, 2);
            rs1 += __shfl_xor_sync(0xffffffffu, rs1, 1);
            rs1 += __shfl_xor_sync(0xffffffffu, rs1, 2);

            l0 = l0 * cr0 + rs0; l1 = l1 * cr1 + rs1;
            m0 = mn0; m1 = mn1;
#pragma unroll
            for (int nf = 0; nf < 8; nf++) {
                oc[nf][0] *= cr0; oc[nf][1] *= cr0;
                oc[nf][2] *= cr1; oc[nf][3] *= cr1;
            }
        }

        // ---- O += P Vh  (P hi-only; V pre-quantized fp16) ----
#pragma unroll
        for (int kc = 0; kc < 2; kc++) {
            uint32_t pah[4];
            {
                const float* e0 = sc[2 * kc];
                const float* e1 = sc[2 * kc + 1];
                pah[0] = packh2(e0[0], e0[1]);
                pah[1] = packh2(e0[2], e0[3]);
                pah[2] = packh2(e1[0], e1[1]);
                pah[3] = packh2(e1[2], e1[3]);
            }
#pragma unroll
            for (int nf = 0; nf < 8; nf++) {
                uint32_t vh[2];
                LDSM_X2T(vh[0], vh[1],
                         vO + stg + (uint32_t)(kc * (16 * APAD * 2) + nf * 16));
                mma_f16(oc[nf], pah, vh);
            }
        }
        __syncthreads();
    }

    // epilogue: normalize, fp16 hi-only scatter to [N, L, H*D]
    const float inv0 = 1.0f / l0, inv1 = 1.0f / l1;
    const int n = nh >> 4;
    const int h = nh & 15;
    const int r0 = qb + wid * 16 + g;
    const int r1 = r0 + 8;
#pragma unroll
    for (int nf = 0; nf < 8; nf++) {
        const int col = h * HDIM + nf * 8 + 2 * t;
        *(uint32_t*)(Oh + (size_t)(n * LSEQ + r0) * EMBD + col) =
            packh2(oc[nf][0] * inv0, oc[nf][1] * inv0);
        *(uint32_t*)(Oh + (size_t)(n * LSEQ + r1) * EMBD + col) =
            packh2(oc[nf][2] * inv1, oc[nf][3] * inv1);
    }
}

// ------------------------- launch -------------------------
extern "C" void kernel_launch(void* const* d_in, const int* in_sizes, int n_in,
                              void* d_out, int out_size)
{
    (void)in_sizes; (void)n_in; (void)out_size;
    const float* x  = (const float*)d_in[0];
    const float* Wq = (const float*)d_in[2];
    const float* Wk = (const float*)d_in[3];
    const float* Wv = (const float*)d_in[4];
    const float* gq = (const float*)d_in[5];
    const float* bq = (const float*)d_in[6];
    const float* gk = (const float*)d_in[7];
    const float* bk = (const float*)d_in[8];
    const float* Wo = (const float*)d_in[9];
    const float* bo = (const float*)d_in[10];
    float* out = (float*)d_out;

    __half *xh, *xl, *wqh, *wql, *wkh, *wkl, *wvh, *wvl, *woh, *wol;
    __half *qh, *ql, *kh, *kl, *vh, *oh;
    cudaGetSymbolAddress((void**)&xh, g_xh);   cudaGetSymbolAddress((void**)&xl, g_xl);
    cudaGetSymbolAddress((void**)&wqh, g_wqh); cudaGetSymbolAddress((void**)&wql, g_wql);
    cudaGetSymbolAddress((void**)&wkh, g_wkh); cudaGetSymbolAddress((void**)&wkl, g_wkl);
    cudaGetSymbolAddress((void**)&wvh, g_wvh); cudaGetSymbolAddress((void**)&wvl, g_wvl);
    cudaGetSymbolAddress((void**)&woh, g_woh); cudaGetSymbolAddress((void**)&wol, g_wol);
    cudaGetSymbolAddress((void**)&qh, g_qh);   cudaGetSymbolAddress((void**)&ql, g_ql);
    cudaGetSymbolAddress((void**)&kh, g_kh);   cudaGetSymbolAddress((void**)&kl, g_kl);
    cudaGetSymbolAddress((void**)&vh, g_vh);
    cudaGetSymbolAddress((void**)&oh, g_oh);

    cudaFuncSetAttribute(h16_gemm<0,3>, cudaFuncAttributeMaxDynamicSharedMemorySize, GEMM_SMEM);
    cudaFuncSetAttribute(h16_gemm<1,2>, cudaFuncAttributeMaxDynamicSharedMemorySize, GEMM_SMEM);
    cudaFuncSetAttribute(h16_gemm<2,2>, cudaFuncAttributeMaxDynamicSharedMemorySize, GEMM_SMEM);
    cudaFuncSetAttribute(attn_mma, cudaFuncAttributeMaxDynamicSharedMemorySize, ATTN_SMEM);

    const int xn4 = X_ELEMS / 4, wn4 = W_ELEMS / 4;
    // 4 split launches before the first GEMM so ncu (-s 5) lands on h16_gemm<0,3>
    split_f32<<<(xn4 + 255) / 256, 256>>>((const float4*)x,  (uint2*)xh,  (uint2*)xl,  xn4);
    split_f32<<<(wn4 + 255) / 256, 256>>>((const float4*)Wq, (uint2*)wqh, (uint2*)wql, wn4);
    split_f32<<<(wn4 + 255) / 256, 256>>>((const float4*)Wk, (uint2*)wkh, (uint2*)wkl, wn4);
    split_f32<<<(wn4 + 255) / 256, 256>>>((const float4*)Wv, (uint2*)wvh, (uint2*)wvl, wn4);

    dim3 gg(MROWS / 128, EMBD / 128);
    h16_gemm<0,3><<<gg, 256, GEMM_SMEM>>>(xh, xl, wqh, wql, gq, bq, nullptr, qh, ql, nullptr);
    h16_gemm<0,3><<<gg, 256, GEMM_SMEM>>>(xh, xl, wkh, wkl, gk, bk, nullptr, kh, kl, nullptr);
    h16_gemm<1,2><<<gg, 256, GEMM_SMEM>>>(xh, nullptr, wvh, wvl, nullptr, nullptr, nullptr,
                                          vh, nullptr, nullptr);

    split_f32<<<(wn4 + 255) / 256, 256>>>((const float4*)Wo, (uint2*)woh, (uint2*)wol, wn4);

    attn_mma<<<dim3(LSEQ / 64, NBATCH * NHEAD), 128, ATTN_SMEM>>>(qh, ql, kh, kl, vh, oh);

    h16_gemm<2,2><<<gg, 256, GEMM_SMEM>>>(oh, nullptr, woh, wol, nullptr, nullptr, bo,
                                          nullptr, nullptr, out);
}

// round 11
// speedup vs baseline: 2.6190x; 1.1144x over previous
#include <cuda_runtime.h>
#include <cuda_fp16.h>
#include <cstdint>

// Problem constants
#define NBATCH 2
#define LSEQ   2048
#define EMBD   1024
#define NHEAD  16
#define HDIM   64
#define MROWS  (NBATCH * LSEQ)   // 4096
#define QKV_ELEMS (NBATCH * NHEAD * LSEQ * HDIM)
#define W_ELEMS (EMBD * EMBD)
#define X_ELEMS (MROWS * EMBD)

// Scratch (device globals: no allocation allowed)
__device__ __half g_xh[X_ELEMS], g_xl[X_ELEMS];
__device__ __half g_wqh[W_ELEMS], g_wql[W_ELEMS];
__device__ __half g_wkh[W_ELEMS], g_wkl[W_ELEMS];
__device__ __half g_wvh[W_ELEMS];
__device__ __half g_woh[W_ELEMS];
__device__ __half g_qh[QKV_ELEMS], g_ql[QKV_ELEMS];
__device__ __half g_kh[QKV_ELEMS], g_kl[QKV_ELEMS];
__device__ __half g_vh[QKV_ELEMS];
__device__ __half g_oh[X_ELEMS];

__device__ __forceinline__ uint32_t smem_u32(const void* p) {
    uint32_t a;
    asm("{ .reg .u64 t; cvta.to.shared.u64 t, %1; cvt.u32.u64 %0, t; }"
        : "=r"(a) : "l"(p));
    return a;
}
__device__ __forceinline__ uint32_t packh2(float a, float b) {
    __half2 h = __floats2half2_rn(a, b);
    return *reinterpret_cast<uint32_t*>(&h);
}
__device__ __forceinline__ void cp_async16(uint32_t dst, const void* src) {
    asm volatile("cp.async.cg.shared.global [%0], [%1], 16;" :: "r"(dst), "l"(src));
}
#define CP_COMMIT() asm volatile("cp.async.commit_group;" ::: "memory")
#define CP_WAIT(N)  asm volatile("cp.async.wait_group %0;" :: "n"(N) : "memory")

#define LDSM_X4(r0, r1, r2, r3, addr) \
    asm volatile("ldmatrix.sync.aligned.m8n8.x4.shared.b16 {%0,%1,%2,%3}, [%4];" \
        : "=r"(r0), "=r"(r1), "=r"(r2), "=r"(r3) : "r"(addr))
#define LDSM_X2(r0, r1, addr) \
    asm volatile("ldmatrix.sync.aligned.m8n8.x2.shared.b16 {%0,%1}, [%2];" \
        : "=r"(r0), "=r"(r1) : "r"(addr))
#define LDSM_X2T(r0, r1, addr) \
    asm volatile("ldmatrix.sync.aligned.m8n8.x2.trans.shared.b16 {%0,%1}, [%2];" \
        : "=r"(r0), "=r"(r1) : "r"(addr))

__device__ __forceinline__ void mma_f16(float* c, const uint32_t* a, const uint32_t* b) {
    asm volatile(
        "mma.sync.aligned.m16n8k16.row.col.f32.f16.f16.f32 "
        "{%0,%1,%2,%3}, {%4,%5,%6,%7}, {%8,%9}, {%0,%1,%2,%3};"
        : "+f"(c[0]), "+f"(c[1]), "+f"(c[2]), "+f"(c[3])
        : "r"(a[0]), "r"(a[1]), "r"(a[2]), "r"(a[3]), "r"(b[0]), "r"(b[1]));
}

// ---------------- split pass: fp32 -> fp16 hi/lo ----------------
__global__ void __launch_bounds__(256) split_f32(
    const float4* __restrict__ src, uint2* __restrict__ hi,
    uint2* __restrict__ lo, int n4)
{
    const int i = blockIdx.x * blockDim.x + threadIdx.x;
    if (i >= n4) return;
    float4 v = src[i];
    __half h0 = __float2half_rn(v.x), h1 = __float2half_rn(v.y),
           h2 = __float2half_rn(v.z), h3 = __float2half_rn(v.w);
    __half2 p01 = __halves2half2(h0, h1), p23 = __halves2half2(h2, h3);
    hi[i] = make_uint2(*(uint32_t*)&p01, *(uint32_t*)&p23);
    lo[i] = make_uint2(packh2(v.x - __half2float(h0), v.y - __half2float(h1)),
                       packh2(v.z - __half2float(h2), v.w - __half2float(h3)));
}

// hi-only conversion (for 1-product operands)
__global__ void __launch_bounds__(256) conv_hi(
    const float4* __restrict__ src, uint2* __restrict__ hi, int n4)
{
    const int i = blockIdx.x * blockDim.x + threadIdx.x;
    if (i >= n4) return;
    float4 v = src[i];
    hi[i] = make_uint2(packh2(v.x, v.y), packh2(v.z, v.w));
}

// ---------------- GEMM: pre-split fp16, 1/2/3-product ----------------
#define GSTR 40                          // halves per smem row (ldmatrix conflict-free)
#define GARR_B (128 * GSTR * 2)          // 10240 B
#define GEMM_SMEM 81920                  // covers 2 stages (max 4 arrays) + C tile

// C = A @ B^T.
// NPROD 3: Ah*Bh + Ah*Bl + Al*Bh (arrays Ah|Al|Bh|Bl)
// NPROD 2: Ah*Bh + Ah*Bl         (arrays Ah|Bh|Bl)
// NPROD 1: Ah*Bh                 (arrays Ah|Bh)
// MODE 0: per-head LayerNorm, half hi+lo head-major output [N,H,L,D]
// MODE 1: half hi-only head-major output
// MODE 2: fp32 row-major output + bias
template <int MODE, int NPROD>
__global__ void __launch_bounds__(256, 2) h16_gemm(
    const __half* __restrict__ Ah_g, const __half* __restrict__ Al_g,
    const __half* __restrict__ Bh_g, const __half* __restrict__ Bl_g,
    const float* __restrict__ gamma, const float* __restrict__ beta,
    const float* __restrict__ bias,
    __half* __restrict__ Ch, __half* __restrict__ Cl, float* __restrict__ C)
{
    constexpr uint32_t BOFF = (NPROD == 3 ? 2u : 1u) * GARR_B;   // Bh array offset
    constexpr uint32_t GSTG = (uint32_t)(NPROD + 1) * GARR_B;    // bytes per stage

    extern __shared__ char sm[];
    const uint32_t sbase = smem_u32(sm);
    const int tid  = threadIdx.x;
    const int lane = tid & 31;
    const int wid  = tid >> 5;
    const int warp_m = wid >> 2;   // 0..1
    const int warp_n = wid & 3;    // 0..3
    const int rb = blockIdx.x * 128;
    const int cb = blockIdx.y * 128;

    // staging coords
    const int srow = tid >> 1;
    const int skoff = (tid & 1) * 16;
    const __half* Ap  = Ah_g + (size_t)(rb + srow) * EMBD + skoff;
    const __half* Alp = (NPROD == 3) ? Al_g + (size_t)(rb + srow) * EMBD + skoff : nullptr;
    const __half* Bp  = Bh_g + (size_t)(cb + srow) * EMBD + skoff;
    const __half* Blp = (NPROD >= 2) ? Bl_g + (size_t)(cb + srow) * EMBD + skoff : nullptr;
    const uint32_t sdst = ((uint32_t)srow * GSTR + (uint32_t)skoff) * 2;

    auto stage = [&](int s, int kc) {
        const uint32_t d = sbase + (uint32_t)s * GSTG + sdst;
        const int go = kc * 32;
        cp_async16(d,                 Ap + go);
        cp_async16(d + 16,            Ap + go + 8);
        if (NPROD == 3) {
            cp_async16(d + GARR_B,      Alp + go);
            cp_async16(d + GARR_B + 16, Alp + go + 8);
        }
        cp_async16(d + BOFF,      Bp + go);
        cp_async16(d + BOFF + 16, Bp + go + 8);
        if (NPROD >= 2) {
            cp_async16(d + BOFF + GARR_B,      Blp + go);
            cp_async16(d + BOFF + GARR_B + 16, Blp + go + 8);
        }
    };

    float acc[4][4][4] = {};

    // fragment lane addressing (uint32, computed once)
    const int afr = lane & 15;
    const int afc = (lane >> 4) << 3;
    const int bfr = lane & 7;
    const int bfc = ((lane & 15) >> 3) << 3;
    const uint32_t aM = sbase + ((uint32_t)(warp_m * 64 + afr) * GSTR + (uint32_t)afc) * 2;
    const uint32_t bN = sbase + BOFF
                      + ((uint32_t)(warp_n * 32 + bfr) * GSTR + (uint32_t)bfc) * 2;

    auto compute = [&](int s) {
        const uint32_t so = (uint32_t)s * GSTG;
#pragma unroll
        for (int ks = 0; ks < 2; ks++) {
            uint32_t bh[4][2], bl[4][2];
#pragma unroll
            for (int nf = 0; nf < 4; nf++) {
                const uint32_t ba = bN + so + (uint32_t)(nf * (8 * GSTR * 2) + ks * 32);
                LDSM_X2(bh[nf][0], bh[nf][1], ba);
                if (NPROD >= 2) { LDSM_X2(bl[nf][0], bl[nf][1], ba + GARR_B); }
            }
#pragma unroll
            for (int mf = 0; mf < 4; mf++) {
                uint32_t ah[4], al[4];
                const uint32_t aa = aM + so + (uint32_t)(mf * (16 * GSTR * 2) + ks * 32);
                LDSM_X4(ah[0], ah[1], ah[2], ah[3], aa);
                if (NPROD == 3) { LDSM_X4(al[0], al[1], al[2], al[3], aa + GARR_B); }
#pragma unroll
                for (int nf = 0; nf < 4; nf++) {
                    mma_f16(acc[mf][nf], ah, bh[nf]);
                    if (NPROD >= 2) mma_f16(acc[mf][nf], ah, bl[nf]);
                    if (NPROD == 3) mma_f16(acc[mf][nf], al, bh[nf]);
                }
            }
        }
    };

    stage(0, 0);
    CP_COMMIT();
    const int NC = EMBD / 32;
    for (int kc = 0; kc < NC; kc++) {
        if (kc + 1 < NC) { stage((kc + 1) & 1, kc + 1); CP_COMMIT(); CP_WAIT(1); }
        else             { CP_WAIT(0); }
        __syncthreads();
        compute(kc & 1);
        __syncthreads();
    }

    // C staging + streamed epilogue
    const int g = lane >> 2;
    const int q = lane & 3;
    float* Ct = (float*)sm;   // [128][132]
#pragma unroll
    for (int mf = 0; mf < 4; mf++)
#pragma unroll
        for (int nf = 0; nf < 4; nf++) {
            const int r = warp_m * 64 + mf * 16 + g;
            const int c = warp_n * 32 + nf * 8 + q * 2;
            *(float2*)&Ct[r * 132 + c]       = make_float2(acc[mf][nf][0], acc[mf][nf][1]);
            *(float2*)&Ct[(r + 8) * 132 + c] = make_float2(acc[mf][nf][2], acc[mf][nf][3]);
        }
    __syncthreads();

    {
        const int row = tid >> 1;
        const int seg = tid & 1;
        const float* crow = &Ct[row * 132 + seg * 64];

        if (MODE == 2) {
            const int c0 = cb + seg * 64;
            float* dst = C + (size_t)(rb + row) * EMBD + c0;
#pragma unroll
            for (int j = 0; j < 16; j++) {
                float4 v = *(const float4*)&crow[4 * j];
                float4 b4 = *(const float4*)&bias[c0 + 4 * j];
                v.x += b4.x; v.y += b4.y; v.z += b4.z; v.w += b4.w;
                *(float4*)(dst + 4 * j) = v;
            }
        } else {
            float mean = 0.f, rstd = 0.f;
            if (MODE == 0) {
                float s = 0.f, s2 = 0.f;
#pragma unroll
                for (int j = 0; j < 16; j++) {
                    float4 v = *(const float4*)&crow[4 * j];
                    s  += v.x + v.y + v.z + v.w;
                    s2 += v.x * v.x + v.y * v.y + v.z * v.z + v.w * v.w;
                }
                mean = s * (1.0f / 64.0f);
                rstd = rsqrtf(s2 * (1.0f / 64.0f) - mean * mean + 1e-5f);
            }
            const int grow = rb + row;
            const int n = grow >> 11;
            const int l = grow & (LSEQ - 1);
            const int hd = (cb >> 6) + seg;
            const size_t off = ((size_t)((n * NHEAD + hd) * LSEQ + l)) * HDIM;
#pragma unroll
            for (int j = 0; j < 8; j++) {
                float v[8];
                *(float4*)&v[0] = *(const float4*)&crow[8 * j];
                *(float4*)&v[4] = *(const float4*)&crow[8 * j + 4];
                if (MODE == 0) {
#pragma unroll
                    for (int k2 = 0; k2 < 8; k2++)
                        v[k2] = (v[k2] - mean) * rstd * __ldg(gamma + 8 * j + k2)
                                + __ldg(beta + 8 * j + k2);
                }
                __half hh[8];
#pragma unroll
                for (int k2 = 0; k2 < 8; k2++) hh[k2] = __float2half_rn(v[k2]);
                *(uint4*)(Ch + off + 8 * j) = *(uint4*)hh;
                if (MODE == 0) {
                    __half ll[8];
#pragma unroll
                    for (int k2 = 0; k2 < 8; k2++)
                        ll[k2] = __float2half_rn(v[k2] - __half2float(hh[k2]));
                    *(uint4*)(Cl + off + 8 * j) = *(uint4*)ll;
                }
            }
        }
    }
}

// ---------------- Attention (R10-proven: 3-prod QK, 1-prod PV) ----------------
#define APAD 72
#define KV_ARR_H (32 * APAD)
#define STAGE_HALVES (3 * KV_ARR_H)
#define ATTN_SMEM (2 * STAGE_HALVES * 2)

__global__ void __launch_bounds__(128, 4) attn_mma(
    const __half* __restrict__ Qh, const __half* __restrict__ Ql,
    const __half* __restrict__ Kh, const __half* __restrict__ Kl,
    const __half* __restrict__ Vh, __half* __restrict__ Oh)
{
    extern __shared__ __half smh[];
    const uint32_t sbase = smem_u32(smh);

    const int tid  = threadIdx.x;
    const int lane = tid & 31;
    const int wid  = tid >> 5;
    const int g    = lane >> 2;
    const int t    = lane & 3;
    const int nh   = blockIdx.y;
    const int qt   = gridDim.x - 1 - blockIdx.x;
    const int qb   = qt * 64;
    const size_t base = (size_t)nh * LSEQ * HDIM;

    const int krow = tid >> 2;
    const int kcol = (tid & 3) * 16;
    const uint32_t kv_sm_off = ((uint32_t)krow * APAD + (uint32_t)kcol) * 2;

    auto stage_kv = [&](int b, int kt) {
        const size_t goff = base + (size_t)(kt * 32 + krow) * HDIM + kcol;
        const uint32_t s0 = sbase + (uint32_t)b * (STAGE_HALVES * 2) + kv_sm_off;
        cp_async16(s0,                        Kh + goff);
        cp_async16(s0 + 16,                   Kh + goff + 8);
        cp_async16(s0 + KV_ARR_H * 2,         Kl + goff);
        cp_async16(s0 + KV_ARR_H * 2 + 16,    Kl + goff + 8);
        cp_async16(s0 + KV_ARR_H * 4,         Vh + goff);
        cp_async16(s0 + KV_ARR_H * 4 + 16,    Vh + goff + 8);
    };

    {
        const int qr = tid >> 1;
        const int qc = (tid & 1) * 32;
        const size_t goff = base + (size_t)(qb + qr) * HDIM + qc;
        const uint32_t s0 = sbase + ((uint32_t)qr * APAD + (uint32_t)qc) * 2;
#pragma unroll
        for (int i = 0; i < 4; i++) {
            cp_async16(s0 + i * 16,                 Qh + goff + i * 8);
            cp_async16(s0 + 64 * APAD * 2 + i * 16, Ql + goff + i * 8);
        }
        CP_COMMIT();
        CP_WAIT(0);
    }
    __syncthreads();

    uint32_t qfh[4][4], qfl[4][4];
    {
        const uint32_t qa = sbase
            + ((uint32_t)(wid * 16 + (lane & 15)) * APAD + (uint32_t)((lane >> 4) << 3)) * 2;
#pragma unroll
        for (int kc = 0; kc < 4; kc++) {
            LDSM_X4(qfh[kc][0], qfh[kc][1], qfh[kc][2], qfh[kc][3], qa + kc * 32);
            LDSM_X4(qfl[kc][0], qfl[kc][1], qfl[kc][2], qfl[kc][3],
                    qa + kc * 32 + 64 * APAD * 2);
        }
    }
    __syncthreads();

    stage_kv(0, 0);
    CP_COMMIT();

    float oc[8][4] = {};
    float m0 = -1e30f, m1 = -1e30f, l0 = 0.f, l1 = 0.f;

    const uint32_t kO = sbase
        + ((uint32_t)(lane & 7) * APAD + (uint32_t)(((lane & 15) >> 3) << 3)) * 2;
    const uint32_t vO = sbase + 4 * KV_ARR_H + (uint32_t)(lane & 15) * (APAD * 2);
    const int nkt = 2 * (qt + 1);

    for (int kt = 0; kt < nkt; kt++) {
        if (kt + 1 < nkt) { stage_kv((kt + 1) & 1, kt + 1); CP_COMMIT(); CP_WAIT(1); }
        else              { CP_WAIT(0); }
        __syncthreads();

        const uint32_t stg = (uint32_t)(kt & 1) * (STAGE_HALVES * 2);

        float sc[4][4] = {};
#pragma unroll
        for (int kc = 0; kc < 4; kc++) {
#pragma unroll
            for (int nf = 0; nf < 4; nf++) {
                const uint32_t ka = kO + stg + (uint32_t)(nf * (8 * APAD * 2) + kc * 32);
                uint32_t bh[2], bl[2];
                LDSM_X2(bh[0], bh[1], ka);
                LDSM_X2(bl[0], bl[1], ka + KV_ARR_H * 2);
                mma_f16(sc[nf], qfh[kc], bh);
                mma_f16(sc[nf], qfh[kc], bl);
                mma_f16(sc[nf], qfl[kc], bh);
            }
        }

        if (kt >= 2 * qt) {
            const int diag = (kt - 2 * qt) * 32;
            const int r0 = wid * 16 + g - diag;
            const int r1 = r0 + 8;
#pragma unroll
            for (int nf = 0; nf < 4; nf++) {
                const int c0 = nf * 8 + 2 * t;
                if (c0     > r0) sc[nf][0] = -1e30f;
                if (c0 + 1 > r0) sc[nf][1] = -1e30f;
                if (c0     > r1) sc[nf][2] = -1e30f;
                if (c0 + 1 > r1) sc[nf][3] = -1e30f;
            }
        }

        {
            float rm0 = -1e30f, rm1 = -1e30f;
#pragma unroll
            for (int nf = 0; nf < 4; nf++) {
                rm0 = fmaxf(rm0, fmaxf(sc[nf][0], sc[nf][1]));
                rm1 = fmaxf(rm1, fmaxf(sc[nf][2], sc[nf][3]));
            }
            rm0 = fmaxf(rm0, __shfl_xor_sync(0xffffffffu, rm0, 1));
            rm0 = fmaxf(rm0, __shfl_xor_sync(0xffffffffu, rm0, 2));
            rm1 = fmaxf(rm1, __shfl_xor_sync(0xffffffffu, rm1, 1));
            rm1 = fmaxf(rm1, __shfl_xor_sync(0xffffffffu, rm1, 2));

            const float mn0 = fmaxf(m0, rm0), mn1 = fmaxf(m1, rm1);
            const float cr0 = __expf(m0 - mn0), cr1 = __expf(m1 - mn1);
            float rs0 = 0.f, rs1 = 0.f;
#pragma unroll
            for (int nf = 0; nf < 4; nf++) {
                sc[nf][0] = __expf(sc[nf][0] - mn0);
                sc[nf][1] = __expf(sc[nf][1] - mn0);
                sc[nf][2] = __expf(sc[nf][2] - mn1);
                sc[nf][3] = __expf(sc[nf][3] - mn1);
                rs0 += sc[nf][0] + sc[nf][1];
                rs1 += sc[nf][2] + sc[nf][3];
            }
            rs0 += __shfl_xor_sync(0xffffffffu, rs0, 1);
            rs0 += __shfl_xor_sync(0xffffffffu, rs0, 2);
            rs1 += __shfl_xor_sync(0xffffffffu, rs1, 1);
            rs1 += __shfl_xor_sync(0xffffffffu, rs1, 2);

            l0 = l0 * cr0 + rs0; l1 = l1 * cr1 + rs1;
            m0 = mn0; m1 = mn1;
#pragma unroll
            for (int nf = 0; nf < 8; nf++) {
                oc[nf][0] *= cr0; oc[nf][1] *= cr0;
                oc[nf][2] *= cr1; oc[nf][3] *= cr1;
            }
        }

        // ---- O += P Vh ----
#pragma unroll
        for (int kc = 0; kc < 2; kc++) {
            uint32_t pah[4];
            {
                const float* e0 = sc[2 * kc];
                const float* e1 = sc[2 * kc + 1];
                pah[0] = packh2(e0[0], e0[1]);
                pah[1] = packh2(e0[2], e0[3]);
                pah[2] = packh2(e1[0], e1[1]);
                pah[3] = packh2(e1[2], e1[3]);
            }
#pragma unroll
            for (int nf = 0; nf < 8; nf++) {
                uint32_t vh[2];
                LDSM_X2T(vh[0], vh[1],
                         vO + stg + (uint32_t)(kc * (16 * APAD * 2) + nf * 16));
                mma_f16(oc[nf], pah, vh);
            }
        }
        __syncthreads();
    }

    // epilogue: normalize, fp16 hi-only scatter to [N, L, H*D]
    const float inv0 = 1.0f / l0, inv1 = 1.0f / l1;
    const int n = nh >> 4;
    const int h = nh & 15;
    const int r0 = qb + wid * 16 + g;
    const int r1 = r0 + 8;
#pragma unroll
    for (int nf = 0; nf < 8; nf++) {
        const int col = h * HDIM + nf * 8 + 2 * t;
        *(uint32_t*)(Oh + (size_t)(n * LSEQ + r0) * EMBD + col) =
            packh2(oc[nf][0] * inv0, oc[nf][1] * inv0);
        *(uint32_t*)(Oh + (size_t)(n * LSEQ + r1) * EMBD + col) =
            packh2(oc[nf][2] * inv1, oc[nf][3] * inv1);
    }
}

// ------------------------- launch -------------------------
extern "C" void kernel_launch(void* const* d_in, const int* in_sizes, int n_in,
                              void* d_out, int out_size)
{
    (void)in_sizes; (void)n_in; (void)out_size;
    const float* x  = (const float*)d_in[0];
    const float* Wq = (const float*)d_in[2];
    const float* Wk = (const float*)d_in[3];
    const float* Wv = (const float*)d_in[4];
    const float* gq = (const float*)d_in[5];
    const float* bq = (const float*)d_in[6];
    const float* gk = (const float*)d_in[7];
    const float* bk = (const float*)d_in[8];
    const float* Wo = (const float*)d_in[9];
    const float* bo = (const float*)d_in[10];
    float* out = (float*)d_out;

    __half *xh, *xl, *wqh, *wql, *wkh, *wkl, *wvh, *woh;
    __half *qh, *ql, *kh, *kl, *vh, *oh;
    cudaGetSymbolAddress((void**)&xh, g_xh);   cudaGetSymbolAddress((void**)&xl, g_xl);
    cudaGetSymbolAddress((void**)&wqh, g_wqh); cudaGetSymbolAddress((void**)&wql, g_wql);
    cudaGetSymbolAddress((void**)&wkh, g_wkh); cudaGetSymbolAddress((void**)&wkl, g_wkl);
    cudaGetSymbolAddress((void**)&wvh, g_wvh);
    cudaGetSymbolAddress((void**)&woh, g_woh);
    cudaGetSymbolAddress((void**)&qh, g_qh);   cudaGetSymbolAddress((void**)&ql, g_ql);
    cudaGetSymbolAddress((void**)&kh, g_kh);   cudaGetSymbolAddress((void**)&kl, g_kl);
    cudaGetSymbolAddress((void**)&vh, g_vh);
    cudaGetSymbolAddress((void**)&oh, g_oh);

    cudaFuncSetAttribute(h16_gemm<0,3>, cudaFuncAttributeMaxDynamicSharedMemorySize, GEMM_SMEM);
    cudaFuncSetAttribute(h16_gemm<1,1>, cudaFuncAttributeMaxDynamicSharedMemorySize, GEMM_SMEM);
    cudaFuncSetAttribute(h16_gemm<2,1>, cudaFuncAttributeMaxDynamicSharedMemorySize, GEMM_SMEM);
    cudaFuncSetAttribute(attn_mma, cudaFuncAttributeMaxDynamicSharedMemorySize, ATTN_SMEM);

    const int xn4 = X_ELEMS / 4, wn4 = W_ELEMS / 4;
    split_f32<<<(xn4 + 255) / 256, 256>>>((const float4*)x,  (uint2*)xh,  (uint2*)xl,  xn4);
    split_f32<<<(wn4 + 255) / 256, 256>>>((const float4*)Wq, (uint2*)wqh, (uint2*)wql, wn4);
    split_f32<<<(wn4 + 255) / 256, 256>>>((const float4*)Wk, (uint2*)wkh, (uint2*)wkl, wn4);
    conv_hi <<<(wn4 + 255) / 256, 256>>>((const float4*)Wv, (uint2*)wvh, wn4);
    conv_hi <<<(wn4 + 255) / 256, 256>>>((const float4*)Wo, (uint2*)woh, wn4);

    dim3 gg(MROWS / 128, EMBD / 128);
    h16_gemm<0,3><<<gg, 256, GEMM_SMEM>>>(xh, xl, wqh, wql, gq, bq, nullptr, qh, ql, nullptr);
    h16_gemm<0,3><<<gg, 256, GEMM_SMEM>>>(xh, xl, wkh, wkl, gk, bk, nullptr, kh, kl, nullptr);
    h16_gemm<1,1><<<gg, 256, GEMM_SMEM>>>(xh, nullptr, wvh, nullptr, nullptr, nullptr, nullptr,
                                          vh, nullptr, nullptr);

    attn_mma<<<dim3(LSEQ / 64, NBATCH * NHEAD), 128, ATTN_SMEM>>>(qh, ql, kh, kl, vh, oh);

    h16_gemm<2,1><<<gg, 256, GEMM_SMEM>>>(oh, nullptr, woh, nullptr, nullptr, nullptr, bo,
                                          nullptr, nullptr, out);
}

// round 12
// speedup vs baseline: 2.6664x; 1.0181x over previous
#include <cuda_runtime.h>
#include <cuda_fp16.h>
#include <cstdint>

// Problem constants
#define NBATCH 2
#define LSEQ   2048
#define EMBD   1024
#define NHEAD  16
#define HDIM   64
#define MROWS  (NBATCH * LSEQ)   // 4096
#define QKV_ELEMS (NBATCH * NHEAD * LSEQ * HDIM)
#define W_ELEMS (EMBD * EMBD)
#define X_ELEMS (MROWS * EMBD)

// Scratch (device globals: no allocation allowed)
__device__ __half g_xh[X_ELEMS], g_xl[X_ELEMS];
__device__ __half g_wqh[W_ELEMS], g_wql[W_ELEMS];
__device__ __half g_wkh[W_ELEMS], g_wkl[W_ELEMS];
__device__ __half g_wvh[W_ELEMS];
__device__ __half g_woh[W_ELEMS];
__device__ __half g_qh[QKV_ELEMS], g_ql[QKV_ELEMS];
__device__ __half g_kh[QKV_ELEMS], g_kl[QKV_ELEMS];
__device__ __half g_vh[QKV_ELEMS];
__device__ __half g_oh[X_ELEMS];

__device__ __forceinline__ uint32_t smem_u32(const void* p) {
    uint32_t a;
    asm("{ .reg .u64 t; cvta.to.shared.u64 t, %1; cvt.u32.u64 %0, t; }"
        : "=r"(a) : "l"(p));
    return a;
}
__device__ __forceinline__ uint32_t packh2(float a, float b) {
    __half2 h = __floats2half2_rn(a, b);
    return *reinterpret_cast<uint32_t*>(&h);
}
__device__ __forceinline__ void cp_async16(uint32_t dst, const void* src) {
    asm volatile("cp.async.cg.shared.global [%0], [%1], 16;" :: "r"(dst), "l"(src));
}
#define CP_COMMIT() asm volatile("cp.async.commit_group;" ::: "memory")
#define CP_WAIT(N)  asm volatile("cp.async.wait_group %0;" :: "n"(N) : "memory")

#define LDSM_X4(r0, r1, r2, r3, addr) \
    asm volatile("ldmatrix.sync.aligned.m8n8.x4.shared.b16 {%0,%1,%2,%3}, [%4];" \
        : "=r"(r0), "=r"(r1), "=r"(r2), "=r"(r3) : "r"(addr))
#define LDSM_X2(r0, r1, addr) \
    asm volatile("ldmatrix.sync.aligned.m8n8.x2.shared.b16 {%0,%1}, [%2];" \
        : "=r"(r0), "=r"(r1) : "r"(addr))
#define LDSM_X2T(r0, r1, addr) \
    asm volatile("ldmatrix.sync.aligned.m8n8.x2.trans.shared.b16 {%0,%1}, [%2];" \
        : "=r"(r0), "=r"(r1) : "r"(addr))

__device__ __forceinline__ void mma_f16(float* c, const uint32_t* a, const uint32_t* b) {
    asm volatile(
        "mma.sync.aligned.m16n8k16.row.col.f32.f16.f16.f32 "
        "{%0,%1,%2,%3}, {%4,%5,%6,%7}, {%8,%9}, {%0,%1,%2,%3};"
        : "+f"(c[0]), "+f"(c[1]), "+f"(c[2]), "+f"(c[3])
        : "r"(a[0]), "r"(a[1]), "r"(a[2]), "r"(a[3]), "r"(b[0]), "r"(b[1]));
}

// ---------------- fused split pass (ONE launch: x hi/lo, Wq/Wk hi/lo, Wv/Wo hi) ----
#define XN4 (X_ELEMS / 4)
#define WN4 (W_ELEMS / 4)

__global__ void __launch_bounds__(256) split_all(
    const float4* __restrict__ x,  uint2* __restrict__ xh,  uint2* __restrict__ xl,
    const float4* __restrict__ wq, uint2* __restrict__ wqh, uint2* __restrict__ wql,
    const float4* __restrict__ wk, uint2* __restrict__ wkh, uint2* __restrict__ wkl,
    const float4* __restrict__ wv, uint2* __restrict__ wvh,
    const float4* __restrict__ wo, uint2* __restrict__ woh)
{
    const int y = blockIdx.y;
    const int i0 = blockIdx.x * 256 + threadIdx.x;

    auto split1 = [](float4 v, uint2& hi, uint2& lo) {
        __half h0 = __float2half_rn(v.x), h1 = __float2half_rn(v.y),
               h2 = __float2half_rn(v.z), h3 = __float2half_rn(v.w);
        __half2 p01 = __halves2half2(h0, h1), p23 = __halves2half2(h2, h3);
        hi = make_uint2(*(uint32_t*)&p01, *(uint32_t*)&p23);
        lo = make_uint2(packh2(v.x - __half2float(h0), v.y - __half2float(h1)),
                        packh2(v.z - __half2float(h2), v.w - __half2float(h3)));
    };

    if (y == 0) {
        // x: 4 strided chunks (XN4 = 4 * WN4)
#pragma unroll
        for (int c = 0; c < 4; c++) {
            const int i = i0 + c * (WN4);
            uint2 hi, lo;
            split1(x[i], hi, lo);
            xh[i] = hi; xl[i] = lo;
        }
    } else if (y == 1) {
        uint2 hi, lo; split1(wq[i0], hi, lo); wqh[i0] = hi; wql[i0] = lo;
    } else if (y == 2) {
        uint2 hi, lo; split1(wk[i0], hi, lo); wkh[i0] = hi; wkl[i0] = lo;
    } else if (y == 3) {
        float4 v = wv[i0];
        wvh[i0] = make_uint2(packh2(v.x, v.y), packh2(v.z, v.w));
    } else {
        float4 v = wo[i0];
        woh[i0] = make_uint2(packh2(v.x, v.y), packh2(v.z, v.w));
    }
}

// ---------------- GEMM: pre-split fp16, 1/2/3-product (R11-proven) ----------------
#define GSTR 40
#define GARR_B (128 * GSTR * 2)          // 10240 B
#define GEMM_SMEM 81920

template <int MODE, int NPROD>
__global__ void __launch_bounds__(256, 2) h16_gemm(
    const __half* __restrict__ Ah_g, const __half* __restrict__ Al_g,
    const __half* __restrict__ Bh_g, const __half* __restrict__ Bl_g,
    const float* __restrict__ gamma, const float* __restrict__ beta,
    const float* __restrict__ bias,
    __half* __restrict__ Ch, __half* __restrict__ Cl, float* __restrict__ C)
{
    constexpr uint32_t BOFF = (NPROD == 3 ? 2u : 1u) * GARR_B;
    constexpr uint32_t GSTG = (uint32_t)(NPROD + 1) * GARR_B;

    extern __shared__ char sm[];
    const uint32_t sbase = smem_u32(sm);
    const int tid  = threadIdx.x;
    const int lane = tid & 31;
    const int wid  = tid >> 5;
    const int warp_m = wid >> 2;
    const int warp_n = wid & 3;
    const int rb = blockIdx.x * 128;
    const int cb = blockIdx.y * 128;

    const int srow = tid >> 1;
    const int skoff = (tid & 1) * 16;
    const __half* Ap  = Ah_g + (size_t)(rb + srow) * EMBD + skoff;
    const __half* Alp = (NPROD == 3) ? Al_g + (size_t)(rb + srow) * EMBD + skoff : nullptr;
    const __half* Bp  = Bh_g + (size_t)(cb + srow) * EMBD + skoff;
    const __half* Blp = (NPROD >= 2) ? Bl_g + (size_t)(cb + srow) * EMBD + skoff : nullptr;
    const uint32_t sdst = ((uint32_t)srow * GSTR + (uint32_t)skoff) * 2;

    auto stage = [&](int s, int kc) {
        const uint32_t d = sbase + (uint32_t)s * GSTG + sdst;
        const int go = kc * 32;
        cp_async16(d,                 Ap + go);
        cp_async16(d + 16,            Ap + go + 8);
        if (NPROD == 3) {
            cp_async16(d + GARR_B,      Alp + go);
            cp_async16(d + GARR_B + 16, Alp + go + 8);
        }
        cp_async16(d + BOFF,      Bp + go);
        cp_async16(d + BOFF + 16, Bp + go + 8);
        if (NPROD >= 2) {
            cp_async16(d + BOFF + GARR_B,      Blp + go);
            cp_async16(d + BOFF + GARR_B + 16, Blp + go + 8);
        }
    };

    float acc[4][4][4] = {};

    const int afr = lane & 15;
    const int afc = (lane >> 4) << 3;
    const int bfr = lane & 7;
    const int bfc = ((lane & 15) >> 3) << 3;
    const uint32_t aM = sbase + ((uint32_t)(warp_m * 64 + afr) * GSTR + (uint32_t)afc) * 2;
    const uint32_t bN = sbase + BOFF
                      + ((uint32_t)(warp_n * 32 + bfr) * GSTR + (uint32_t)bfc) * 2;

    auto compute = [&](int s) {
        const uint32_t so = (uint32_t)s * GSTG;
#pragma unroll
        for (int ks = 0; ks < 2; ks++) {
            uint32_t bh[4][2], bl[4][2];
#pragma unroll
            for (int nf = 0; nf < 4; nf++) {
                const uint32_t ba = bN + so + (uint32_t)(nf * (8 * GSTR * 2) + ks * 32);
                LDSM_X2(bh[nf][0], bh[nf][1], ba);
                if (NPROD >= 2) { LDSM_X2(bl[nf][0], bl[nf][1], ba + GARR_B); }
            }
#pragma unroll
            for (int mf = 0; mf < 4; mf++) {
                uint32_t ah[4], al[4];
                const uint32_t aa = aM + so + (uint32_t)(mf * (16 * GSTR * 2) + ks * 32);
                LDSM_X4(ah[0], ah[1], ah[2], ah[3], aa);
                if (NPROD == 3) { LDSM_X4(al[0], al[1], al[2], al[3], aa + GARR_B); }
#pragma unroll
                for (int nf = 0; nf < 4; nf++) {
                    mma_f16(acc[mf][nf], ah, bh[nf]);
                    if (NPROD >= 2) mma_f16(acc[mf][nf], ah, bl[nf]);
                    if (NPROD == 3) mma_f16(acc[mf][nf], al, bh[nf]);
                }
            }
        }
    };

    stage(0, 0);
    CP_COMMIT();
    const int NC = EMBD / 32;
    for (int kc = 0; kc < NC; kc++) {
        if (kc + 1 < NC) { stage((kc + 1) & 1, kc + 1); CP_COMMIT(); CP_WAIT(1); }
        else             { CP_WAIT(0); }
        __syncthreads();
        compute(kc & 1);
        __syncthreads();
    }

    const int g = lane >> 2;
    const int q = lane & 3;
    float* Ct = (float*)sm;   // [128][132]
#pragma unroll
    for (int mf = 0; mf < 4; mf++)
#pragma unroll
        for (int nf = 0; nf < 4; nf++) {
            const int r = warp_m * 64 + mf * 16 + g;
            const int c = warp_n * 32 + nf * 8 + q * 2;
            *(float2*)&Ct[r * 132 + c]       = make_float2(acc[mf][nf][0], acc[mf][nf][1]);
            *(float2*)&Ct[(r + 8) * 132 + c] = make_float2(acc[mf][nf][2], acc[mf][nf][3]);
        }
    __syncthreads();

    {
        const int row = tid >> 1;
        const int seg = tid & 1;
        const float* crow = &Ct[row * 132 + seg * 64];

        if (MODE == 2) {
            const int c0 = cb + seg * 64;
            float* dst = C + (size_t)(rb + row) * EMBD + c0;
#pragma unroll
            for (int j = 0; j < 16; j++) {
                float4 v = *(const float4*)&crow[4 * j];
                float4 b4 = *(const float4*)&bias[c0 + 4 * j];
                v.x += b4.x; v.y += b4.y; v.z += b4.z; v.w += b4.w;
                *(float4*)(dst + 4 * j) = v;
            }
        } else {
            float mean = 0.f, rstd = 0.f;
            if (MODE == 0) {
                float s = 0.f, s2 = 0.f;
#pragma unroll
                for (int j = 0; j < 16; j++) {
                    float4 v = *(const float4*)&crow[4 * j];
                    s  += v.x + v.y + v.z + v.w;
                    s2 += v.x * v.x + v.y * v.y + v.z * v.z + v.w * v.w;
                }
                mean = s * (1.0f / 64.0f);
                rstd = rsqrtf(s2 * (1.0f / 64.0f) - mean * mean + 1e-5f);
            }
            const int grow = rb + row;
            const int n = grow >> 11;
            const int l = grow & (LSEQ - 1);
            const int hd = (cb >> 6) + seg;
            const size_t off = ((size_t)((n * NHEAD + hd) * LSEQ + l)) * HDIM;
#pragma unroll
            for (int j = 0; j < 8; j++) {
                float v[8];
                *(float4*)&v[0] = *(const float4*)&crow[8 * j];
                *(float4*)&v[4] = *(const float4*)&crow[8 * j + 4];
                if (MODE == 0) {
#pragma unroll
                    for (int k2 = 0; k2 < 8; k2++)
                        v[k2] = (v[k2] - mean) * rstd * __ldg(gamma + 8 * j + k2)
                                + __ldg(beta + 8 * j + k2);
                }
                __half hh[8];
#pragma unroll
                for (int k2 = 0; k2 < 8; k2++) hh[k2] = __float2half_rn(v[k2]);
                *(uint4*)(Ch + off + 8 * j) = *(uint4*)hh;
                if (MODE == 0) {
                    __half ll[8];
#pragma unroll
                    for (int k2 = 0; k2 < 8; k2++)
                        ll[k2] = __float2half_rn(v[k2] - __half2float(hh[k2]));
                    *(uint4*)(Cl + off + 8 * j) = *(uint4*)ll;
                }
            }
        }
    }
}

// ---------------- Attention v5: 3-stage pipeline, 1 barrier/tile, deferred l-sum ----
#define APAD 72
#define KV_ARR_H (32 * APAD)
#define STAGE_B (3 * KV_ARR_H * 2)       // 13824 B per stage (Kh|Kl|Vh)
#define ATTN_SMEM (3 * STAGE_B)          // 41472 B

__global__ void __launch_bounds__(128, 4) attn_mma(
    const __half* __restrict__ Qh, const __half* __restrict__ Ql,
    const __half* __restrict__ Kh, const __half* __restrict__ Kl,
    const __half* __restrict__ Vh, __half* __restrict__ Oh)
{
    extern __shared__ __half smh[];
    const uint32_t sbase = smem_u32(smh);

    const int tid  = threadIdx.x;
    const int lane = tid & 31;
    const int wid  = tid >> 5;
    const int g    = lane >> 2;
    const int t    = lane & 3;
    const int nh   = blockIdx.y;
    const int qt   = gridDim.x - 1 - blockIdx.x;   // heavy tiles first
    const int qb   = qt * 64;
    const size_t base = (size_t)nh * LSEQ * HDIM;

    const int krow = tid >> 2;
    const int kcol = (tid & 3) * 16;
    const uint32_t kv_sm_off = ((uint32_t)krow * APAD + (uint32_t)kcol) * 2;

    auto stage_kv = [&](int b, int kt) {
        const size_t goff = base + (size_t)(kt * 32 + krow) * HDIM + kcol;
        const uint32_t s0 = sbase + (uint32_t)b * STAGE_B + kv_sm_off;
        cp_async16(s0,                        Kh + goff);
        cp_async16(s0 + 16,                   Kh + goff + 8);
        cp_async16(s0 + KV_ARR_H * 2,         Kl + goff);
        cp_async16(s0 + KV_ARR_H * 2 + 16,    Kl + goff + 8);
        cp_async16(s0 + KV_ARR_H * 4,         Vh + goff);
        cp_async16(s0 + KV_ARR_H * 4 + 16,    Vh + goff + 8);
    };

    // --- prologue: Q tile (64x64 hi+lo) staged into smem start ---
    {
        const int qr = tid >> 1;
        const int qc = (tid & 1) * 32;
        const size_t goff = base + (size_t)(qb + qr) * HDIM + qc;
        const uint32_t s0 = sbase + ((uint32_t)qr * APAD + (uint32_t)qc) * 2;
#pragma unroll
        for (int i = 0; i < 4; i++) {
            cp_async16(s0 + i * 16,                 Qh + goff + i * 8);
            cp_async16(s0 + 64 * APAD * 2 + i * 16, Ql + goff + i * 8);
        }
        CP_COMMIT();
        CP_WAIT(0);
    }
    __syncthreads();

    uint32_t qfh[4][4], qfl[4][4];
    {
        const uint32_t qa = sbase
            + ((uint32_t)(wid * 16 + (lane & 15)) * APAD + (uint32_t)((lane >> 4) << 3)) * 2;
#pragma unroll
        for (int kc = 0; kc < 4; kc++) {
            LDSM_X4(qfh[kc][0], qfh[kc][1], qfh[kc][2], qfh[kc][3], qa + kc * 32);
            LDSM_X4(qfl[kc][0], qfl[kc][1], qfl[kc][2], qfl[kc][3],
                    qa + kc * 32 + 64 * APAD * 2);
        }
    }
    __syncthreads();   // Q reads complete before K/V staging overwrites region

    const int nkt = 2 * (qt + 1);
    stage_kv(0, 0);
    CP_COMMIT();
    if (1 < nkt) { stage_kv(1, 1); CP_COMMIT(); }

    float oc[8][4] = {};
    float m0 = -1e30f, m1 = -1e30f, l0 = 0.f, l1 = 0.f;

    const uint32_t kO = sbase
        + ((uint32_t)(lane & 7) * APAD + (uint32_t)(((lane & 15) >> 3) << 3)) * 2;
    const uint32_t vO = sbase + 4 * KV_ARR_H + (uint32_t)(lane & 15) * (APAD * 2);

    int buf = 0;
    for (int kt = 0; kt < nkt; kt++) {
        if (kt + 1 < nkt) { CP_WAIT(1); } else { CP_WAIT(0); }
        __syncthreads();   // tile kt visible; all warps done with tile kt-1's buffer
        if (kt + 2 < nkt) {
            int b2 = buf + 2; if (b2 >= 3) b2 -= 3;
            stage_kv(b2, kt + 2);
            CP_COMMIT();
        }

        const uint32_t stg = (uint32_t)buf * STAGE_B;

        // ---- S = Q K^T (3-product split), 64x32 ----
        float sc[4][4] = {};
#pragma unroll
        for (int kc = 0; kc < 4; kc++) {
#pragma unroll
            for (int nf = 0; nf < 4; nf++) {
                const uint32_t ka = kO + stg + (uint32_t)(nf * (8 * APAD * 2) + kc * 32);
                uint32_t bh[2], bl[2];
                LDSM_X2(bh[0], bh[1], ka);
                LDSM_X2(bl[0], bl[1], ka + KV_ARR_H * 2);
                mma_f16(sc[nf], qfh[kc], bh);
                mma_f16(sc[nf], qfh[kc], bl);
                mma_f16(sc[nf], qfl[kc], bh);
            }
        }

        // ---- causal mask (last two tiles) ----
        if (kt >= 2 * qt) {
            const int diag = (kt - 2 * qt) * 32;
            const int r0 = wid * 16 + g - diag;
            const int r1 = r0 + 8;
#pragma unroll
            for (int nf = 0; nf < 4; nf++) {
                const int c0 = nf * 8 + 2 * t;
                if (c0     > r0) sc[nf][0] = -1e30f;
                if (c0 + 1 > r0) sc[nf][1] = -1e30f;
                if (c0     > r1) sc[nf][2] = -1e30f;
                if (c0 + 1 > r1) sc[nf][3] = -1e30f;
            }
        }

        // ---- online softmax (deferred cross-thread l-sum) ----
        {
            float rm0 = -1e30f, rm1 = -1e30f;
#pragma unroll
            for (int nf = 0; nf < 4; nf++) {
                rm0 = fmaxf(rm0, fmaxf(sc[nf][0], sc[nf][1]));
                rm1 = fmaxf(rm1, fmaxf(sc[nf][2], sc[nf][3]));
            }
            rm0 = fmaxf(rm0, __shfl_xor_sync(0xffffffffu, rm0, 1));
            rm0 = fmaxf(rm0, __shfl_xor_sync(0xffffffffu, rm0, 2));
            rm1 = fmaxf(rm1, __shfl_xor_sync(0xffffffffu, rm1, 1));
            rm1 = fmaxf(rm1, __shfl_xor_sync(0xffffffffu, rm1, 2));

            const float mn0 = fmaxf(m0, rm0), mn1 = fmaxf(m1, rm1);
            const float cr0 = __expf(m0 - mn0), cr1 = __expf(m1 - mn1);
            float rs0 = 0.f, rs1 = 0.f;
#pragma unroll
            for (int nf = 0; nf < 4; nf++) {
                sc[nf][0] = __expf(sc[nf][0] - mn0);
                sc[nf][1] = __expf(sc[nf][1] - mn0);
                sc[nf][2] = __expf(sc[nf][2] - mn1);
                sc[nf][3] = __expf(sc[nf][3] - mn1);
                rs0 += sc[nf][0] + sc[nf][1];
                rs1 += sc[nf][2] + sc[nf][3];
            }
            // per-thread partial sums; quad reduction deferred to epilogue
            l0 = l0 * cr0 + rs0;
            l1 = l1 * cr1 + rs1;
            m0 = mn0; m1 = mn1;
#pragma unroll
            for (int nf = 0; nf < 8; nf++) {
                oc[nf][0] *= cr0; oc[nf][1] *= cr0;
                oc[nf][2] *= cr1; oc[nf][3] *= cr1;
            }
        }

        // ---- O += P Vh ----
#pragma unroll
        for (int kc = 0; kc < 2; kc++) {
            uint32_t pah[4];
            {
                const float* e0 = sc[2 * kc];
                const float* e1 = sc[2 * kc + 1];
                pah[0] = packh2(e0[0], e0[1]);
                pah[1] = packh2(e0[2], e0[3]);
                pah[2] = packh2(e1[0], e1[1]);
                pah[3] = packh2(e1[2], e1[3]);
            }
#pragma unroll
            for (int nf = 0; nf < 8; nf++) {
                uint32_t vh[2];
                LDSM_X2T(vh[0], vh[1],
                         vO + stg + (uint32_t)(kc * (16 * APAD * 2) + nf * 16));
                mma_f16(oc[nf], pah, vh);
            }
        }

        if (++buf == 3) buf = 0;
    }

    // ---- epilogue: finish l reduction, normalize, fp16 scatter ----
    l0 += __shfl_xor_sync(0xffffffffu, l0, 1);
    l0 += __shfl_xor_sync(0xffffffffu, l0, 2);
    l1 += __shfl_xor_sync(0xffffffffu, l1, 1);
    l1 += __shfl_xor_sync(0xffffffffu, l1, 2);
    const float inv0 = 1.0f / l0, inv1 = 1.0f / l1;
    const int n = nh >> 4;
    const int h = nh & 15;
    const int r0 = qb + wid * 16 + g;
    const int r1 = r0 + 8;
#pragma unroll
    for (int nf = 0; nf < 8; nf++) {
        const int col = h * HDIM + nf * 8 + 2 * t;
        *(uint32_t*)(Oh + (size_t)(n * LSEQ + r0) * EMBD + col) =
            packh2(oc[nf][0] * inv0, oc[nf][1] * inv0);
        *(uint32_t*)(Oh + (size_t)(n * LSEQ + r1) * EMBD + col) =
            packh2(oc[nf][2] * inv1, oc[nf][3] * inv1);
    }
}

// ------------------------- launch -------------------------
extern "C" void kernel_launch(void* const* d_in, const int* in_sizes, int n_in,
                              void* d_out, int out_size)
{
    (void)in_sizes; (void)n_in; (void)out_size;
    const float* x  = (const float*)d_in[0];
    const float* Wq = (const float*)d_in[2];
    const float* Wk = (const float*)d_in[3];
    const float* Wv = (const float*)d_in[4];
    const float* gq = (const float*)d_in[5];
    const float* bq = (const float*)d_in[6];
    const float* gk = (const float*)d_in[7];
    const float* bk = (const float*)d_in[8];
    const float* Wo = (const float*)d_in[9];
    const float* bo = (const float*)d_in[10];
    float* out = (float*)d_out;

    __half *xh, *xl, *wqh, *wql, *wkh, *wkl, *wvh, *woh;
    __half *qh, *ql, *kh, *kl, *vh, *oh;
    cudaGetSymbolAddress((void**)&xh, g_xh);   cudaGetSymbolAddress((void**)&xl, g_xl);
    cudaGetSymbolAddress((void**)&wqh, g_wqh); cudaGetSymbolAddress((void**)&wql, g_wql);
    cudaGetSymbolAddress((void**)&wkh, g_wkh); cudaGetSymbolAddress((void**)&wkl, g_wkl);
    cudaGetSymbolAddress((void**)&wvh, g_wvh);
    cudaGetSymbolAddress((void**)&woh, g_woh);
    cudaGetSymbolAddress((void**)&qh, g_qh);   cudaGetSymbolAddress((void**)&ql, g_ql);
    cudaGetSymbolAddress((void**)&kh, g_kh);   cudaGetSymbolAddress((void**)&kl, g_kl);
    cudaGetSymbolAddress((void**)&vh, g_vh);
    cudaGetSymbolAddress((void**)&oh, g_oh);

    cudaFuncSetAttribute(h16_gemm<0,3>, cudaFuncAttributeMaxDynamicSharedMemorySize, GEMM_SMEM);
    cudaFuncSetAttribute(h16_gemm<1,1>, cudaFuncAttributeMaxDynamicSharedMemorySize, GEMM_SMEM);
    cudaFuncSetAttribute(h16_gemm<2,1>, cudaFuncAttributeMaxDynamicSharedMemorySize, GEMM_SMEM);
    cudaFuncSetAttribute(attn_mma, cudaFuncAttributeMaxDynamicSharedMemorySize, ATTN_SMEM);

    // #1: fused split (x hi/lo, Wq/Wk hi/lo, Wv/Wo hi)
    split_all<<<dim3(WN4 / 256, 5), 256>>>(
        (const float4*)x,  (uint2*)xh,  (uint2*)xl,
        (const float4*)Wq, (uint2*)wqh, (uint2*)wql,
        (const float4*)Wk, (uint2*)wkh, (uint2*)wkl,
        (const float4*)Wv, (uint2*)wvh,
        (const float4*)Wo, (uint2*)woh);

    dim3 gg(MROWS / 128, EMBD / 128);
    // #2: V first (so attn is launch #5 for ncu capture)
    h16_gemm<1,1><<<gg, 256, GEMM_SMEM>>>(xh, nullptr, wvh, nullptr, nullptr, nullptr, nullptr,
                                          vh, nullptr, nullptr);
    // #3, #4: Q, K projections
    h16_gemm<0,3><<<gg, 256, GEMM_SMEM>>>(xh, xl, wqh, wql, gq, bq, nullptr, qh, ql, nullptr);
    h16_gemm<0,3><<<gg, 256, GEMM_SMEM>>>(xh, xl, wkh, wkl, gk, bk, nullptr, kh, kl, nullptr);

    // #5: attention
    attn_mma<<<dim3(LSEQ / 64, NBATCH * NHEAD), 128, ATTN_SMEM>>>(qh, ql, kh, kl, vh, oh);

    // #6: output projection
    h16_gemm<2,1><<<gg, 256, GEMM_SMEM>>>(oh, nullptr, woh, nullptr, nullptr, nullptr, bo,
                                          nullptr, nullptr, out);
}

// round 14
// speedup vs baseline: 2.7413x; 1.0281x over previous
#include <cuda_runtime.h>
#include <cuda_fp16.h>
#include <cstdint>

// Problem constants
#define NBATCH 2
#define LSEQ   2048
#define EMBD   1024
#define NHEAD  16
#define HDIM   64
#define MROWS  (NBATCH * LSEQ)   // 4096
#define QKV_ELEMS (NBATCH * NHEAD * LSEQ * HDIM)
#define W_ELEMS (EMBD * EMBD)
#define X_ELEMS (MROWS * EMBD)

// Scratch (device globals: no allocation allowed)
__device__ __half g_xh[X_ELEMS], g_xl[X_ELEMS];
__device__ __half g_wqh[W_ELEMS], g_wql[W_ELEMS];
__device__ __half g_wkh[W_ELEMS], g_wkl[W_ELEMS];
__device__ __half g_wvh[W_ELEMS];
__device__ __half g_woh[W_ELEMS];
__device__ __half g_qh[QKV_ELEMS], g_ql[QKV_ELEMS];
__device__ __half g_kh[QKV_ELEMS], g_kl[QKV_ELEMS];
__device__ __half g_vh[QKV_ELEMS];
__device__ __half g_oh[X_ELEMS];

__device__ __forceinline__ uint32_t smem_u32(const void* p) {
    uint32_t a;
    asm("{ .reg .u64 t; cvta.to.shared.u64 t, %1; cvt.u32.u64 %0, t; }"
        : "=r"(a) : "l"(p));
    return a;
}
__device__ __forceinline__ uint32_t packh2(float a, float b) {
    __half2 h = __floats2half2_rn(a, b);
    return *reinterpret_cast<uint32_t*>(&h);
}
__device__ __forceinline__ void cp_async16(uint32_t dst, const void* src) {
    asm volatile("cp.async.cg.shared.global [%0], [%1], 16;" :: "r"(dst), "l"(src));
}
#define CP_COMMIT() asm volatile("cp.async.commit_group;" ::: "memory")
#define CP_WAIT(N)  asm volatile("cp.async.wait_group %0;" :: "n"(N) : "memory")

#define LDSM_X4(r0, r1, r2, r3, addr) \
    asm volatile("ldmatrix.sync.aligned.m8n8.x4.shared.b16 {%0,%1,%2,%3}, [%4];" \
        : "=r"(r0), "=r"(r1), "=r"(r2), "=r"(r3) : "r"(addr))
#define LDSM_X4T(r0, r1, r2, r3, addr) \
    asm volatile("ldmatrix.sync.aligned.m8n8.x4.trans.shared.b16 {%0,%1,%2,%3}, [%4];" \
        : "=r"(r0), "=r"(r1), "=r"(r2), "=r"(r3) : "r"(addr))

__device__ __forceinline__ void mma_f16(float* c, const uint32_t* a, const uint32_t* b) {
    asm volatile(
        "mma.sync.aligned.m16n8k16.row.col.f32.f16.f16.f32 "
        "{%0,%1,%2,%3}, {%4,%5,%6,%7}, {%8,%9}, {%0,%1,%2,%3};"
        : "+f"(c[0]), "+f"(c[1]), "+f"(c[2]), "+f"(c[3])
        : "r"(a[0]), "r"(a[1]), "r"(a[2]), "r"(a[3]), "r"(b[0]), "r"(b[1]));
}

// ---------------- fused split pass ----------------
#define WN4 (W_ELEMS / 4)

__global__ void __launch_bounds__(256) split_all(
    const float4* __restrict__ x,  uint2* __restrict__ xh,  uint2* __restrict__ xl,
    const float4* __restrict__ wq, uint2* __restrict__ wqh, uint2* __restrict__ wql,
    const float4* __restrict__ wk, uint2* __restrict__ wkh, uint2* __restrict__ wkl,
    const float4* __restrict__ wv, uint2* __restrict__ wvh,
    const float4* __restrict__ wo, uint2* __restrict__ woh)
{
    const int y = blockIdx.y;
    const int i0 = blockIdx.x * 256 + threadIdx.x;

    auto split1 = [](float4 v, uint2& hi, uint2& lo) {
        __half h0 = __float2half_rn(v.x), h1 = __float2half_rn(v.y),
               h2 = __float2half_rn(v.z), h3 = __float2half_rn(v.w);
        __half2 p01 = __halves2half2(h0, h1), p23 = __halves2half2(h2, h3);
        hi = make_uint2(*(uint32_t*)&p01, *(uint32_t*)&p23);
        lo = make_uint2(packh2(v.x - __half2float(h0), v.y - __half2float(h1)),
                        packh2(v.z - __half2float(h2), v.w - __half2float(h3)));
    };

    if (y == 0) {
#pragma unroll
        for (int c = 0; c < 4; c++) {
            const int i = i0 + c * WN4;
            uint2 hi, lo;
            split1(x[i], hi, lo);
            xh[i] = hi; xl[i] = lo;
        }
    } else if (y == 1) {
        uint2 hi, lo; split1(wq[i0], hi, lo); wqh[i0] = hi; wql[i0] = lo;
    } else if (y == 2) {
        uint2 hi, lo; split1(wk[i0], hi, lo); wkh[i0] = hi; wkl[i0] = lo;
    } else if (y == 3) {
        float4 v = wv[i0];
        wvh[i0] = make_uint2(packh2(v.x, v.y), packh2(v.z, v.w));
    } else {
        float4 v = wo[i0];
        woh[i0] = make_uint2(packh2(v.x, v.y), packh2(v.z, v.w));
    }
}

// ---------------- GEMM: R12 skeleton (GSTR=40, 2-stage) + X4 B-frag pairs ----------
#define GSTR 40                          // 80B rows: 16B-aligned + conflict-free
#define GARR_B (128 * GSTR * 2)          // 10240 B
#define GEMM_SMEM 81920                  // 2 stages of NPROD=3 (covers Ct too)

template <int MODE, int NPROD>
__global__ void __launch_bounds__(256, 2) h16_gemm(
    const __half* __restrict__ Ah_g, const __half* __restrict__ Al_g,
    const __half* __restrict__ Bh_g, const __half* __restrict__ Bl_g,
    const float* __restrict__ gamma, const float* __restrict__ beta,
    const float* __restrict__ bias,
    __half* __restrict__ Ch, __half* __restrict__ Cl, float* __restrict__ C)
{
    constexpr uint32_t BOFF = (NPROD == 3 ? 2u : 1u) * GARR_B;
    constexpr uint32_t GSTG = (uint32_t)(NPROD + 1) * GARR_B;

    extern __shared__ char sm[];
    const uint32_t sbase = smem_u32(sm);
    const int tid  = threadIdx.x;
    const int lane = tid & 31;
    const int wid  = tid >> 5;
    const int warp_m = wid >> 2;
    const int warp_n = wid & 3;
    const int rb = blockIdx.x * 128;
    const int cb = blockIdx.y * 128;

    const int srow = tid >> 1;
    const int skoff = (tid & 1) * 16;
    const __half* Ap  = Ah_g + (size_t)(rb + srow) * EMBD + skoff;
    const __half* Alp = (NPROD == 3) ? Al_g + (size_t)(rb + srow) * EMBD + skoff : nullptr;
    const __half* Bp  = Bh_g + (size_t)(cb + srow) * EMBD + skoff;
    const __half* Blp = (NPROD >= 2) ? Bl_g + (size_t)(cb + srow) * EMBD + skoff : nullptr;
    const uint32_t sdst = ((uint32_t)srow * GSTR + (uint32_t)skoff) * 2;

    auto stage = [&](int s, int kc) {
        const uint32_t d = sbase + (uint32_t)s * GSTG + sdst;
        const int go = kc * 32;
        cp_async16(d,                 Ap + go);
        cp_async16(d + 16,            Ap + go + 8);
        if (NPROD == 3) {
            cp_async16(d + GARR_B,      Alp + go);
            cp_async16(d + GARR_B + 16, Alp + go + 8);
        }
        cp_async16(d + BOFF,      Bp + go);
        cp_async16(d + BOFF + 16, Bp + go + 8);
        if (NPROD >= 2) {
            cp_async16(d + BOFF + GARR_B,      Blp + go);
            cp_async16(d + BOFF + GARR_B + 16, Blp + go + 8);
        }
    };

    float acc[4][4][4] = {};

    // A-frag X4 base (one mf per load)
    const uint32_t aM = sbase
        + ((uint32_t)(warp_m * 64 + (lane & 15)) * GSTR + (uint32_t)((lane >> 4) << 3)) * 2;
    // B-frag X4 base (two nf per load)
    const uint32_t bN = sbase + BOFF
        + ((uint32_t)(warp_n * 32 + ((lane >> 4) << 3) + (lane & 7)) * GSTR
           + (uint32_t)(((lane & 15) >> 3) << 3)) * 2;

    auto compute = [&](int s) {
        const uint32_t so = (uint32_t)s * GSTG;
#pragma unroll
        for (int ks = 0; ks < 2; ks++) {
            uint32_t bh[4][2], bl[4][2];
#pragma unroll
            for (int nfp = 0; nfp < 2; nfp++) {
                const uint32_t ba = bN + so + (uint32_t)(nfp * (16 * GSTR * 2) + ks * 32);
                LDSM_X4(bh[2*nfp][0], bh[2*nfp][1], bh[2*nfp+1][0], bh[2*nfp+1][1], ba);
                if (NPROD >= 2) {
                    LDSM_X4(bl[2*nfp][0], bl[2*nfp][1], bl[2*nfp+1][0], bl[2*nfp+1][1],
                            ba + GARR_B);
                }
            }
#pragma unroll
            for (int mf = 0; mf < 4; mf++) {
                uint32_t ah[4], al[4];
                const uint32_t aa = aM + so + (uint32_t)(mf * (16 * GSTR * 2) + ks * 32);
                LDSM_X4(ah[0], ah[1], ah[2], ah[3], aa);
                if (NPROD == 3) { LDSM_X4(al[0], al[1], al[2], al[3], aa + GARR_B); }
#pragma unroll
                for (int nf = 0; nf < 4; nf++) {
                    mma_f16(acc[mf][nf], ah, bh[nf]);
                    if (NPROD >= 2) mma_f16(acc[mf][nf], ah, bl[nf]);
                    if (NPROD == 3) mma_f16(acc[mf][nf], al, bh[nf]);
                }
            }
        }
    };

    stage(0, 0);
    CP_COMMIT();
    const int NC = EMBD / 32;
    for (int kc = 0; kc < NC; kc++) {
        if (kc + 1 < NC) { stage((kc + 1) & 1, kc + 1); CP_COMMIT(); CP_WAIT(1); }
        else             { CP_WAIT(0); }
        __syncthreads();
        compute(kc & 1);
        __syncthreads();
    }

    const int g = lane >> 2;
    const int q = lane & 3;
    float* Ct = (float*)sm;   // [128][132]
#pragma unroll
    for (int mf = 0; mf < 4; mf++)
#pragma unroll
        for (int nf = 0; nf < 4; nf++) {
            const int r = warp_m * 64 + mf * 16 + g;
            const int c = warp_n * 32 + nf * 8 + q * 2;
            *(float2*)&Ct[r * 132 + c]       = make_float2(acc[mf][nf][0], acc[mf][nf][1]);
            *(float2*)&Ct[(r + 8) * 132 + c] = make_float2(acc[mf][nf][2], acc[mf][nf][3]);
        }
    __syncthreads();

    {
        const int row = tid >> 1;
        const int seg = tid & 1;
        const float* crow = &Ct[row * 132 + seg * 64];

        if (MODE == 2) {
            const int c0 = cb + seg * 64;
            float* dst = C + (size_t)(rb + row) * EMBD + c0;
#pragma unroll
            for (int j = 0; j < 16; j++) {
                float4 v = *(const float4*)&crow[4 * j];
                float4 b4 = *(const float4*)&bias[c0 + 4 * j];
                v.x += b4.x; v.y += b4.y; v.z += b4.z; v.w += b4.w;
                *(float4*)(dst + 4 * j) = v;
            }
        } else {
            float mean = 0.f, rstd = 0.f;
            if (MODE == 0) {
                float s = 0.f, s2 = 0.f;
#pragma unroll
                for (int j = 0; j < 16; j++) {
                    float4 v = *(const float4*)&crow[4 * j];
                    s  += v.x + v.y + v.z + v.w;
                    s2 += v.x * v.x + v.y * v.y + v.z * v.z + v.w * v.w;
                }
                mean = s * (1.0f / 64.0f);
                rstd = rsqrtf(s2 * (1.0f / 64.0f) - mean * mean + 1e-5f);
            }
            const int grow = rb + row;
            const int n = grow >> 11;
            const int l = grow & (LSEQ - 1);
            const int hd = (cb >> 6) + seg;
            const size_t off = ((size_t)((n * NHEAD + hd) * LSEQ + l)) * HDIM;
#pragma unroll
            for (int j = 0; j < 8; j++) {
                float v[8];
                *(float4*)&v[0] = *(const float4*)&crow[8 * j];
                *(float4*)&v[4] = *(const float4*)&crow[8 * j + 4];
                if (MODE == 0) {
#pragma unroll
                    for (int k2 = 0; k2 < 8; k2++)
                        v[k2] = (v[k2] - mean) * rstd * __ldg(gamma + 8 * j + k2)
                                + __ldg(beta + 8 * j + k2);
                }
                __half hh[8];
#pragma unroll
                for (int k2 = 0; k2 < 8; k2++) hh[k2] = __float2half_rn(v[k2]);
                *(uint4*)(Ch + off + 8 * j) = *(uint4*)hh;
                if (MODE == 0) {
                    __half ll[8];
#pragma unroll
                    for (int k2 = 0; k2 < 8; k2++)
                        ll[k2] = __float2half_rn(v[k2] - __half2float(hh[k2]));
                    *(uint4*)(Cl + off + 8 * j) = *(uint4*)ll;
                }
            }
        }
    }
}

// ---------------- Attention v6: 3-stage, X4 K-frags, X4T V-frags ----------------
#define APAD 72                          // 144B rows: 16B-aligned, conflict-free
#define KV_ARR_H (32 * APAD)
#define STAGE_B (3 * KV_ARR_H * 2)       // 13824 B (Kh|Kl|Vh)
#define ATTN_SMEM (3 * STAGE_B)          // 41472 B

__global__ void __launch_bounds__(128, 4) attn_mma(
    const __half* __restrict__ Qh, const __half* __restrict__ Ql,
    const __half* __restrict__ Kh, const __half* __restrict__ Kl,
    const __half* __restrict__ Vh, __half* __restrict__ Oh)
{
    extern __shared__ __half smh[];
    const uint32_t sbase = smem_u32(smh);

    const int tid  = threadIdx.x;
    const int lane = tid & 31;
    const int wid  = tid >> 5;
    const int g    = lane >> 2;
    const int t    = lane & 3;
    const int nh   = blockIdx.y;
    const int qt   = gridDim.x - 1 - blockIdx.x;
    const int qb   = qt * 64;
    const size_t base = (size_t)nh * LSEQ * HDIM;

    const int krow = tid >> 2;
    const int kcol = (tid & 3) * 16;
    const uint32_t kv_sm_off = ((uint32_t)krow * APAD + (uint32_t)kcol) * 2;

    auto stage_kv = [&](int b, int kt) {
        const size_t goff = base + (size_t)(kt * 32 + krow) * HDIM + kcol;
        const uint32_t s0 = sbase + (uint32_t)b * STAGE_B + kv_sm_off;
        cp_async16(s0,                        Kh + goff);
        cp_async16(s0 + 16,                   Kh + goff + 8);
        cp_async16(s0 + KV_ARR_H * 2,         Kl + goff);
        cp_async16(s0 + KV_ARR_H * 2 + 16,    Kl + goff + 8);
        cp_async16(s0 + KV_ARR_H * 4,         Vh + goff);
        cp_async16(s0 + KV_ARR_H * 4 + 16,    Vh + goff + 8);
    };

    // --- prologue: Q tile ---
    {
        const int qr = tid >> 1;
        const int qc = (tid & 1) * 32;
        const size_t goff = base + (size_t)(qb + qr) * HDIM + qc;
        const uint32_t s0 = sbase + ((uint32_t)qr * APAD + (uint32_t)qc) * 2;
#pragma unroll
        for (int i = 0; i < 4; i++) {
            cp_async16(s0 + i * 16,                 Qh + goff + i * 8);
            cp_async16(s0 + 64 * APAD * 2 + i * 16, Ql + goff + i * 8);
        }
        CP_COMMIT();
        CP_WAIT(0);
    }
    __syncthreads();

    uint32_t qfh[4][4], qfl[4][4];
    {
        const uint32_t qa = sbase
            + ((uint32_t)(wid * 16 + (lane & 15)) * APAD + (uint32_t)((lane >> 4) << 3)) * 2;
#pragma unroll
        for (int kc = 0; kc < 4; kc++) {
            LDSM_X4(qfh[kc][0], qfh[kc][1], qfh[kc][2], qfh[kc][3], qa + kc * 32);
            LDSM_X4(qfl[kc][0], qfl[kc][1], qfl[kc][2], qfl[kc][3],
                    qa + kc * 32 + 64 * APAD * 2);
        }
    }
    __syncthreads();

    const int nkt = 2 * (qt + 1);
    stage_kv(0, 0);
    CP_COMMIT();
    if (1 < nkt) { stage_kv(1, 1); CP_COMMIT(); }

    float oc[8][4] = {};
    float m0 = -1e30f, m1 = -1e30f, l0 = 0.f, l1 = 0.f;

    const uint32_t kO4 = sbase
        + ((uint32_t)(((lane >> 4) << 3) + (lane & 7)) * APAD
           + (uint32_t)(((lane & 15) >> 3) << 3)) * 2;
    const uint32_t vO4 = sbase + 4 * KV_ARR_H
        + ((uint32_t)(lane & 15) * APAD + (uint32_t)((lane >> 4) << 3)) * 2;

    int buf = 0;
    for (int kt = 0; kt < nkt; kt++) {
        if (kt + 1 < nkt) { CP_WAIT(1); } else { CP_WAIT(0); }
        __syncthreads();
        if (kt + 2 < nkt) {
            int b2 = buf + 2; if (b2 >= 3) b2 -= 3;
            stage_kv(b2, kt + 2);
            CP_COMMIT();
        }

        const uint32_t stg = (uint32_t)buf * STAGE_B;

        float sc[4][4] = {};
#pragma unroll
        for (int kc = 0; kc < 4; kc++) {
#pragma unroll
            for (int nfp = 0; nfp < 2; nfp++) {
                const uint32_t ka = kO4 + stg + (uint32_t)(nfp * (16 * APAD * 2) + kc * 32);
                uint32_t bh[2][2], bl[2][2];
                LDSM_X4(bh[0][0], bh[0][1], bh[1][0], bh[1][1], ka);
                LDSM_X4(bl[0][0], bl[0][1], bl[1][0], bl[1][1], ka + KV_ARR_H * 2);
#pragma unroll
                for (int j = 0; j < 2; j++) {
                    const int nf = 2 * nfp + j;
                    mma_f16(sc[nf], qfh[kc], bh[j]);
                    mma_f16(sc[nf], qfh[kc], bl[j]);
                    mma_f16(sc[nf], qfl[kc], bh[j]);
                }
            }
        }

        if (kt >= 2 * qt) {
            const int diag = (kt - 2 * qt) * 32;
            const int r0 = wid * 16 + g - diag;
            const int r1 = r0 + 8;
#pragma unroll
            for (int nf = 0; nf < 4; nf++) {
                const int c0 = nf * 8 + 2 * t;
                if (c0     > r0) sc[nf][0] = -1e30f;
                if (c0 + 1 > r0) sc[nf][1] = -1e30f;
                if (c0     > r1) sc[nf][2] = -1e30f;
                if (c0 + 1 > r1) sc[nf][3] = -1e30f;
            }
        }

        {
            float rm0 = -1e30f, rm1 = -1e30f;
#pragma unroll
            for (int nf = 0; nf < 4; nf++) {
                rm0 = fmaxf(rm0, fmaxf(sc[nf][0], sc[nf][1]));
                rm1 = fmaxf(rm1, fmaxf(sc[nf][2], sc[nf][3]));
            }
            rm0 = fmaxf(rm0, __shfl_xor_sync(0xffffffffu, rm0, 1));
            rm0 = fmaxf(rm0, __shfl_xor_sync(0xffffffffu, rm0, 2));
            rm1 = fmaxf(rm1, __shfl_xor_sync(0xffffffffu, rm1, 1));
            rm1 = fmaxf(rm1, __shfl_xor_sync(0xffffffffu, rm1, 2));

            const float mn0 = fmaxf(m0, rm0), mn1 = fmaxf(m1, rm1);
            const float cr0 = __expf(m0 - mn0), cr1 = __expf(m1 - mn1);
            float rs0 = 0.f, rs1 = 0.f;
#pragma unroll
            for (int nf = 0; nf < 4; nf++) {
                sc[nf][0] = __expf(sc[nf][0] - mn0);
                sc[nf][1] = __expf(sc[nf][1] - mn0);
                sc[nf][2] = __expf(sc[nf][2] - mn1);
                sc[nf][3] = __expf(sc[nf][3] - mn1);
                rs0 += sc[nf][0] + sc[nf][1];
                rs1 += sc[nf][2] + sc[nf][3];
            }
            l0 = l0 * cr0 + rs0;
            l1 = l1 * cr1 + rs1;
            m0 = mn0; m1 = mn1;
#pragma unroll
            for (int nf = 0; nf < 8; nf++) {
                oc[nf][0] *= cr0; oc[nf][1] *= cr0;
                oc[nf][2] *= cr1; oc[nf][3] *= cr1;
            }
        }

#pragma unroll
        for (int kc = 0; kc < 2; kc++) {
            uint32_t pah[4];
            {
                const float* e0 = sc[2 * kc];
                const float* e1 = sc[2 * kc + 1];
                pah[0] = packh2(e0[0], e0[1]);
                pah[1] = packh2(e0[2], e0[3]);
                pah[2] = packh2(e1[0], e1[1]);
                pah[3] = packh2(e1[2], e1[3]);
            }
#pragma unroll
            for (int nfp = 0; nfp < 4; nfp++) {
                uint32_t vh[2][2];
                LDSM_X4T(vh[0][0], vh[0][1], vh[1][0], vh[1][1],
                         vO4 + stg + (uint32_t)(kc * (16 * APAD * 2) + nfp * 32));
                mma_f16(oc[2 * nfp],     pah, vh[0]);
                mma_f16(oc[2 * nfp + 1], pah, vh[1]);
            }
        }

        if (++buf == 3) buf = 0;
    }

    // ---- epilogue ----
    l0 += __shfl_xor_sync(0xffffffffu, l0, 1);
    l0 += __shfl_xor_sync(0xffffffffu, l0, 2);
    l1 += __shfl_xor_sync(0xffffffffu, l1, 1);
    l1 += __shfl_xor_sync(0xffffffffu, l1, 2);
    const float inv0 = 1.0f / l0, inv1 = 1.0f / l1;
    const int n = nh >> 4;
    const int h = nh & 15;
    const int r0 = qb + wid * 16 + g;
    const int r1 = r0 + 8;
#pragma unroll
    for (int nf = 0; nf < 8; nf++) {
        const int col = h * HDIM + nf * 8 + 2 * t;
        *(uint32_t*)(Oh + (size_t)(n * LSEQ + r0) * EMBD + col) =
            packh2(oc[nf][0] * inv0, oc[nf][1] * inv0);
        *(uint32_t*)(Oh + (size_t)(n * LSEQ + r1) * EMBD + col) =
            packh2(oc[nf][2] * inv1, oc[nf][3] * inv1);
    }
}

// ------------------------- launch -------------------------
extern "C" void kernel_launch(void* const* d_in, const int* in_sizes, int n_in,
                              void* d_out, int out_size)
{
    (void)in_sizes; (void)n_in; (void)out_size;
    const float* x  = (const float*)d_in[0];
    const float* Wq = (const float*)d_in[2];
    const float* Wk = (const float*)d_in[3];
    const float* Wv = (const float*)d_in[4];
    const float* gq = (const float*)d_in[5];
    const float* bq = (const float*)d_in[6];
    const float* gk = (const float*)d_in[7];
    const float* bk = (const float*)d_in[8];
    const float* Wo = (const float*)d_in[9];
    const float* bo = (const float*)d_in[10];
    float* out = (float*)d_out;

    __half *xh, *xl, *wqh, *wql, *wkh, *wkl, *wvh, *woh;
    __half *qh, *ql, *kh, *kl, *vh, *oh;
    cudaGetSymbolAddress((void**)&xh, g_xh);   cudaGetSymbolAddress((void**)&xl, g_xl);
    cudaGetSymbolAddress((void**)&wqh, g_wqh); cudaGetSymbolAddress((void**)&wql, g_wql);
    cudaGetSymbolAddress((void**)&wkh, g_wkh); cudaGetSymbolAddress((void**)&wkl, g_wkl);
    cudaGetSymbolAddress((void**)&wvh, g_wvh);
    cudaGetSymbolAddress((void**)&woh, g_woh);
    cudaGetSymbolAddress((void**)&qh, g_qh);   cudaGetSymbolAddress((void**)&ql, g_ql);
    cudaGetSymbolAddress((void**)&kh, g_kh);   cudaGetSymbolAddress((void**)&kl, g_kl);
    cudaGetSymbolAddress((void**)&vh, g_vh);
    cudaGetSymbolAddress((void**)&oh, g_oh);

    cudaFuncSetAttribute(h16_gemm<0,3>, cudaFuncAttributeMaxDynamicSharedMemorySize, GEMM_SMEM);
    cudaFuncSetAttribute(h16_gemm<1,1>, cudaFuncAttributeMaxDynamicSharedMemorySize, GEMM_SMEM);
    cudaFuncSetAttribute(h16_gemm<2,1>, cudaFuncAttributeMaxDynamicSharedMemorySize, GEMM_SMEM);
    cudaFuncSetAttribute(attn_mma, cudaFuncAttributeMaxDynamicSharedMemorySize, ATTN_SMEM);

    // #1: fused split
    split_all<<<dim3(WN4 / 256, 5), 256>>>(
        (const float4*)x,  (uint2*)xh,  (uint2*)xl,
        (const float4*)Wq, (uint2*)wqh, (uint2*)wql,
        (const float4*)Wk, (uint2*)wkh, (uint2*)wkl,
        (const float4*)Wv, (uint2*)wvh,
        (const float4*)Wo, (uint2*)woh);

    dim3 gg(MROWS / 128, EMBD / 128);
    // #2: V first (attn stays launch #5 for ncu)
    h16_gemm<1,1><<<gg, 256, GEMM_SMEM>>>(xh, nullptr, wvh, nullptr, nullptr, nullptr, nullptr,
                                          vh, nullptr, nullptr);
    // #3, #4: Q, K projections
    h16_gemm<0,3><<<gg, 256, GEMM_SMEM>>>(xh, xl, wqh, wql, gq, bq, nullptr, qh, ql, nullptr);
    h16_gemm<0,3><<<gg, 256, GEMM_SMEM>>>(xh, xl, wkh, wkl, gk, bk, nullptr, kh, kl, nullptr);

    // #5: attention
    attn_mma<<<dim3(LSEQ / 64, NBATCH * NHEAD), 128, ATTN_SMEM>>>(qh, ql, kh, kl, vh, oh);

    // #6: output projection
    h16_gemm<2,1><<<gg, 256, GEMM_SMEM>>>(oh, nullptr, woh, nullptr, nullptr, nullptr, bo,
                                          nullptr, nullptr, out);
}